// round 1
// baseline (speedup 1.0000x reference)
#include <cuda_runtime.h>
#include <cstdint>

// Problem constants
#define NN     50000
#define EIN    800000
#define ET     (EIN + NN)      // edges + self loops = 850000
#define IND    128
#define HEADS  4
#define HID    64
#define HC     256             // HEADS*HID
#define OUTD   64
#define NEG_SLOPE 0.2f

// ---------------- device scratch (static, no runtime alloc) ----------------
__device__ float    g_xh  [(size_t)NN * HC];   // x @ W  [N,256]
__device__ float    g_agg [(size_t)NN * HC];   // segment-sum accumulator
__device__ float    g_h   [(size_t)NN * HC];   // layer output (relu(agg+b))
__device__ float    g_asrc[(size_t)NN * HEADS];
__device__ float    g_adst[(size_t)NN * HEADS];
__device__ unsigned g_mkey[(size_t)NN * HEADS]; // segment max (ordered-uint)
__device__ float    g_den [(size_t)NN * HEADS]; // segment sum of exp
__device__ float    g_e   [(size_t)ET * HEADS]; // per-edge logits
__device__ int      g_src [ET];
__device__ int      g_dst [ET];
__device__ int      g_is64;

// ---------------- helpers ----------------
__device__ __forceinline__ unsigned enc_f(float f) {
    unsigned u = __float_as_uint(f);
    return (u & 0x80000000u) ? ~u : (u | 0x80000000u);
}
__device__ __forceinline__ float dec_f(unsigned k) {
    return (k & 0x80000000u) ? __uint_as_float(k & 0x7fffffffu)
                             : __uint_as_float(~k);
}
__device__ __forceinline__ float lrelu(float v) {
    return v >= 0.f ? v : NEG_SLOPE * v;
}

// ---------------- edge index prep ----------------
__global__ void detect_kernel(const long long* __restrict__ ei) {
    if (threadIdx.x == 0 && blockIdx.x == 0) {
        int is64 = 1;
        for (int k = 0; k < 16; k++) {
            long long v = ei[k];
            if (v < 0 || v >= (long long)NN) { is64 = 0; break; }
        }
        g_is64 = is64;
    }
}

__global__ void convert_edges_kernel(const void* __restrict__ ei) {
    int i = blockIdx.x * blockDim.x + threadIdx.x;
    if (i >= ET) return;
    if (i < EIN) {
        if (g_is64) {
            const long long* p = (const long long*)ei;
            g_src[i] = (int)p[i];
            g_dst[i] = (int)p[EIN + i];
        } else {
            const int* p = (const int*)ei;
            g_src[i] = p[i];
            g_dst[i] = p[EIN + i];
        }
    } else {
        int n = i - EIN;
        g_src[i] = n;
        g_dst[i] = n;
    }
}

// ---------------- GEMM: C[M,Ncol] = A[M,K] @ B[K,Ncol] (+bias) ----------------
// BM=BN=64, BK=16, 256 threads, 4x4 per thread.
__global__ void gemm_kernel(const float* __restrict__ A, const float* __restrict__ B,
                            float* __restrict__ C, int M, int K, int Ncol,
                            const float* __restrict__ bias) {
    __shared__ float As[16][68];
    __shared__ float Bs[16][68];
    const int tid = threadIdx.x;
    const int tx = tid & 15, ty = tid >> 4;
    const int row0 = blockIdx.y * 64;
    const int col0 = blockIdx.x * 64;

    float acc[4][4] = {};

    for (int k0 = 0; k0 < K; k0 += 16) {
        #pragma unroll
        for (int i = 0; i < 4; i++) {
            int idx = tid + i * 256;
            int r = idx >> 4;       // 0..63 (A row within tile)
            int c = idx & 15;       // 0..15 (k within tile)
            int gr = row0 + r;
            As[c][r] = (gr < M) ? A[(size_t)gr * K + k0 + c] : 0.f;
        }
        #pragma unroll
        for (int i = 0; i < 4; i++) {
            int idx = tid + i * 256;
            int r = idx >> 6;       // 0..15 (k within tile)
            int c = idx & 63;       // 0..63 (B col within tile)
            Bs[r][c] = B[(size_t)(k0 + r) * Ncol + col0 + c];
        }
        __syncthreads();
        #pragma unroll
        for (int k = 0; k < 16; k++) {
            float4 a4 = *(const float4*)&As[k][ty * 4];
            float4 b4 = *(const float4*)&Bs[k][tx * 4];
            float a[4] = {a4.x, a4.y, a4.z, a4.w};
            float b[4] = {b4.x, b4.y, b4.z, b4.w};
            #pragma unroll
            for (int r = 0; r < 4; r++)
                #pragma unroll
                for (int c = 0; c < 4; c++)
                    acc[r][c] = fmaf(a[r], b[c], acc[r][c]);
        }
        __syncthreads();
    }

    #pragma unroll
    for (int r = 0; r < 4; r++) {
        int gr = row0 + ty * 4 + r;
        if (gr < M) {
            #pragma unroll
            for (int c = 0; c < 4; c++) {
                int gc = col0 + tx * 4 + c;
                float v = acc[r][c];
                if (bias) v += bias[gc];
                C[(size_t)gr * Ncol + gc] = v;
            }
        }
    }
}

// ---------------- per-node attention coefficients ----------------
// one warp per (node, head): asrc[n,h] = dot(xh[n,h,:], a_src[h,:]), same for dst
__global__ void alpha_kernel(const float* __restrict__ aw_src,
                             const float* __restrict__ aw_dst) {
    int warp = (blockIdx.x * blockDim.x + threadIdx.x) >> 5;
    int lane = threadIdx.x & 31;
    if (warp >= NN * HEADS) return;
    int n = warp >> 2, h = warp & 3;
    const float* row = g_xh + (size_t)n * HC + h * HID;
    float x0 = row[lane], x1 = row[lane + 32];
    float s = x0 * aw_src[h * HID + lane] + x1 * aw_src[h * HID + lane + 32];
    float d = x0 * aw_dst[h * HID + lane] + x1 * aw_dst[h * HID + lane + 32];
    #pragma unroll
    for (int o = 16; o > 0; o >>= 1) {
        s += __shfl_xor_sync(0xffffffffu, s, o);
        d += __shfl_xor_sync(0xffffffffu, d, o);
    }
    if (lane == 0) {
        g_asrc[warp] = s;
        g_adst[warp] = d;
    }
}

// ---------------- zero accumulators ----------------
__global__ void init_kernel() {
    int i = blockIdx.x * blockDim.x + threadIdx.x;
    if (i < NN * HC) g_agg[i] = 0.f;
    if (i < NN * HEADS) { g_mkey[i] = 0u; g_den[i] = 0.f; }
}

// ---------------- edge pass 1: logits + segment max ----------------
__global__ void edge_logits_kernel() {
    int i = blockIdx.x * blockDim.x + threadIdx.x;
    if (i >= ET) return;
    int s = g_src[i], d = g_dst[i];
    float4 as = *(const float4*)(g_asrc + (size_t)s * 4);
    float4 ad = *(const float4*)(g_adst + (size_t)d * 4);
    float e0 = lrelu(as.x + ad.x);
    float e1 = lrelu(as.y + ad.y);
    float e2 = lrelu(as.z + ad.z);
    float e3 = lrelu(as.w + ad.w);
    *(float4*)(g_e + (size_t)i * 4) = make_float4(e0, e1, e2, e3);
    atomicMax(&g_mkey[d * 4 + 0], enc_f(e0));
    atomicMax(&g_mkey[d * 4 + 1], enc_f(e1));
    atomicMax(&g_mkey[d * 4 + 2], enc_f(e2));
    atomicMax(&g_mkey[d * 4 + 3], enc_f(e3));
}

// ---------------- edge pass 2: denom = segment sum of exp(e - m) ----------------
__global__ void edge_denom_kernel() {
    int i = blockIdx.x * blockDim.x + threadIdx.x;
    if (i >= ET) return;
    int d = g_dst[i];
    float4 e = *(const float4*)(g_e + (size_t)i * 4);
    atomicAdd(&g_den[d * 4 + 0], __expf(e.x - dec_f(g_mkey[d * 4 + 0])));
    atomicAdd(&g_den[d * 4 + 1], __expf(e.y - dec_f(g_mkey[d * 4 + 1])));
    atomicAdd(&g_den[d * 4 + 2], __expf(e.z - dec_f(g_mkey[d * 4 + 2])));
    atomicAdd(&g_den[d * 4 + 3], __expf(e.w - dec_f(g_mkey[d * 4 + 3])));
}

// ---------------- edge pass 3: weighted gather-scatter ----------------
// one block (256 threads) per edge; thread t handles channel t (head = t/64)
__global__ void edge_msg_kernel() {
    int i = blockIdx.x;
    int t = threadIdx.x;
    int s = g_src[i], d = g_dst[i];
    int h = t >> 6;
    float e = g_e[(size_t)i * 4 + h];
    float m = dec_f(g_mkey[d * 4 + h]);
    float den = g_den[d * 4 + h];
    float alpha = __expf(e - m) / (den + 1e-16f);
    float v = g_xh[(size_t)s * HC + t] * alpha;
    atomicAdd(&g_agg[(size_t)d * HC + t], v);
}

// ---------------- epilogue: h = relu(agg + b) ----------------
__global__ void bias_relu_kernel(const float* __restrict__ b) {
    int i = blockIdx.x * blockDim.x + threadIdx.x;
    if (i >= NN * HC) return;
    float v = g_agg[i] + b[i & (HC - 1)];
    g_h[i] = v > 0.f ? v : 0.f;
}

// ---------------- host ----------------
extern "C" void kernel_launch(void* const* d_in, const int* in_sizes, int n_in,
                              void* d_out, int out_size) {
    const float*     x   = (const float*)d_in[0];
    const long long* ei  = (const long long*)d_in[1];
    // d_in[2] = edge_attr (ignored)
    const float* W1  = (const float*)d_in[3];
    const float* as1 = (const float*)d_in[4];
    const float* ad1 = (const float*)d_in[5];
    const float* b1  = (const float*)d_in[6];
    const float* W2  = (const float*)d_in[7];
    const float* as2 = (const float*)d_in[8];
    const float* ad2 = (const float*)d_in[9];
    const float* b2  = (const float*)d_in[10];
    const float* Wfc = (const float*)d_in[11];
    const float* bfc = (const float*)d_in[12];
    float* out = (float*)d_out;

    float *p_xh = nullptr, *p_h = nullptr;
    cudaGetSymbolAddress((void**)&p_xh, g_xh);
    cudaGetSymbolAddress((void**)&p_h,  g_h);

    const int TPB = 256;
    const int eblk = (ET + TPB - 1) / TPB;
    const int nblk_hc = (NN * HC + TPB - 1) / TPB;
    const int ablk = (NN * HEADS * 32 + TPB - 1) / TPB; // warp per (node,head)

    // edge index prep (once per call; deterministic)
    detect_kernel<<<1, 32>>>(ei);
    convert_edges_kernel<<<eblk, TPB>>>((const void*)ei);

    // ---- layer 1: x[ N,128 ] -> h[ N,256 ] ----
    {
        dim3 grid(HC / 64, (NN + 63) / 64);
        gemm_kernel<<<grid, 256>>>(x, W1, p_xh, NN, IND, HC, nullptr);
        alpha_kernel<<<ablk, TPB>>>(as1, ad1);
        init_kernel<<<nblk_hc, TPB>>>();
        edge_logits_kernel<<<eblk, TPB>>>();
        edge_denom_kernel<<<eblk, TPB>>>();
        edge_msg_kernel<<<ET, 256>>>();
        bias_relu_kernel<<<nblk_hc, TPB>>>(b1);
    }

    // ---- layer 2: h[ N,256 ] -> h[ N,256 ] ----
    {
        dim3 grid(HC / 64, (NN + 63) / 64);
        gemm_kernel<<<grid, 256>>>(p_h, W2, p_xh, NN, HC, HC, nullptr);
        alpha_kernel<<<ablk, TPB>>>(as2, ad2);
        init_kernel<<<nblk_hc, TPB>>>();
        edge_logits_kernel<<<eblk, TPB>>>();
        edge_denom_kernel<<<eblk, TPB>>>();
        edge_msg_kernel<<<ET, 256>>>();
        bias_relu_kernel<<<nblk_hc, TPB>>>(b2);
    }

    // ---- fc head: out = h @ Wfc + bfc ----
    {
        dim3 grid(OUTD / 64, (NN + 63) / 64);
        gemm_kernel<<<grid, 256>>>(p_h, Wfc, out, NN, HC, OUTD, bfc);
    }
}

// round 2
// speedup vs baseline: 3.8374x; 3.8374x over previous
#include <cuda_runtime.h>
#include <cstdint>
#include <cfloat>

// Problem constants
#define NN     50000
#define EIN    800000
#define ET     (EIN + NN)      // edges + self loops = 850000
#define IND    128
#define HEADS  4
#define HID    64
#define HC     256             // HEADS*HID
#define OUTD   64
#define NEG_SLOPE 0.2f

// ---------------- device scratch (static, no runtime alloc) ----------------
__device__ float g_xh  [(size_t)NN * HC];   // x @ W  [N,256]
__device__ float g_h   [(size_t)NN * HC];   // layer output (relu(agg+b))
__device__ float g_asrc[(size_t)NN * HEADS];
__device__ float g_adst[(size_t)NN * HEADS];
__device__ int   g_deg [NN];
__device__ int   g_off [NN + 1];
__device__ int   g_cur [NN];
__device__ int   g_csrc[ET];                // CSR (by dst) source indices
__device__ int   g_src [ET];
__device__ int   g_dst [ET];
__device__ int   g_is64;

__device__ __forceinline__ float lrelu(float v) {
    return v >= 0.f ? v : NEG_SLOPE * v;
}

// ---------------- edge index prep ----------------
__global__ void detect_kernel(const long long* __restrict__ ei) {
    if (threadIdx.x == 0 && blockIdx.x == 0) {
        int is64 = 1;
        for (int k = 0; k < 16; k++) {
            long long v = ei[k];
            if (v < 0 || v >= (long long)NN) { is64 = 0; break; }
        }
        g_is64 = is64;
    }
}

__global__ void zero_deg_kernel() {
    int i = blockIdx.x * blockDim.x + threadIdx.x;
    if (i < NN) g_deg[i] = 0;
}

// convert edge index to int32 src/dst (+self loops) and histogram dst
__global__ void convert_hist_kernel(const void* __restrict__ ei) {
    int i = blockIdx.x * blockDim.x + threadIdx.x;
    if (i >= ET) return;
    int s, d;
    if (i < EIN) {
        if (g_is64) {
            const long long* p = (const long long*)ei;
            s = (int)p[i];
            d = (int)p[EIN + i];
        } else {
            const int* p = (const int*)ei;
            s = p[i];
            d = p[EIN + i];
        }
    } else {
        s = d = i - EIN;
    }
    g_src[i] = s;
    g_dst[i] = d;
    atomicAdd(&g_deg[d], 1);
}

// single-block exclusive scan over g_deg -> g_off, g_cur
__global__ void scan_kernel() {
    __shared__ int sh[1024];
    int t = threadIdx.x;
    int run = 0;
    for (int base = 0; base < NN; base += 1024) {
        int i = base + t;
        int v = (i < NN) ? g_deg[i] : 0;
        sh[t] = v;
        __syncthreads();
        #pragma unroll
        for (int off = 1; off < 1024; off <<= 1) {
            int y = (t >= off) ? sh[t - off] : 0;
            __syncthreads();
            sh[t] += y;
            __syncthreads();
        }
        if (i < NN) {
            int excl = run + sh[t] - v;
            g_off[i] = excl;
            g_cur[i] = excl;
        }
        int total = sh[1023];
        __syncthreads();
        run += total;
    }
    if (t == 0) g_off[NN] = run;
}

__global__ void scatter_kernel() {
    int i = blockIdx.x * blockDim.x + threadIdx.x;
    if (i >= ET) return;
    int d = g_dst[i];
    int pos = atomicAdd(&g_cur[d], 1);
    g_csrc[pos] = g_src[i];
}

// ---------------- SGEMM 128x128x8, 256 threads, 8x8 micro-tile ----------------
// C[M,N] = A[M,K] @ B[K,N].  N must be a multiple of 128, K a multiple of 8.
__global__ void __launch_bounds__(256, 2)
gemm128_kernel(const float* __restrict__ A, const float* __restrict__ B,
               float* __restrict__ C, int M, int K, int N) {
    __shared__ float As[8][128];
    __shared__ float Bs[8][128];
    const int tid = threadIdx.x;
    const int tx = tid & 15, ty = tid >> 4;
    const int row0 = blockIdx.y * 128;
    const int col0 = blockIdx.x * 128;

    const int ar = tid >> 1;          // 0..127  (A row within tile)
    const int ak = (tid & 1) * 4;     // 0 or 4  (k offset)
    const int br = tid >> 5;          // 0..7    (B k-row)
    const int bc = (tid & 31) * 4;    // 0..124  (B col)

    float acc[8][8] = {};

    for (int k0 = 0; k0 < K; k0 += 8) {
        float4 a4 = make_float4(0.f, 0.f, 0.f, 0.f);
        int gr = row0 + ar;
        if (gr < M) a4 = *(const float4*)(A + (size_t)gr * K + k0 + ak);
        float4 b4 = *(const float4*)(B + (size_t)(k0 + br) * N + col0 + bc);

        As[ak + 0][ar] = a4.x;
        As[ak + 1][ar] = a4.y;
        As[ak + 2][ar] = a4.z;
        As[ak + 3][ar] = a4.w;
        *(float4*)&Bs[br][bc] = b4;
        __syncthreads();

        #pragma unroll
        for (int k = 0; k < 8; k++) {
            float4 a0 = *(const float4*)&As[k][ty * 8];
            float4 a1 = *(const float4*)&As[k][ty * 8 + 4];
            float4 b0 = *(const float4*)&Bs[k][tx * 8];
            float4 b1 = *(const float4*)&Bs[k][tx * 8 + 4];
            float a[8] = {a0.x, a0.y, a0.z, a0.w, a1.x, a1.y, a1.z, a1.w};
            float b[8] = {b0.x, b0.y, b0.z, b0.w, b1.x, b1.y, b1.z, b1.w};
            #pragma unroll
            for (int r = 0; r < 8; r++)
                #pragma unroll
                for (int c = 0; c < 8; c++)
                    acc[r][c] = fmaf(a[r], b[c], acc[r][c]);
        }
        __syncthreads();
    }

    #pragma unroll
    for (int r = 0; r < 8; r++) {
        int gr = row0 + ty * 8 + r;
        if (gr < M) {
            float4 v0 = make_float4(acc[r][0], acc[r][1], acc[r][2], acc[r][3]);
            float4 v1 = make_float4(acc[r][4], acc[r][5], acc[r][6], acc[r][7]);
            *(float4*)(C + (size_t)gr * N + col0 + tx * 8)     = v0;
            *(float4*)(C + (size_t)gr * N + col0 + tx * 8 + 4) = v1;
        }
    }
}

// ---------------- small SGEMM (64x64) for the fc head ----------------
__global__ void gemm64_kernel(const float* __restrict__ A, const float* __restrict__ B,
                              float* __restrict__ C, int M, int K, int Ncol,
                              const float* __restrict__ bias) {
    __shared__ float As[16][68];
    __shared__ float Bs[16][68];
    const int tid = threadIdx.x;
    const int tx = tid & 15, ty = tid >> 4;
    const int row0 = blockIdx.y * 64;
    const int col0 = blockIdx.x * 64;

    float acc[4][4] = {};

    for (int k0 = 0; k0 < K; k0 += 16) {
        #pragma unroll
        for (int i = 0; i < 4; i++) {
            int idx = tid + i * 256;
            int r = idx >> 4;
            int c = idx & 15;
            int gr = row0 + r;
            As[c][r] = (gr < M) ? A[(size_t)gr * K + k0 + c] : 0.f;
        }
        #pragma unroll
        for (int i = 0; i < 4; i++) {
            int idx = tid + i * 256;
            int r = idx >> 6;
            int c = idx & 63;
            Bs[r][c] = B[(size_t)(k0 + r) * Ncol + col0 + c];
        }
        __syncthreads();
        #pragma unroll
        for (int k = 0; k < 16; k++) {
            float4 a4 = *(const float4*)&As[k][ty * 4];
            float4 b4 = *(const float4*)&Bs[k][tx * 4];
            float a[4] = {a4.x, a4.y, a4.z, a4.w};
            float b[4] = {b4.x, b4.y, b4.z, b4.w};
            #pragma unroll
            for (int r = 0; r < 4; r++)
                #pragma unroll
                for (int c = 0; c < 4; c++)
                    acc[r][c] = fmaf(a[r], b[c], acc[r][c]);
        }
        __syncthreads();
    }

    #pragma unroll
    for (int r = 0; r < 4; r++) {
        int gr = row0 + ty * 4 + r;
        if (gr < M) {
            #pragma unroll
            for (int c = 0; c < 4; c++) {
                int gc = col0 + tx * 4 + c;
                float v = acc[r][c];
                if (bias) v += bias[gc];
                C[(size_t)gr * Ncol + gc] = v;
            }
        }
    }
}

// ---------------- per-node attention coefficients ----------------
__global__ void alpha_kernel(const float* __restrict__ aw_src,
                             const float* __restrict__ aw_dst) {
    int warp = (blockIdx.x * blockDim.x + threadIdx.x) >> 5;
    int lane = threadIdx.x & 31;
    if (warp >= NN * HEADS) return;
    int n = warp >> 2, h = warp & 3;
    const float* row = g_xh + (size_t)n * HC + h * HID;
    float x0 = row[lane], x1 = row[lane + 32];
    float s = x0 * aw_src[h * HID + lane] + x1 * aw_src[h * HID + lane + 32];
    float d = x0 * aw_dst[h * HID + lane] + x1 * aw_dst[h * HID + lane + 32];
    #pragma unroll
    for (int o = 16; o > 0; o >>= 1) {
        s += __shfl_xor_sync(0xffffffffu, s, o);
        d += __shfl_xor_sync(0xffffffffu, d, o);
    }
    if (lane == 0) {
        g_asrc[warp] = s;
        g_adst[warp] = d;
    }
}

// ---------------- fused softmax + aggregation: one warp per dst node ----------------
// out[d, :] = relu( sum_e alpha_e * xh[src_e, :] + bias )
__global__ void agg_kernel(const float* __restrict__ bias, float* __restrict__ out) {
    int warp = (blockIdx.x * blockDim.x + threadIdx.x) >> 5;
    int lane = threadIdx.x & 31;
    if (warp >= NN) return;
    const int d = warp;
    const int beg = g_off[d], end = g_off[d + 1];
    const float4 ad = *(const float4*)(g_adst + (size_t)d * 4);

    // pass 1: per-head max over incoming edges
    float m0 = -FLT_MAX, m1 = -FLT_MAX, m2 = -FLT_MAX, m3 = -FLT_MAX;
    for (int p = beg + lane; p < end; p += 32) {
        int s = g_csrc[p];
        float4 as = *(const float4*)(g_asrc + (size_t)s * 4);
        m0 = fmaxf(m0, lrelu(as.x + ad.x));
        m1 = fmaxf(m1, lrelu(as.y + ad.y));
        m2 = fmaxf(m2, lrelu(as.z + ad.z));
        m3 = fmaxf(m3, lrelu(as.w + ad.w));
    }
    #pragma unroll
    for (int o = 16; o > 0; o >>= 1) {
        m0 = fmaxf(m0, __shfl_xor_sync(0xffffffffu, m0, o));
        m1 = fmaxf(m1, __shfl_xor_sync(0xffffffffu, m1, o));
        m2 = fmaxf(m2, __shfl_xor_sync(0xffffffffu, m2, o));
        m3 = fmaxf(m3, __shfl_xor_sync(0xffffffffu, m3, o));
    }

    // pass 2: per-head sum of exp
    float s0 = 0.f, s1 = 0.f, s2 = 0.f, s3 = 0.f;
    for (int p = beg + lane; p < end; p += 32) {
        int s = g_csrc[p];
        float4 as = *(const float4*)(g_asrc + (size_t)s * 4);
        s0 += __expf(lrelu(as.x + ad.x) - m0);
        s1 += __expf(lrelu(as.y + ad.y) - m1);
        s2 += __expf(lrelu(as.z + ad.z) - m2);
        s3 += __expf(lrelu(as.w + ad.w) - m3);
    }
    #pragma unroll
    for (int o = 16; o > 0; o >>= 1) {
        s0 += __shfl_xor_sync(0xffffffffu, s0, o);
        s1 += __shfl_xor_sync(0xffffffffu, s1, o);
        s2 += __shfl_xor_sync(0xffffffffu, s2, o);
        s3 += __shfl_xor_sync(0xffffffffu, s3, o);
    }
    const float i0 = 1.f / (s0 + 1e-16f);
    const float i1 = 1.f / (s1 + 1e-16f);
    const float i2 = 1.f / (s2 + 1e-16f);
    const float i3 = 1.f / (s3 + 1e-16f);

    // pass 3: weighted accumulation.
    // lane owns channels [lane*4, lane*4+4) (head h0 = lane>>4)
    //            and     [128+lane*4, 128+lane*4+4) (head h1 = h0+2)
    const int hsel = lane >> 4;   // 0 or 1
    const float mh0 = hsel ? m1 : m0;
    const float mh1 = hsel ? m3 : m2;
    const float ih0 = hsel ? i1 : i0;
    const float ih1 = hsel ? i3 : i2;

    float4 acc0 = make_float4(0.f, 0.f, 0.f, 0.f);
    float4 acc1 = make_float4(0.f, 0.f, 0.f, 0.f);
    const float* xh0 = g_xh + (size_t)lane * 4;
    const float* xh1 = g_xh + 128 + (size_t)lane * 4;

    for (int p = beg; p < end; p++) {
        int s = g_csrc[p];                       // broadcast
        float4 as = *(const float4*)(g_asrc + (size_t)s * 4);
        float e0 = lrelu(as.x + ad.x);
        float e1 = lrelu(as.y + ad.y);
        float e2 = lrelu(as.z + ad.z);
        float e3 = lrelu(as.w + ad.w);
        float eh0 = hsel ? e1 : e0;
        float eh1 = hsel ? e3 : e2;
        float a0 = __expf(eh0 - mh0) * ih0;
        float a1 = __expf(eh1 - mh1) * ih1;
        float4 x0 = *(const float4*)(xh0 + (size_t)s * HC);
        float4 x1 = *(const float4*)(xh1 + (size_t)s * HC);
        acc0.x = fmaf(a0, x0.x, acc0.x);
        acc0.y = fmaf(a0, x0.y, acc0.y);
        acc0.z = fmaf(a0, x0.z, acc0.z);
        acc0.w = fmaf(a0, x0.w, acc0.w);
        acc1.x = fmaf(a1, x1.x, acc1.x);
        acc1.y = fmaf(a1, x1.y, acc1.y);
        acc1.z = fmaf(a1, x1.z, acc1.z);
        acc1.w = fmaf(a1, x1.w, acc1.w);
    }

    // epilogue: bias + relu, write coalesced
    float4 b0 = *(const float4*)(bias + lane * 4);
    float4 b1 = *(const float4*)(bias + 128 + lane * 4);
    acc0.x = fmaxf(acc0.x + b0.x, 0.f);
    acc0.y = fmaxf(acc0.y + b0.y, 0.f);
    acc0.z = fmaxf(acc0.z + b0.z, 0.f);
    acc0.w = fmaxf(acc0.w + b0.w, 0.f);
    acc1.x = fmaxf(acc1.x + b1.x, 0.f);
    acc1.y = fmaxf(acc1.y + b1.y, 0.f);
    acc1.z = fmaxf(acc1.z + b1.z, 0.f);
    acc1.w = fmaxf(acc1.w + b1.w, 0.f);
    *(float4*)(out + (size_t)d * HC + lane * 4)       = acc0;
    *(float4*)(out + (size_t)d * HC + 128 + lane * 4) = acc1;
}

// ---------------- host ----------------
extern "C" void kernel_launch(void* const* d_in, const int* in_sizes, int n_in,
                              void* d_out, int out_size) {
    const float*     x   = (const float*)d_in[0];
    const long long* ei  = (const long long*)d_in[1];
    const float* W1  = (const float*)d_in[3];
    const float* as1 = (const float*)d_in[4];
    const float* ad1 = (const float*)d_in[5];
    const float* b1  = (const float*)d_in[6];
    const float* W2  = (const float*)d_in[7];
    const float* as2 = (const float*)d_in[8];
    const float* ad2 = (const float*)d_in[9];
    const float* b2  = (const float*)d_in[10];
    const float* Wfc = (const float*)d_in[11];
    const float* bfc = (const float*)d_in[12];
    float* out = (float*)d_out;

    float *p_xh = nullptr, *p_h = nullptr;
    cudaGetSymbolAddress((void**)&p_xh, g_xh);
    cudaGetSymbolAddress((void**)&p_h,  g_h);

    const int TPB = 256;
    const int eblk = (ET + TPB - 1) / TPB;
    const int nblk = (NN + TPB - 1) / TPB;
    const int ablk = (NN * HEADS * 32 + TPB - 1) / TPB;
    const int gblk = (NN * 32 + TPB - 1) / TPB;

    // CSR build (deterministic per call)
    detect_kernel<<<1, 32>>>(ei);
    zero_deg_kernel<<<nblk, TPB>>>();
    convert_hist_kernel<<<eblk, TPB>>>((const void*)ei);
    scan_kernel<<<1, 1024>>>();
    scatter_kernel<<<eblk, TPB>>>();

    // ---- layer 1 ----
    {
        dim3 grid(HC / 128, (NN + 127) / 128);
        gemm128_kernel<<<grid, 256>>>(x, W1, p_xh, NN, IND, HC);
        alpha_kernel<<<ablk, TPB>>>(as1, ad1);
        agg_kernel<<<gblk, TPB>>>(b1, p_h);
    }
    // ---- layer 2 ----
    {
        dim3 grid(HC / 128, (NN + 127) / 128);
        gemm128_kernel<<<grid, 256>>>(p_h, W2, p_xh, NN, HC, HC);
        alpha_kernel<<<ablk, TPB>>>(as2, ad2);
        agg_kernel<<<gblk, TPB>>>(b2, p_h);
    }
    // ---- fc head ----
    {
        dim3 grid(OUTD / 64, (NN + 63) / 64);
        gemm64_kernel<<<grid, 256>>>(p_h, Wfc, out, NN, HC, OUTD, bfc);
    }
}

// round 3
// speedup vs baseline: 4.6901x; 1.2222x over previous
#include <cuda_runtime.h>
#include <cstdint>
#include <cfloat>

// Problem constants
#define NN     50000
#define EIN    800000
#define ET     (EIN + NN)      // edges + self loops = 850000
#define IND    128
#define HEADS  4
#define HID    64
#define HC     256             // HEADS*HID
#define OUTD   64
#define NEG_SLOPE 0.2f

#define SCAN_B 256
#define NBLK   ((NN + SCAN_B - 1) / SCAN_B)   // 196

// ---------------- device scratch (static, no runtime alloc) ----------------
__device__ float g_xh  [(size_t)NN * HC];
__device__ float g_h   [(size_t)NN * HC];
__device__ float g_asrc[(size_t)NN * HEADS];
__device__ float g_adst[(size_t)NN * HEADS];
__device__ int   g_deg [NN];
__device__ int   g_off [NN + 1];
__device__ int   g_cur [NN];
__device__ int   g_part[NBLK];
__device__ int   g_csrc[ET];
__device__ int   g_src [ET];
__device__ int   g_dst [ET];
__device__ int   g_is64;

__device__ __forceinline__ float lrelu(float v) {
    return v >= 0.f ? v : NEG_SLOPE * v;
}

// ---------------- edge index prep ----------------
__global__ void detect_kernel(const long long* __restrict__ ei) {
    if (threadIdx.x == 0 && blockIdx.x == 0) {
        int is64 = 1;
        for (int k = 0; k < 16; k++) {
            long long v = ei[k];
            if (v < 0 || v >= (long long)NN) { is64 = 0; break; }
        }
        g_is64 = is64;
    }
}

__global__ void zero_deg_kernel() {
    int i = blockIdx.x * blockDim.x + threadIdx.x;
    if (i < NN) g_deg[i] = 0;
}

__global__ void convert_hist_kernel(const void* __restrict__ ei) {
    int i = blockIdx.x * blockDim.x + threadIdx.x;
    if (i >= ET) return;
    int s, d;
    if (i < EIN) {
        if (g_is64) {
            const long long* p = (const long long*)ei;
            s = (int)p[i];
            d = (int)p[EIN + i];
        } else {
            const int* p = (const int*)ei;
            s = p[i];
            d = p[EIN + i];
        }
    } else {
        s = d = i - EIN;
    }
    g_src[i] = s;
    g_dst[i] = d;
    atomicAdd(&g_deg[d], 1);
}

// ---------------- device-wide exclusive scan over g_deg ----------------
// block-level exclusive scan helper: returns exclusive prefix; *tot gets block total
__device__ __forceinline__ int block_excl_scan(int v, int t, int* tot) {
    __shared__ int ws[8];
    int lane = t & 31, w = t >> 5;
    int x = v;
    #pragma unroll
    for (int o = 1; o < 32; o <<= 1) {
        int y = __shfl_up_sync(0xffffffffu, x, o);
        if (lane >= o) x += y;
    }
    if (lane == 31) ws[w] = x;
    __syncthreads();
    if (w == 0) {
        int z = (lane < 8) ? ws[lane] : 0;
        #pragma unroll
        for (int o = 1; o < 8; o <<= 1) {
            int y = __shfl_up_sync(0xffffffffu, z, o);
            if (lane >= o) z += y;
        }
        if (lane < 8) ws[lane] = z;
    }
    __syncthreads();
    int base = (w > 0) ? ws[w - 1] : 0;
    int total = ws[7];
    __syncthreads();
    *tot = total;
    return base + x - v;
}

__global__ void scan_partial_kernel() {
    int i = blockIdx.x * SCAN_B + threadIdx.x;
    int v = (i < NN) ? g_deg[i] : 0;
    int tot;
    block_excl_scan(v, threadIdx.x, &tot);
    if (threadIdx.x == 0) g_part[blockIdx.x] = tot;
}

__global__ void scan_part2_kernel() {
    int t = threadIdx.x;
    int v = (t < NBLK) ? g_part[t] : 0;
    int tot;
    int excl = block_excl_scan(v, t, &tot);
    if (t < NBLK) g_part[t] = excl;
    if (t == 0) g_off[NN] = tot;
}

__global__ void scan_final_kernel() {
    int i = blockIdx.x * SCAN_B + threadIdx.x;
    int v = (i < NN) ? g_deg[i] : 0;
    int tot;
    int excl = block_excl_scan(v, threadIdx.x, &tot) + g_part[blockIdx.x];
    if (i < NN) {
        g_off[i] = excl;
        g_cur[i] = excl;
    }
}

__global__ void scatter_kernel() {
    int i = blockIdx.x * blockDim.x + threadIdx.x;
    if (i >= ET) return;
    int d = g_dst[i];
    int pos = atomicAdd(&g_cur[d], 1);
    g_csrc[pos] = g_src[i];
}

// ---------------- SGEMM 128x128x16, 256 threads, 8x8 micro-tile, reg prefetch ----
__global__ void __launch_bounds__(256, 2)
gemm128_kernel(const float* __restrict__ A, const float* __restrict__ B,
               float* __restrict__ C, int M, int K, int N) {
    __shared__ float As[16][132];
    __shared__ float Bs[16][132];
    const int tid = threadIdx.x;
    const int tx = tid & 15, ty = tid >> 4;
    const int row0 = blockIdx.y * 128;
    const int col0 = blockIdx.x * 128;

    const int ar = tid >> 2;          // 0..63
    const int ak = (tid & 3) * 4;     // 0,4,8,12
    const int br = tid >> 5;          // 0..7
    const int bc = (tid & 31) * 4;    // 0..124

    const int gr0 = row0 + ar;
    const int gr1 = row0 + ar + 64;

    float acc[8][8] = {};
    float4 pa0, pa1, pb0, pb1;

    // prologue: load tile 0
    pa0 = (gr0 < M) ? *(const float4*)(A + (size_t)gr0 * K + ak) : make_float4(0.f,0.f,0.f,0.f);
    pa1 = (gr1 < M) ? *(const float4*)(A + (size_t)gr1 * K + ak) : make_float4(0.f,0.f,0.f,0.f);
    pb0 = *(const float4*)(B + (size_t)br * N + col0 + bc);
    pb1 = *(const float4*)(B + (size_t)(br + 8) * N + col0 + bc);

    As[ak+0][ar]    = pa0.x; As[ak+1][ar]    = pa0.y; As[ak+2][ar]    = pa0.z; As[ak+3][ar]    = pa0.w;
    As[ak+0][ar+64] = pa1.x; As[ak+1][ar+64] = pa1.y; As[ak+2][ar+64] = pa1.z; As[ak+3][ar+64] = pa1.w;
    *(float4*)&Bs[br][bc]     = pb0;
    *(float4*)&Bs[br + 8][bc] = pb1;
    __syncthreads();

    for (int k0 = 16; k0 <= K; k0 += 16) {
        // prefetch next tile into registers
        if (k0 < K) {
            pa0 = (gr0 < M) ? *(const float4*)(A + (size_t)gr0 * K + k0 + ak) : make_float4(0.f,0.f,0.f,0.f);
            pa1 = (gr1 < M) ? *(const float4*)(A + (size_t)gr1 * K + k0 + ak) : make_float4(0.f,0.f,0.f,0.f);
            pb0 = *(const float4*)(B + (size_t)(k0 + br) * N + col0 + bc);
            pb1 = *(const float4*)(B + (size_t)(k0 + br + 8) * N + col0 + bc);
        }
        // compute current smem tile
        #pragma unroll
        for (int k = 0; k < 16; k++) {
            float4 a0 = *(const float4*)&As[k][ty * 8];
            float4 a1 = *(const float4*)&As[k][ty * 8 + 4];
            float4 b0 = *(const float4*)&Bs[k][tx * 8];
            float4 b1 = *(const float4*)&Bs[k][tx * 8 + 4];
            float a[8] = {a0.x, a0.y, a0.z, a0.w, a1.x, a1.y, a1.z, a1.w};
            float b[8] = {b0.x, b0.y, b0.z, b0.w, b1.x, b1.y, b1.z, b1.w};
            #pragma unroll
            for (int r = 0; r < 8; r++)
                #pragma unroll
                for (int c = 0; c < 8; c++)
                    acc[r][c] = fmaf(a[r], b[c], acc[r][c]);
        }
        __syncthreads();
        if (k0 < K) {
            As[ak+0][ar]    = pa0.x; As[ak+1][ar]    = pa0.y; As[ak+2][ar]    = pa0.z; As[ak+3][ar]    = pa0.w;
            As[ak+0][ar+64] = pa1.x; As[ak+1][ar+64] = pa1.y; As[ak+2][ar+64] = pa1.z; As[ak+3][ar+64] = pa1.w;
            *(float4*)&Bs[br][bc]     = pb0;
            *(float4*)&Bs[br + 8][bc] = pb1;
            __syncthreads();
        }
    }

    #pragma unroll
    for (int r = 0; r < 8; r++) {
        int gr = row0 + ty * 8 + r;
        if (gr < M) {
            float4 v0 = make_float4(acc[r][0], acc[r][1], acc[r][2], acc[r][3]);
            float4 v1 = make_float4(acc[r][4], acc[r][5], acc[r][6], acc[r][7]);
            *(float4*)(C + (size_t)gr * N + col0 + tx * 8)     = v0;
            *(float4*)(C + (size_t)gr * N + col0 + tx * 8 + 4) = v1;
        }
    }
}

// ---------------- small SGEMM (64x64) for the fc head ----------------
__global__ void gemm64_kernel(const float* __restrict__ A, const float* __restrict__ B,
                              float* __restrict__ C, int M, int K, int Ncol,
                              const float* __restrict__ bias) {
    __shared__ float As[16][68];
    __shared__ float Bs[16][68];
    const int tid = threadIdx.x;
    const int tx = tid & 15, ty = tid >> 4;
    const int row0 = blockIdx.y * 64;
    const int col0 = blockIdx.x * 64;

    float acc[4][4] = {};

    for (int k0 = 0; k0 < K; k0 += 16) {
        #pragma unroll
        for (int i = 0; i < 4; i++) {
            int idx = tid + i * 256;
            int r = idx >> 4;
            int c = idx & 15;
            int gr = row0 + r;
            As[c][r] = (gr < M) ? A[(size_t)gr * K + k0 + c] : 0.f;
        }
        #pragma unroll
        for (int i = 0; i < 4; i++) {
            int idx = tid + i * 256;
            int r = idx >> 6;
            int c = idx & 63;
            Bs[r][c] = B[(size_t)(k0 + r) * Ncol + col0 + c];
        }
        __syncthreads();
        #pragma unroll
        for (int k = 0; k < 16; k++) {
            float4 a4 = *(const float4*)&As[k][ty * 4];
            float4 b4 = *(const float4*)&Bs[k][tx * 4];
            float a[4] = {a4.x, a4.y, a4.z, a4.w};
            float b[4] = {b4.x, b4.y, b4.z, b4.w};
            #pragma unroll
            for (int r = 0; r < 4; r++)
                #pragma unroll
                for (int c = 0; c < 4; c++)
                    acc[r][c] = fmaf(a[r], b[c], acc[r][c]);
        }
        __syncthreads();
    }

    #pragma unroll
    for (int r = 0; r < 4; r++) {
        int gr = row0 + ty * 4 + r;
        if (gr < M) {
            #pragma unroll
            for (int c = 0; c < 4; c++) {
                int gc = col0 + tx * 4 + c;
                float v = acc[r][c];
                if (bias) v += bias[gc];
                C[(size_t)gr * Ncol + gc] = v;
            }
        }
    }
}

// ---------------- per-node attention coefficients ----------------
__global__ void alpha_kernel(const float* __restrict__ aw_src,
                             const float* __restrict__ aw_dst) {
    int warp = (blockIdx.x * blockDim.x + threadIdx.x) >> 5;
    int lane = threadIdx.x & 31;
    if (warp >= NN * HEADS) return;
    int n = warp >> 2, h = warp & 3;
    const float* row = g_xh + (size_t)n * HC + h * HID;
    float x0 = row[lane], x1 = row[lane + 32];
    float s = x0 * aw_src[h * HID + lane] + x1 * aw_src[h * HID + lane + 32];
    float d = x0 * aw_dst[h * HID + lane] + x1 * aw_dst[h * HID + lane + 32];
    #pragma unroll
    for (int o = 16; o > 0; o >>= 1) {
        s += __shfl_xor_sync(0xffffffffu, s, o);
        d += __shfl_xor_sync(0xffffffffu, d, o);
    }
    if (lane == 0) {
        g_asrc[warp] = s;
        g_adst[warp] = d;
    }
}

// ---------------- fused softmax + aggregation: one warp per dst node ----------------
__global__ void agg_kernel(const float* __restrict__ bias, float* __restrict__ out) {
    int warp = (blockIdx.x * blockDim.x + threadIdx.x) >> 5;
    int lane = threadIdx.x & 31;
    if (warp >= NN) return;
    const int d = warp;
    const int beg = g_off[d], end = g_off[d + 1];
    const float4 ad = *(const float4*)(g_adst + (size_t)d * 4);

    // pass 1: per-head max
    float m0 = -FLT_MAX, m1 = -FLT_MAX, m2 = -FLT_MAX, m3 = -FLT_MAX;
    for (int p = beg + lane; p < end; p += 32) {
        int s = g_csrc[p];
        float4 as = *(const float4*)(g_asrc + (size_t)s * 4);
        m0 = fmaxf(m0, lrelu(as.x + ad.x));
        m1 = fmaxf(m1, lrelu(as.y + ad.y));
        m2 = fmaxf(m2, lrelu(as.z + ad.z));
        m3 = fmaxf(m3, lrelu(as.w + ad.w));
    }
    #pragma unroll
    for (int o = 16; o > 0; o >>= 1) {
        m0 = fmaxf(m0, __shfl_xor_sync(0xffffffffu, m0, o));
        m1 = fmaxf(m1, __shfl_xor_sync(0xffffffffu, m1, o));
        m2 = fmaxf(m2, __shfl_xor_sync(0xffffffffu, m2, o));
        m3 = fmaxf(m3, __shfl_xor_sync(0xffffffffu, m3, o));
    }

    // pass 2: per-head sum of exp
    float s0 = 0.f, s1 = 0.f, s2 = 0.f, s3 = 0.f;
    for (int p = beg + lane; p < end; p += 32) {
        int s = g_csrc[p];
        float4 as = *(const float4*)(g_asrc + (size_t)s * 4);
        s0 += __expf(lrelu(as.x + ad.x) - m0);
        s1 += __expf(lrelu(as.y + ad.y) - m1);
        s2 += __expf(lrelu(as.z + ad.z) - m2);
        s3 += __expf(lrelu(as.w + ad.w) - m3);
    }
    #pragma unroll
    for (int o = 16; o > 0; o >>= 1) {
        s0 += __shfl_xor_sync(0xffffffffu, s0, o);
        s1 += __shfl_xor_sync(0xffffffffu, s1, o);
        s2 += __shfl_xor_sync(0xffffffffu, s2, o);
        s3 += __shfl_xor_sync(0xffffffffu, s3, o);
    }
    const float i0 = 1.f / (s0 + 1e-16f);
    const float i1 = 1.f / (s1 + 1e-16f);
    const float i2 = 1.f / (s2 + 1e-16f);
    const float i3 = 1.f / (s3 + 1e-16f);

    // pass 3: weighted accumulation
    const int hsel = lane >> 4;
    const float mh0 = hsel ? m1 : m0;
    const float mh1 = hsel ? m3 : m2;
    const float ih0 = hsel ? i1 : i0;
    const float ih1 = hsel ? i3 : i2;

    float4 acc0 = make_float4(0.f, 0.f, 0.f, 0.f);
    float4 acc1 = make_float4(0.f, 0.f, 0.f, 0.f);
    const float* xh0 = g_xh + (size_t)lane * 4;
    const float* xh1 = g_xh + 128 + (size_t)lane * 4;

    for (int p = beg; p < end; p++) {
        int s = g_csrc[p];
        float4 as = *(const float4*)(g_asrc + (size_t)s * 4);
        float e0 = lrelu(as.x + ad.x);
        float e1 = lrelu(as.y + ad.y);
        float e2 = lrelu(as.z + ad.z);
        float e3 = lrelu(as.w + ad.w);
        float eh0 = hsel ? e1 : e0;
        float eh1 = hsel ? e3 : e2;
        float a0 = __expf(eh0 - mh0) * ih0;
        float a1 = __expf(eh1 - mh1) * ih1;
        float4 x0 = *(const float4*)(xh0 + (size_t)s * HC);
        float4 x1 = *(const float4*)(xh1 + (size_t)s * HC);
        acc0.x = fmaf(a0, x0.x, acc0.x);
        acc0.y = fmaf(a0, x0.y, acc0.y);
        acc0.z = fmaf(a0, x0.z, acc0.z);
        acc0.w = fmaf(a0, x0.w, acc0.w);
        acc1.x = fmaf(a1, x1.x, acc1.x);
        acc1.y = fmaf(a1, x1.y, acc1.y);
        acc1.z = fmaf(a1, x1.z, acc1.z);
        acc1.w = fmaf(a1, x1.w, acc1.w);
    }

    float4 b0 = *(const float4*)(bias + lane * 4);
    float4 b1 = *(const float4*)(bias + 128 + lane * 4);
    acc0.x = fmaxf(acc0.x + b0.x, 0.f);
    acc0.y = fmaxf(acc0.y + b0.y, 0.f);
    acc0.z = fmaxf(acc0.z + b0.z, 0.f);
    acc0.w = fmaxf(acc0.w + b0.w, 0.f);
    acc1.x = fmaxf(acc1.x + b1.x, 0.f);
    acc1.y = fmaxf(acc1.y + b1.y, 0.f);
    acc1.z = fmaxf(acc1.z + b1.z, 0.f);
    acc1.w = fmaxf(acc1.w + b1.w, 0.f);
    *(float4*)(out + (size_t)d * HC + lane * 4)       = acc0;
    *(float4*)(out + (size_t)d * HC + 128 + lane * 4) = acc1;
}

// ---------------- host ----------------
extern "C" void kernel_launch(void* const* d_in, const int* in_sizes, int n_in,
                              void* d_out, int out_size) {
    const float*     x   = (const float*)d_in[0];
    const long long* ei  = (const long long*)d_in[1];
    const float* W1  = (const float*)d_in[3];
    const float* as1 = (const float*)d_in[4];
    const float* ad1 = (const float*)d_in[5];
    const float* b1  = (const float*)d_in[6];
    const float* W2  = (const float*)d_in[7];
    const float* as2 = (const float*)d_in[8];
    const float* ad2 = (const float*)d_in[9];
    const float* b2  = (const float*)d_in[10];
    const float* Wfc = (const float*)d_in[11];
    const float* bfc = (const float*)d_in[12];
    float* out = (float*)d_out;

    float *p_xh = nullptr, *p_h = nullptr;
    cudaGetSymbolAddress((void**)&p_xh, g_xh);
    cudaGetSymbolAddress((void**)&p_h,  g_h);

    const int TPB = 256;
    const int eblk = (ET + TPB - 1) / TPB;
    const int nblk = (NN + TPB - 1) / TPB;
    const int ablk = (NN * HEADS * 32 + TPB - 1) / TPB;
    const int gblk = (NN * 32 + TPB - 1) / TPB;

    // CSR build (deterministic per call)
    detect_kernel<<<1, 32>>>(ei);
    zero_deg_kernel<<<nblk, TPB>>>();
    convert_hist_kernel<<<eblk, TPB>>>((const void*)ei);
    scan_partial_kernel<<<NBLK, SCAN_B>>>();
    scan_part2_kernel<<<1, SCAN_B>>>();
    scan_final_kernel<<<NBLK, SCAN_B>>>();
    scatter_kernel<<<eblk, TPB>>>();

    // ---- layer 1 ----
    {
        dim3 grid(HC / 128, (NN + 127) / 128);
        gemm128_kernel<<<grid, 256>>>(x, W1, p_xh, NN, IND, HC);
        alpha_kernel<<<ablk, TPB>>>(as1, ad1);
        agg_kernel<<<gblk, TPB>>>(b1, p_h);
    }
    // ---- layer 2 ----
    {
        dim3 grid(HC / 128, (NN + 127) / 128);
        gemm128_kernel<<<grid, 256>>>(p_h, W2, p_xh, NN, HC, HC);
        alpha_kernel<<<ablk, TPB>>>(as2, ad2);
        agg_kernel<<<gblk, TPB>>>(b2, p_h);
    }
    // ---- fc head ----
    {
        dim3 grid(OUTD / 64, (NN + 63) / 64);
        gemm64_kernel<<<grid, 256>>>(p_h, Wfc, out, NN, HC, OUTD, bfc);
    }
}

// round 5
// speedup vs baseline: 6.0454x; 1.2890x over previous
#include <cuda_runtime.h>
#include <cuda_bf16.h>
#include <cstdint>
#include <cfloat>

// Problem constants
#define NN     50000
#define EIN    800000
#define ET     (EIN + NN)
#define IND    128
#define HEADS  4
#define HID    64
#define HC     256
#define OUTD   64
#define NEG_SLOPE 0.2f

#define SCAN_B 256
#define NBLK   ((NN + SCAN_B - 1) / SCAN_B)

// ---------------- device scratch ----------------
__device__ float g_xh  [(size_t)NN * HC];
__device__ float g_asrc[(size_t)NN * HEADS];
__device__ float g_adst[(size_t)NN * HEADS];
__device__ __align__(16) __nv_bfloat16 g_ahi[(size_t)NN * HC];
__device__ __align__(16) __nv_bfloat16 g_alo[(size_t)NN * HC];
__device__ __align__(16) __nv_bfloat16 g_b1hi[256 * 128];
__device__ __align__(16) __nv_bfloat16 g_b1lo[256 * 128];
__device__ __align__(16) __nv_bfloat16 g_b2hi[256 * 256];
__device__ __align__(16) __nv_bfloat16 g_b2lo[256 * 256];
__device__ __align__(16) __nv_bfloat16 g_bfhi[64 * 256];
__device__ __align__(16) __nv_bfloat16 g_bflo[64 * 256];
__device__ int   g_deg [NN];
__device__ int   g_off [NN + 1];
__device__ int   g_cur [NN];
__device__ int   g_part[NBLK];
__device__ int   g_csrc[ET];
__device__ int   g_src [ET];
__device__ int   g_dst [ET];
__device__ int   g_is64;

__device__ __forceinline__ float lrelu(float v) {
    return v >= 0.f ? v : NEG_SLOPE * v;
}
__device__ __forceinline__ void split_bf16(float v, __nv_bfloat16* hi, __nv_bfloat16* lo) {
    __nv_bfloat16 h = __float2bfloat16(v);
    *hi = h;
    *lo = __float2bfloat16(v - __bfloat162float(h));
}

// ---------------- edge index prep ----------------
__global__ void detect_kernel(const long long* __restrict__ ei) {
    if (threadIdx.x == 0 && blockIdx.x == 0) {
        int is64 = 1;
        for (int k = 0; k < 16; k++) {
            long long v = ei[k];
            if (v < 0 || v >= (long long)NN) { is64 = 0; break; }
        }
        g_is64 = is64;
    }
}

__global__ void zero_deg_kernel() {
    int i = blockIdx.x * blockDim.x + threadIdx.x;
    if (i < NN) g_deg[i] = 0;
}

__global__ void convert_hist_kernel(const void* __restrict__ ei) {
    int i = blockIdx.x * blockDim.x + threadIdx.x;
    if (i >= ET) return;
    int s, d;
    if (i < EIN) {
        if (g_is64) {
            const long long* p = (const long long*)ei;
            s = (int)p[i];
            d = (int)p[EIN + i];
        } else {
            const int* p = (const int*)ei;
            s = p[i];
            d = p[EIN + i];
        }
    } else {
        s = d = i - EIN;
    }
    g_src[i] = s;
    g_dst[i] = d;
    atomicAdd(&g_deg[d], 1);
}

// ---------------- input conversions to bf16 hi/lo ----------------
__global__ void conv_x_kernel(const float* __restrict__ x) {
    int i = blockIdx.x * blockDim.x + threadIdx.x;
    const int tot = NN * IND;
    for (; i < tot; i += gridDim.x * blockDim.x)
        split_bf16(x[i], &g_ahi[i], &g_alo[i]);
}

// W1 [128,256] -> B1 [256,128]; W2 [256,256] -> B2 [256,256]; Wfc [256,64] -> Bf [64,256]
__global__ void conv_w_kernel(const float* __restrict__ W1,
                              const float* __restrict__ W2,
                              const float* __restrict__ Wfc) {
    int i = blockIdx.x * blockDim.x + threadIdx.x;
    const int s1 = 128 * 256, s2 = s1 + 256 * 256, s3 = s2 + 256 * 64;
    if (i < s1) {
        int k = i / 256, n = i % 256;
        split_bf16(W1[i], &g_b1hi[n * 128 + k], &g_b1lo[n * 128 + k]);
    } else if (i < s2) {
        int j = i - s1;
        int k = j / 256, n = j % 256;
        split_bf16(W2[j], &g_b2hi[n * 256 + k], &g_b2lo[n * 256 + k]);
    } else if (i < s3) {
        int j = i - s2;
        int k = j / 64, n = j % 64;
        split_bf16(Wfc[j], &g_bfhi[n * 256 + k], &g_bflo[n * 256 + k]);
    }
}

// ---------------- mma.sync bf16 helper ----------------
__device__ __forceinline__ void mma16816(float* c, const uint32_t* a, const uint32_t* b) {
    asm volatile(
        "mma.sync.aligned.m16n8k16.row.col.f32.bf16.bf16.f32 "
        "{%0,%1,%2,%3}, {%4,%5,%6,%7}, {%8,%9}, {%0,%1,%2,%3};"
        : "+f"(c[0]), "+f"(c[1]), "+f"(c[2]), "+f"(c[3])
        : "r"(a[0]), "r"(a[1]), "r"(a[2]), "r"(a[3]), "r"(b[0]), "r"(b[1]));
}

// ---------------- tensor-core GEMM via mma.sync ----------------
// C[M, NTOT] = A[M, KTOT] @ B[NTOT, KTOT]^T, two-term bf16 split (3 MMA terms).
// Block: 128 x BN tile, 256 threads (8 warps: 2 in M x 4 in N). BK=32, reg prefetch.
template<int BN, int KTOT, int NTOT, bool BIAS>
__global__ void __launch_bounds__(256, 1)
gemm_mma_kernel(const __nv_bfloat16* __restrict__ Ahi,
                const __nv_bfloat16* __restrict__ Alo,
                const __nv_bfloat16* __restrict__ Bhi,
                const __nv_bfloat16* __restrict__ Blo,
                float* __restrict__ C,
                const float* __restrict__ bias) {
    constexpr int RS  = 40;            // smem row stride in elements (80B: 16B-aligned, conflict-free)
    constexpr int NF  = BN / 32;       // n-fragments per warp (4 or 2)
    constexpr int NB4 = BN / 64;       // uint4 loads per thread per B half (2 or 1)

    __shared__ __nv_bfloat16 sm[(2 * 128 + 2 * BN) * RS];
    __nv_bfloat16* smAh = sm;
    __nv_bfloat16* smAl = sm + 128 * RS;
    __nv_bfloat16* smBh = sm + 2 * 128 * RS;
    __nv_bfloat16* smBl = smBh + BN * RS;

    const int tid  = threadIdx.x;
    const int wid  = tid >> 5, lane = tid & 31;
    const int wm   = wid & 1, wn = wid >> 1;
    const int row0 = blockIdx.y * 128;
    const int col0 = blockIdx.x * BN;

    float acc[4][NF][4];
    #pragma unroll
    for (int i = 0; i < 4; i++)
        #pragma unroll
        for (int j = 0; j < NF; j++)
            #pragma unroll
            for (int q = 0; q < 4; q++) acc[i][j][q] = 0.f;

    uint4 pah[2], pal[2], pbh[2], pbl[2];
    const uint4 Z = make_uint4(0u, 0u, 0u, 0u);

    // ---- prologue: load k-chunk 0 into regs ----
    #pragma unroll
    for (int q = 0; q < 2; q++) {
        int idx = tid + q * 256;
        int row = idx >> 2, c8 = (idx & 3) * 8;
        int gr = row0 + row;
        pah[q] = (gr < NN) ? *(const uint4*)(Ahi + (size_t)gr * KTOT + c8) : Z;
        pal[q] = (gr < NN) ? *(const uint4*)(Alo + (size_t)gr * KTOT + c8) : Z;
    }
    #pragma unroll
    for (int q = 0; q < NB4; q++) {
        int idx = tid + q * 256;
        int row = idx >> 2, c8 = (idx & 3) * 8;
        pbh[q] = *(const uint4*)(Bhi + (size_t)(col0 + row) * KTOT + c8);
        pbl[q] = *(const uint4*)(Blo + (size_t)(col0 + row) * KTOT + c8);
    }
    #pragma unroll
    for (int q = 0; q < 2; q++) {
        int idx = tid + q * 256;
        int row = idx >> 2, c8 = (idx & 3) * 8;
        *(uint4*)(smAh + row * RS + c8) = pah[q];
        *(uint4*)(smAl + row * RS + c8) = pal[q];
    }
    #pragma unroll
    for (int q = 0; q < NB4; q++) {
        int idx = tid + q * 256;
        int row = idx >> 2, c8 = (idx & 3) * 8;
        *(uint4*)(smBh + row * RS + c8) = pbh[q];
        *(uint4*)(smBl + row * RS + c8) = pbl[q];
    }
    __syncthreads();

    const int arow = (lane >> 2);        // 0..7
    const int acol = (lane & 3) * 2;     // 0,2,4,6

    for (int k0 = 32; k0 <= KTOT; k0 += 32) {
        // prefetch next chunk
        if (k0 < KTOT) {
            #pragma unroll
            for (int q = 0; q < 2; q++) {
                int idx = tid + q * 256;
                int row = idx >> 2, c8 = (idx & 3) * 8;
                int gr = row0 + row;
                pah[q] = (gr < NN) ? *(const uint4*)(Ahi + (size_t)gr * KTOT + k0 + c8) : Z;
                pal[q] = (gr < NN) ? *(const uint4*)(Alo + (size_t)gr * KTOT + k0 + c8) : Z;
            }
            #pragma unroll
            for (int q = 0; q < NB4; q++) {
                int idx = tid + q * 256;
                int row = idx >> 2, c8 = (idx & 3) * 8;
                pbh[q] = *(const uint4*)(Bhi + (size_t)(col0 + row) * KTOT + k0 + c8);
                pbl[q] = *(const uint4*)(Blo + (size_t)(col0 + row) * KTOT + k0 + c8);
            }
        }

        // compute the two k16 substeps of the current chunk
        #pragma unroll
        for (int ks = 0; ks < 2; ks++) {
            const int kc = ks * 16 + acol;
            // B fragments for all n-frags
            uint32_t bh[NF][2], bl[NF][2];
            #pragma unroll
            for (int j = 0; j < NF; j++) {
                int nrow = wn * (BN / 4) + j * 8 + arow;
                bh[j][0] = *(const uint32_t*)(smBh + nrow * RS + kc);
                bh[j][1] = *(const uint32_t*)(smBh + nrow * RS + kc + 8);
                bl[j][0] = *(const uint32_t*)(smBl + nrow * RS + kc);
                bl[j][1] = *(const uint32_t*)(smBl + nrow * RS + kc + 8);
            }
            #pragma unroll
            for (int i = 0; i < 4; i++) {
                int r0 = wm * 64 + i * 16 + arow;
                uint32_t ah[4], al[4];
                ah[0] = *(const uint32_t*)(smAh + r0 * RS + kc);
                ah[1] = *(const uint32_t*)(smAh + (r0 + 8) * RS + kc);
                ah[2] = *(const uint32_t*)(smAh + r0 * RS + kc + 8);
                ah[3] = *(const uint32_t*)(smAh + (r0 + 8) * RS + kc + 8);
                al[0] = *(const uint32_t*)(smAl + r0 * RS + kc);
                al[1] = *(const uint32_t*)(smAl + (r0 + 8) * RS + kc);
                al[2] = *(const uint32_t*)(smAl + r0 * RS + kc + 8);
                al[3] = *(const uint32_t*)(smAl + (r0 + 8) * RS + kc + 8);
                #pragma unroll
                for (int j = 0; j < NF; j++) {
                    mma16816(acc[i][j], ah, bh[j]);
                    mma16816(acc[i][j], ah, bl[j]);
                    mma16816(acc[i][j], al, bh[j]);
                }
            }
        }
        __syncthreads();
        if (k0 < KTOT) {
            #pragma unroll
            for (int q = 0; q < 2; q++) {
                int idx = tid + q * 256;
                int row = idx >> 2, c8 = (idx & 3) * 8;
                *(uint4*)(smAh + row * RS + c8) = pah[q];
                *(uint4*)(smAl + row * RS + c8) = pal[q];
            }
            #pragma unroll
            for (int q = 0; q < NB4; q++) {
                int idx = tid + q * 256;
                int row = idx >> 2, c8 = (idx & 3) * 8;
                *(uint4*)(smBh + row * RS + c8) = pbh[q];
                *(uint4*)(smBl + row * RS + c8) = pbl[q];
            }
            __syncthreads();
        }
    }

    // ---- epilogue ----
    #pragma unroll
    for (int i = 0; i < 4; i++) {
        int r = row0 + wm * 64 + i * 16 + arow;
        #pragma unroll
        for (int j = 0; j < NF; j++) {
            int c = col0 + wn * (BN / 4) + j * 8 + acol;
            float bx = 0.f, by = 0.f;
            if (BIAS) { bx = bias[c]; by = bias[c + 1]; }
            if (r < NN) {
                float2 v = make_float2(acc[i][j][0] + bx, acc[i][j][1] + by);
                *(float2*)(C + (size_t)r * NTOT + c) = v;
            }
            if (r + 8 < NN) {
                float2 v = make_float2(acc[i][j][2] + bx, acc[i][j][3] + by);
                *(float2*)(C + (size_t)(r + 8) * NTOT + c) = v;
            }
        }
    }
}

// ---------------- scan (3-phase, device-wide) ----------------
__device__ __forceinline__ int block_excl_scan(int v, int t, int* tot) {
    __shared__ int ws[8];
    int lane = t & 31, w = t >> 5;
    int x = v;
    #pragma unroll
    for (int o = 1; o < 32; o <<= 1) {
        int y = __shfl_up_sync(0xffffffffu, x, o);
        if (lane >= o) x += y;
    }
    if (lane == 31) ws[w] = x;
    __syncthreads();
    if (w == 0) {
        int z = (lane < 8) ? ws[lane] : 0;
        #pragma unroll
        for (int o = 1; o < 8; o <<= 1) {
            int y = __shfl_up_sync(0xffffffffu, z, o);
            if (lane >= o) z += y;
        }
        if (lane < 8) ws[lane] = z;
    }
    __syncthreads();
    int base = (w > 0) ? ws[w - 1] : 0;
    int total = ws[7];
    __syncthreads();
    *tot = total;
    return base + x - v;
}

__global__ void scan_partial_kernel() {
    int i = blockIdx.x * SCAN_B + threadIdx.x;
    int v = (i < NN) ? g_deg[i] : 0;
    int tot;
    block_excl_scan(v, threadIdx.x, &tot);
    if (threadIdx.x == 0) g_part[blockIdx.x] = tot;
}

__global__ void scan_part2_kernel() {
    int t = threadIdx.x;
    int v = (t < NBLK) ? g_part[t] : 0;
    int tot;
    int excl = block_excl_scan(v, t, &tot);
    if (t < NBLK) g_part[t] = excl;
    if (t == 0) g_off[NN] = tot;
}

__global__ void scan_final_kernel() {
    int i = blockIdx.x * SCAN_B + threadIdx.x;
    int v = (i < NN) ? g_deg[i] : 0;
    int tot;
    int excl = block_excl_scan(v, threadIdx.x, &tot) + g_part[blockIdx.x];
    if (i < NN) {
        g_off[i] = excl;
        g_cur[i] = excl;
    }
}

__global__ void scatter_kernel() {
    int i = blockIdx.x * blockDim.x + threadIdx.x;
    if (i >= ET) return;
    int d = g_dst[i];
    int pos = atomicAdd(&g_cur[d], 1);
    g_csrc[pos] = g_src[i];
}

// ---------------- per-node attention coefficients ----------------
__global__ void alpha_kernel(const float* __restrict__ aw_src,
                             const float* __restrict__ aw_dst) {
    int warp = (blockIdx.x * blockDim.x + threadIdx.x) >> 5;
    int lane = threadIdx.x & 31;
    if (warp >= NN * HEADS) return;
    int n = warp >> 2, h = warp & 3;
    const float* row = g_xh + (size_t)n * HC + h * HID;
    float x0 = row[lane], x1 = row[lane + 32];
    float s = x0 * aw_src[h * HID + lane] + x1 * aw_src[h * HID + lane + 32];
    float d = x0 * aw_dst[h * HID + lane] + x1 * aw_dst[h * HID + lane + 32];
    #pragma unroll
    for (int o = 16; o > 0; o >>= 1) {
        s += __shfl_xor_sync(0xffffffffu, s, o);
        d += __shfl_xor_sync(0xffffffffu, d, o);
    }
    if (lane == 0) {
        g_asrc[warp] = s;
        g_adst[warp] = d;
    }
}

// ---------------- fused softmax + aggregation: one warp per dst node ----------------
// writes relu(agg + bias) as bf16 hi/lo split into g_ahi/g_alo (stride HC)
__global__ void agg_kernel(const float* __restrict__ bias) {
    int warp = (blockIdx.x * blockDim.x + threadIdx.x) >> 5;
    int lane = threadIdx.x & 31;
    if (warp >= NN) return;
    const int d = warp;
    const int beg = g_off[d], end = g_off[d + 1];
    const float4 ad = *(const float4*)(g_adst + (size_t)d * 4);

    float m0 = -FLT_MAX, m1 = -FLT_MAX, m2 = -FLT_MAX, m3 = -FLT_MAX;
    for (int p = beg + lane; p < end; p += 32) {
        int s = g_csrc[p];
        float4 as = *(const float4*)(g_asrc + (size_t)s * 4);
        m0 = fmaxf(m0, lrelu(as.x + ad.x));
        m1 = fmaxf(m1, lrelu(as.y + ad.y));
        m2 = fmaxf(m2, lrelu(as.z + ad.z));
        m3 = fmaxf(m3, lrelu(as.w + ad.w));
    }
    #pragma unroll
    for (int o = 16; o > 0; o >>= 1) {
        m0 = fmaxf(m0, __shfl_xor_sync(0xffffffffu, m0, o));
        m1 = fmaxf(m1, __shfl_xor_sync(0xffffffffu, m1, o));
        m2 = fmaxf(m2, __shfl_xor_sync(0xffffffffu, m2, o));
        m3 = fmaxf(m3, __shfl_xor_sync(0xffffffffu, m3, o));
    }

    float s0 = 0.f, s1 = 0.f, s2 = 0.f, s3 = 0.f;
    for (int p = beg + lane; p < end; p += 32) {
        int s = g_csrc[p];
        float4 as = *(const float4*)(g_asrc + (size_t)s * 4);
        s0 += __expf(lrelu(as.x + ad.x) - m0);
        s1 += __expf(lrelu(as.y + ad.y) - m1);
        s2 += __expf(lrelu(as.z + ad.z) - m2);
        s3 += __expf(lrelu(as.w + ad.w) - m3);
    }
    #pragma unroll
    for (int o = 16; o > 0; o >>= 1) {
        s0 += __shfl_xor_sync(0xffffffffu, s0, o);
        s1 += __shfl_xor_sync(0xffffffffu, s1, o);
        s2 += __shfl_xor_sync(0xffffffffu, s2, o);
        s3 += __shfl_xor_sync(0xffffffffu, s3, o);
    }
    const float i0 = 1.f / (s0 + 1e-16f);
    const float i1 = 1.f / (s1 + 1e-16f);
    const float i2 = 1.f / (s2 + 1e-16f);
    const float i3 = 1.f / (s3 + 1e-16f);

    const int hsel = lane >> 4;
    const float mh0 = hsel ? m1 : m0;
    const float mh1 = hsel ? m3 : m2;
    const float ih0 = hsel ? i1 : i0;
    const float ih1 = hsel ? i3 : i2;

    float4 acc0 = make_float4(0.f, 0.f, 0.f, 0.f);
    float4 acc1 = make_float4(0.f, 0.f, 0.f, 0.f);
    const float* xh0 = g_xh + (size_t)lane * 4;
    const float* xh1 = g_xh + 128 + (size_t)lane * 4;

    for (int p = beg; p < end; p++) {
        int s = g_csrc[p];
        float4 as = *(const float4*)(g_asrc + (size_t)s * 4);
        float e0 = lrelu(as.x + ad.x);
        float e1 = lrelu(as.y + ad.y);
        float e2 = lrelu(as.z + ad.z);
        float e3 = lrelu(as.w + ad.w);
        float eh0 = hsel ? e1 : e0;
        float eh1 = hsel ? e3 : e2;
        float a0 = __expf(eh0 - mh0) * ih0;
        float a1 = __expf(eh1 - mh1) * ih1;
        float4 x0 = *(const float4*)(xh0 + (size_t)s * HC);
        float4 x1 = *(const float4*)(xh1 + (size_t)s * HC);
        acc0.x = fmaf(a0, x0.x, acc0.x);
        acc0.y = fmaf(a0, x0.y, acc0.y);
        acc0.z = fmaf(a0, x0.z, acc0.z);
        acc0.w = fmaf(a0, x0.w, acc0.w);
        acc1.x = fmaf(a1, x1.x, acc1.x);
        acc1.y = fmaf(a1, x1.y, acc1.y);
        acc1.z = fmaf(a1, x1.z, acc1.z);
        acc1.w = fmaf(a1, x1.w, acc1.w);
    }

    float4 b0 = *(const float4*)(bias + lane * 4);
    float4 b1 = *(const float4*)(bias + 128 + lane * 4);
    float v[8];
    v[0] = fmaxf(acc0.x + b0.x, 0.f);
    v[1] = fmaxf(acc0.y + b0.y, 0.f);
    v[2] = fmaxf(acc0.z + b0.z, 0.f);
    v[3] = fmaxf(acc0.w + b0.w, 0.f);
    v[4] = fmaxf(acc1.x + b1.x, 0.f);
    v[5] = fmaxf(acc1.y + b1.y, 0.f);
    v[6] = fmaxf(acc1.z + b1.z, 0.f);
    v[7] = fmaxf(acc1.w + b1.w, 0.f);
    size_t base0 = (size_t)d * HC + lane * 4;
    size_t base1 = (size_t)d * HC + 128 + lane * 4;
    #pragma unroll
    for (int j = 0; j < 4; j++) {
        split_bf16(v[j],     &g_ahi[base0 + j], &g_alo[base0 + j]);
        split_bf16(v[4 + j], &g_ahi[base1 + j], &g_alo[base1 + j]);
    }
}

// ---------------- host ----------------
extern "C" void kernel_launch(void* const* d_in, const int* in_sizes, int n_in,
                              void* d_out, int out_size) {
    const float*     x   = (const float*)d_in[0];
    const long long* ei  = (const long long*)d_in[1];
    const float* W1  = (const float*)d_in[3];
    const float* as1 = (const float*)d_in[4];
    const float* ad1 = (const float*)d_in[5];
    const float* b1  = (const float*)d_in[6];
    const float* W2  = (const float*)d_in[7];
    const float* as2 = (const float*)d_in[8];
    const float* ad2 = (const float*)d_in[9];
    const float* b2  = (const float*)d_in[10];
    const float* Wfc = (const float*)d_in[11];
    const float* bfc = (const float*)d_in[12];
    float* out = (float*)d_out;

    float *p_xh = nullptr;
    __nv_bfloat16 *p_ahi = nullptr, *p_alo = nullptr;
    __nv_bfloat16 *p_b1hi = nullptr, *p_b1lo = nullptr;
    __nv_bfloat16 *p_b2hi = nullptr, *p_b2lo = nullptr;
    __nv_bfloat16 *p_bfhi = nullptr, *p_bflo = nullptr;
    cudaGetSymbolAddress((void**)&p_xh,  g_xh);
    cudaGetSymbolAddress((void**)&p_ahi, g_ahi);
    cudaGetSymbolAddress((void**)&p_alo, g_alo);
    cudaGetSymbolAddress((void**)&p_b1hi, g_b1hi);
    cudaGetSymbolAddress((void**)&p_b1lo, g_b1lo);
    cudaGetSymbolAddress((void**)&p_b2hi, g_b2hi);
    cudaGetSymbolAddress((void**)&p_b2lo, g_b2lo);
    cudaGetSymbolAddress((void**)&p_bfhi, g_bfhi);
    cudaGetSymbolAddress((void**)&p_bflo, g_bflo);

    const int TPB = 256;
    const int eblk = (ET + TPB - 1) / TPB;
    const int nblk = (NN + TPB - 1) / TPB;
    const int ablk = (NN * HEADS * 32 + TPB - 1) / TPB;
    const int gblk = (NN * 32 + TPB - 1) / TPB;
    const int mtiles = (NN + 127) / 128;   // 391

    // launch order keeps the layer-1 tensor GEMM at index 5 for ncu (-s 5 -c 1)
    detect_kernel<<<1, 32>>>(ei);                                   // 0
    zero_deg_kernel<<<nblk, TPB>>>();                               // 1
    convert_hist_kernel<<<eblk, TPB>>>((const void*)ei);            // 2
    conv_x_kernel<<<4096, TPB>>>(x);                                // 3
    conv_w_kernel<<<(128*256 + 256*256 + 256*64 + TPB - 1) / TPB, TPB>>>(W1, W2, Wfc); // 4
    {
        dim3 grid(2, mtiles);
        gemm_mma_kernel<128, 128, 256, false><<<grid, 256>>>(       // 5 (profiled)
            p_ahi, p_alo, p_b1hi, p_b1lo, p_xh, nullptr);
    }
    scan_partial_kernel<<<NBLK, SCAN_B>>>();                        // 6
    scan_part2_kernel<<<1, SCAN_B>>>();                             // 7
    scan_final_kernel<<<NBLK, SCAN_B>>>();                          // 8
    scatter_kernel<<<eblk, TPB>>>();                                // 9
    alpha_kernel<<<ablk, TPB>>>(as1, ad1);                          // 10
    agg_kernel<<<gblk, TPB>>>(b1);                                  // 11
    {
        dim3 grid(2, mtiles);
        gemm_mma_kernel<128, 256, 256, false><<<grid, 256>>>(       // 12
            p_ahi, p_alo, p_b2hi, p_b2lo, p_xh, nullptr);
    }
    alpha_kernel<<<ablk, TPB>>>(as2, ad2);                          // 13
    agg_kernel<<<gblk, TPB>>>(b2);                                  // 14
    {
        dim3 grid(1, mtiles);
        gemm_mma_kernel<64, 256, 64, true><<<grid, 256>>>(          // 15
            p_ahi, p_alo, p_bfhi, p_bflo, out, bfc);
    }
}

// round 6
// speedup vs baseline: 6.4744x; 1.0710x over previous
#include <cuda_runtime.h>
#include <cuda_bf16.h>
#include <cstdint>
#include <cfloat>

// Problem constants
#define NN     50000
#define EIN    800000
#define ET     (EIN + NN)
#define IND    128
#define HEADS  4
#define HID    64
#define HC     256
#define OUTD   64
#define NEG_SLOPE 0.2f

#define SCAN_B 256
#define NBLK   ((NN + SCAN_B - 1) / SCAN_B)

// ---------------- device scratch ----------------
__device__ float g_xh  [(size_t)NN * HC];
__device__ float g_asrc[(size_t)NN * HEADS];
__device__ float g_adst[(size_t)NN * HEADS];
__device__ __align__(16) __nv_bfloat16 g_ahi[(size_t)NN * HC];
__device__ __align__(16) __nv_bfloat16 g_alo[(size_t)NN * HC];
__device__ __align__(16) __nv_bfloat16 g_b1hi[256 * 128];
__device__ __align__(16) __nv_bfloat16 g_b1lo[256 * 128];
__device__ __align__(16) __nv_bfloat16 g_b2hi[256 * 256];
__device__ __align__(16) __nv_bfloat16 g_b2lo[256 * 256];
__device__ __align__(16) __nv_bfloat16 g_bfhi[64 * 256];
__device__ __align__(16) __nv_bfloat16 g_bflo[64 * 256];
__device__ int   g_deg [NN];
__device__ int   g_off [NN + 1];
__device__ int   g_cur [NN];
__device__ int   g_part[NBLK];
__device__ int   g_csrc[ET];
__device__ int   g_src [ET];
__device__ int   g_dst [ET];
__device__ int   g_is64;

__device__ __forceinline__ float lrelu(float v) {
    return v >= 0.f ? v : NEG_SLOPE * v;
}
__device__ __forceinline__ void split_bf16(float v, __nv_bfloat16* hi, __nv_bfloat16* lo) {
    __nv_bfloat16 h = __float2bfloat16(v);
    *hi = h;
    *lo = __float2bfloat16(v - __bfloat162float(h));
}

// ---------------- edge index prep ----------------
__global__ void detect_kernel(const long long* __restrict__ ei) {
    if (threadIdx.x == 0 && blockIdx.x == 0) {
        int is64 = 1;
        for (int k = 0; k < 16; k++) {
            long long v = ei[k];
            if (v < 0 || v >= (long long)NN) { is64 = 0; break; }
        }
        g_is64 = is64;
    }
}

// zero deg + alpha accumulators
__global__ void zero_all_kernel() {
    int i = blockIdx.x * blockDim.x + threadIdx.x;
    if (i < NN) g_deg[i] = 0;
    if (i < NN * HEADS) { g_asrc[i] = 0.f; g_adst[i] = 0.f; }
}

__global__ void zero_alpha_kernel() {
    int i = blockIdx.x * blockDim.x + threadIdx.x;
    if (i < NN * HEADS) { g_asrc[i] = 0.f; g_adst[i] = 0.f; }
}

__global__ void convert_hist_kernel(const void* __restrict__ ei) {
    int i = blockIdx.x * blockDim.x + threadIdx.x;
    if (i >= ET) return;
    int s, d;
    if (i < EIN) {
        if (g_is64) {
            const long long* p = (const long long*)ei;
            s = (int)p[i];
            d = (int)p[EIN + i];
        } else {
            const int* p = (const int*)ei;
            s = p[i];
            d = p[EIN + i];
        }
    } else {
        s = d = i - EIN;
    }
    g_src[i] = s;
    g_dst[i] = d;
    atomicAdd(&g_deg[d], 1);
}

// W1 [128,256] -> B1 [256,128]; W2 [256,256] -> B2 [256,256]; Wfc [256,64] -> Bf [64,256]
__global__ void conv_w_kernel(const float* __restrict__ W1,
                              const float* __restrict__ W2,
                              const float* __restrict__ Wfc) {
    int i = blockIdx.x * blockDim.x + threadIdx.x;
    const int s1 = 128 * 256, s2 = s1 + 256 * 256, s3 = s2 + 256 * 64;
    if (i < s1) {
        int k = i / 256, n = i % 256;
        split_bf16(W1[i], &g_b1hi[n * 128 + k], &g_b1lo[n * 128 + k]);
    } else if (i < s2) {
        int j = i - s1;
        int k = j / 256, n = j % 256;
        split_bf16(W2[j], &g_b2hi[n * 256 + k], &g_b2lo[n * 256 + k]);
    } else if (i < s3) {
        int j = i - s2;
        int k = j / 64, n = j % 64;
        split_bf16(Wfc[j], &g_bfhi[n * 256 + k], &g_bflo[n * 256 + k]);
    }
}

// ---------------- mma.sync bf16 helper ----------------
__device__ __forceinline__ void mma16816(float* c, const uint32_t* a, const uint32_t* b) {
    asm volatile(
        "mma.sync.aligned.m16n8k16.row.col.f32.bf16.bf16.f32 "
        "{%0,%1,%2,%3}, {%4,%5,%6,%7}, {%8,%9}, {%0,%1,%2,%3};"
        : "+f"(c[0]), "+f"(c[1]), "+f"(c[2]), "+f"(c[3])
        : "r"(a[0]), "r"(a[1]), "r"(a[2]), "r"(a[3]), "r"(b[0]), "r"(b[1]));
}

__device__ __forceinline__ uint32_t pack_bf16x2(float a, float b) {
    __nv_bfloat162 h = __floats2bfloat162_rn(a, b);
    return *(uint32_t*)&h;
}

// ---------------- tensor-core GEMM via mma.sync ----------------
// C[M, NTOT] = A[M, KTOT] @ B[NTOT, KTOT]^T, two-term bf16 split (3 MMA terms).
// Block: 128 x BN tile, 256 threads (8 warps: 2 in M x 4 in N). BK=32, reg prefetch.
// AF32: A given as fp32, split to hi/lo during smem staging.
// ALPHA: epilogue also accumulates asrc/adst = xh . a_src/a_dst per (row, head).
template<int BN, int KTOT, int NTOT, bool BIAS, bool AF32, bool ALPHA>
__global__ void __launch_bounds__(256, 1)
gemm_mma_kernel(const void* __restrict__ Aptr,
                const __nv_bfloat16* __restrict__ Alo,
                const __nv_bfloat16* __restrict__ Bhi,
                const __nv_bfloat16* __restrict__ Blo,
                float* __restrict__ C,
                const float* __restrict__ bias,
                const float* __restrict__ aw_src,
                const float* __restrict__ aw_dst) {
    constexpr int RS  = 40;            // smem row stride (80B, conflict-free)
    constexpr int NF  = BN / 32;
    constexpr int NB4 = BN / 64;

    __shared__ __nv_bfloat16 sm[(2 * 128 + 2 * BN) * RS];
    __nv_bfloat16* smAh = sm;
    __nv_bfloat16* smAl = sm + 128 * RS;
    __nv_bfloat16* smBh = sm + 2 * 128 * RS;
    __nv_bfloat16* smBl = smBh + BN * RS;

    const int tid  = threadIdx.x;
    const int wid  = tid >> 5, lane = tid & 31;
    const int wm   = wid & 1, wn = wid >> 1;
    const int row0 = blockIdx.y * 128;
    const int col0 = blockIdx.x * BN;

    const __nv_bfloat16* Ahi = (const __nv_bfloat16*)Aptr;
    const float* Af = (const float*)Aptr;

    float acc[4][NF][4];
    #pragma unroll
    for (int i = 0; i < 4; i++)
        #pragma unroll
        for (int j = 0; j < NF; j++)
            #pragma unroll
            for (int q = 0; q < 4; q++) acc[i][j][q] = 0.f;

    uint4 pah[2], pal[2], pbh[2], pbl[2];
    float4 pf[4];
    const uint4 Z = make_uint4(0u, 0u, 0u, 0u);
    const float4 ZF = make_float4(0.f, 0.f, 0.f, 0.f);

    // ---- A/B chunk loaders (register prefetch + smem store) ----
    auto loadA = [&](int k0) {
        if (AF32) {
            #pragma unroll
            for (int q = 0; q < 4; q++) {
                int idx = tid + q * 256;
                int row = idx >> 3, c4 = (idx & 7) * 4;
                int gr = row0 + row;
                pf[q] = (gr < NN) ? *(const float4*)(Af + (size_t)gr * KTOT + k0 + c4) : ZF;
            }
        } else {
            #pragma unroll
            for (int q = 0; q < 2; q++) {
                int idx = tid + q * 256;
                int row = idx >> 2, c8 = (idx & 3) * 8;
                int gr = row0 + row;
                pah[q] = (gr < NN) ? *(const uint4*)(Ahi + (size_t)gr * KTOT + k0 + c8) : Z;
                pal[q] = (gr < NN) ? *(const uint4*)(Alo + (size_t)gr * KTOT + k0 + c8) : Z;
            }
        }
    };
    auto storeA = [&]() {
        if (AF32) {
            #pragma unroll
            for (int q = 0; q < 4; q++) {
                int idx = tid + q * 256;
                int row = idx >> 3, c4 = (idx & 7) * 4;
                float4 v = pf[q];
                __nv_bfloat16 h0, h1, h2, h3, l0, l1, l2, l3;
                split_bf16(v.x, &h0, &l0);
                split_bf16(v.y, &h1, &l1);
                split_bf16(v.z, &h2, &l2);
                split_bf16(v.w, &h3, &l3);
                uint2 hh, ll;
                hh.x = pack_bf16x2(__bfloat162float(h0), __bfloat162float(h1));
                hh.y = pack_bf16x2(__bfloat162float(h2), __bfloat162float(h3));
                ll.x = pack_bf16x2(__bfloat162float(l0), __bfloat162float(l1));
                ll.y = pack_bf16x2(__bfloat162float(l2), __bfloat162float(l3));
                *(uint2*)(smAh + row * RS + c4) = hh;
                *(uint2*)(smAl + row * RS + c4) = ll;
            }
        } else {
            #pragma unroll
            for (int q = 0; q < 2; q++) {
                int idx = tid + q * 256;
                int row = idx >> 2, c8 = (idx & 3) * 8;
                *(uint4*)(smAh + row * RS + c8) = pah[q];
                *(uint4*)(smAl + row * RS + c8) = pal[q];
            }
        }
    };
    auto loadB = [&](int k0) {
        #pragma unroll
        for (int q = 0; q < NB4; q++) {
            int idx = tid + q * 256;
            int row = idx >> 2, c8 = (idx & 3) * 8;
            pbh[q] = *(const uint4*)(Bhi + (size_t)(col0 + row) * KTOT + k0 + c8);
            pbl[q] = *(const uint4*)(Blo + (size_t)(col0 + row) * KTOT + k0 + c8);
        }
    };
    auto storeB = [&]() {
        #pragma unroll
        for (int q = 0; q < NB4; q++) {
            int idx = tid + q * 256;
            int row = idx >> 2, c8 = (idx & 3) * 8;
            *(uint4*)(smBh + row * RS + c8) = pbh[q];
            *(uint4*)(smBl + row * RS + c8) = pbl[q];
        }
    };

    loadA(0); loadB(0);
    storeA(); storeB();
    __syncthreads();

    const int arow = (lane >> 2);
    const int acol = (lane & 3) * 2;

    for (int k0 = 32; k0 <= KTOT; k0 += 32) {
        if (k0 < KTOT) { loadA(k0); loadB(k0); }

        #pragma unroll
        for (int ks = 0; ks < 2; ks++) {
            const int kc = ks * 16 + acol;
            uint32_t bh[NF][2], bl[NF][2];
            #pragma unroll
            for (int j = 0; j < NF; j++) {
                int nrow = wn * (BN / 4) + j * 8 + arow;
                bh[j][0] = *(const uint32_t*)(smBh + nrow * RS + kc);
                bh[j][1] = *(const uint32_t*)(smBh + nrow * RS + kc + 8);
                bl[j][0] = *(const uint32_t*)(smBl + nrow * RS + kc);
                bl[j][1] = *(const uint32_t*)(smBl + nrow * RS + kc + 8);
            }
            #pragma unroll
            for (int i = 0; i < 4; i++) {
                int r0 = wm * 64 + i * 16 + arow;
                uint32_t ah[4], al[4];
                ah[0] = *(const uint32_t*)(smAh + r0 * RS + kc);
                ah[1] = *(const uint32_t*)(smAh + (r0 + 8) * RS + kc);
                ah[2] = *(const uint32_t*)(smAh + r0 * RS + kc + 8);
                ah[3] = *(const uint32_t*)(smAh + (r0 + 8) * RS + kc + 8);
                al[0] = *(const uint32_t*)(smAl + r0 * RS + kc);
                al[1] = *(const uint32_t*)(smAl + (r0 + 8) * RS + kc);
                al[2] = *(const uint32_t*)(smAl + r0 * RS + kc + 8);
                al[3] = *(const uint32_t*)(smAl + (r0 + 8) * RS + kc + 8);
                #pragma unroll
                for (int j = 0; j < NF; j++) {
                    mma16816(acc[i][j], ah, bh[j]);
                    mma16816(acc[i][j], ah, bl[j]);
                    mma16816(acc[i][j], al, bh[j]);
                }
            }
        }
        __syncthreads();
        if (k0 < KTOT) {
            storeA(); storeB();
            __syncthreads();
        }
    }

    // ---- epilogue: write C ----
    #pragma unroll
    for (int i = 0; i < 4; i++) {
        int r = row0 + wm * 64 + i * 16 + arow;
        #pragma unroll
        for (int j = 0; j < NF; j++) {
            int c = col0 + wn * (BN / 4) + j * 8 + acol;
            float bx = 0.f, by = 0.f;
            if (BIAS) { bx = bias[c]; by = bias[c + 1]; }
            if (r < NN) {
                float2 v = make_float2(acc[i][j][0] + bx, acc[i][j][1] + by);
                *(float2*)(C + (size_t)r * NTOT + c) = v;
            }
            if (r + 8 < NN) {
                float2 v = make_float2(acc[i][j][2] + bx, acc[i][j][3] + by);
                *(float2*)(C + (size_t)(r + 8) * NTOT + c) = v;
            }
        }
    }

    // ---- epilogue: fused alpha accumulation (asrc/adst) ----
    if (ALPHA) {
        const int hw = (col0 + wn * 32) >> 6;          // head for this warp's 32-col span
        #pragma unroll
        for (int i = 0; i < 4; i++) {
            float ss0 = 0.f, sd0 = 0.f, ss1 = 0.f, sd1 = 0.f;
            #pragma unroll
            for (int j = 0; j < NF; j++) {
                #pragma unroll
                for (int qq = 0; qq < 2; qq++) {
                    int cw = hw * HID + ((wn & 1) * 32 + j * 8 + acol + qq);
                    float ws = aw_src[cw], wd = aw_dst[cw];
                    ss0 += acc[i][j][qq]     * ws;
                    sd0 += acc[i][j][qq]     * wd;
                    ss1 += acc[i][j][2 + qq] * ws;
                    sd1 += acc[i][j][2 + qq] * wd;
                }
            }
            #pragma unroll
            for (int o = 1; o < 4; o <<= 1) {
                ss0 += __shfl_xor_sync(0xffffffffu, ss0, o);
                sd0 += __shfl_xor_sync(0xffffffffu, sd0, o);
                ss1 += __shfl_xor_sync(0xffffffffu, ss1, o);
                sd1 += __shfl_xor_sync(0xffffffffu, sd1, o);
            }
            if ((lane & 3) == 0) {
                int r = row0 + wm * 64 + i * 16 + arow;
                if (r < NN) {
                    atomicAdd(&g_asrc[r * 4 + hw], ss0);
                    atomicAdd(&g_adst[r * 4 + hw], sd0);
                }
                if (r + 8 < NN) {
                    atomicAdd(&g_asrc[(r + 8) * 4 + hw], ss1);
                    atomicAdd(&g_adst[(r + 8) * 4 + hw], sd1);
                }
            }
        }
    }
}

// ---------------- scan (3-phase, device-wide) ----------------
__device__ __forceinline__ int block_excl_scan(int v, int t, int* tot) {
    __shared__ int ws[8];
    int lane = t & 31, w = t >> 5;
    int x = v;
    #pragma unroll
    for (int o = 1; o < 32; o <<= 1) {
        int y = __shfl_up_sync(0xffffffffu, x, o);
        if (lane >= o) x += y;
    }
    if (lane == 31) ws[w] = x;
    __syncthreads();
    if (w == 0) {
        int z = (lane < 8) ? ws[lane] : 0;
        #pragma unroll
        for (int o = 1; o < 8; o <<= 1) {
            int y = __shfl_up_sync(0xffffffffu, z, o);
            if (lane >= o) z += y;
        }
        if (lane < 8) ws[lane] = z;
    }
    __syncthreads();
    int base = (w > 0) ? ws[w - 1] : 0;
    int total = ws[7];
    __syncthreads();
    *tot = total;
    return base + x - v;
}

__global__ void scan_partial_kernel() {
    int i = blockIdx.x * SCAN_B + threadIdx.x;
    int v = (i < NN) ? g_deg[i] : 0;
    int tot;
    block_excl_scan(v, threadIdx.x, &tot);
    if (threadIdx.x == 0) g_part[blockIdx.x] = tot;
}

__global__ void scan_part2_kernel() {
    int t = threadIdx.x;
    int v = (t < NBLK) ? g_part[t] : 0;
    int tot;
    int excl = block_excl_scan(v, t, &tot);
    if (t < NBLK) g_part[t] = excl;
    if (t == 0) g_off[NN] = tot;
}

__global__ void scan_final_kernel() {
    int i = blockIdx.x * SCAN_B + threadIdx.x;
    int v = (i < NN) ? g_deg[i] : 0;
    int tot;
    int excl = block_excl_scan(v, threadIdx.x, &tot) + g_part[blockIdx.x];
    if (i < NN) {
        g_off[i] = excl;
        g_cur[i] = excl;
    }
}

__global__ void scatter_kernel() {
    int i = blockIdx.x * blockDim.x + threadIdx.x;
    if (i >= ET) return;
    int d = g_dst[i];
    int pos = atomicAdd(&g_cur[d], 1);
    g_csrc[pos] = g_src[i];
}

// ---------------- fused softmax + aggregation: one warp per dst node ----------------
// single online pass for (max, expsum), then weighted accumulation.
// writes relu(agg + bias) as bf16 hi/lo split into g_ahi/g_alo, fp32 into xh_out.
__global__ void agg_kernel(const float* __restrict__ bias, float* __restrict__ xh_out) {
    int warp = (blockIdx.x * blockDim.x + threadIdx.x) >> 5;
    int lane = threadIdx.x & 31;
    if (warp >= NN) return;
    const int d = warp;
    const int beg = g_off[d], end = g_off[d + 1];
    const float4 ad = *(const float4*)(g_adst + (size_t)d * 4);

    // online (max, sum) per head
    float m0 = -FLT_MAX, m1 = -FLT_MAX, m2 = -FLT_MAX, m3 = -FLT_MAX;
    float s0 = 0.f, s1 = 0.f, s2 = 0.f, s3 = 0.f;
    for (int p = beg + lane; p < end; p += 32) {
        int s = g_csrc[p];
        float4 as = *(const float4*)(g_asrc + (size_t)s * 4);
        float e0 = lrelu(as.x + ad.x);
        float e1 = lrelu(as.y + ad.y);
        float e2 = lrelu(as.z + ad.z);
        float e3 = lrelu(as.w + ad.w);
        float n0 = fmaxf(m0, e0), n1 = fmaxf(m1, e1);
        float n2 = fmaxf(m2, e2), n3 = fmaxf(m3, e3);
        s0 = s0 * __expf(m0 - n0) + __expf(e0 - n0);
        s1 = s1 * __expf(m1 - n1) + __expf(e1 - n1);
        s2 = s2 * __expf(m2 - n2) + __expf(e2 - n2);
        s3 = s3 * __expf(m3 - n3) + __expf(e3 - n3);
        m0 = n0; m1 = n1; m2 = n2; m3 = n3;
    }
    #pragma unroll
    for (int o = 16; o > 0; o >>= 1) {
        float om, os;
        om = __shfl_xor_sync(0xffffffffu, m0, o); os = __shfl_xor_sync(0xffffffffu, s0, o);
        { float n = fmaxf(m0, om); s0 = s0 * __expf(m0 - n) + os * __expf(om - n); m0 = n; }
        om = __shfl_xor_sync(0xffffffffu, m1, o); os = __shfl_xor_sync(0xffffffffu, s1, o);
        { float n = fmaxf(m1, om); s1 = s1 * __expf(m1 - n) + os * __expf(om - n); m1 = n; }
        om = __shfl_xor_sync(0xffffffffu, m2, o); os = __shfl_xor_sync(0xffffffffu, s2, o);
        { float n = fmaxf(m2, om); s2 = s2 * __expf(m2 - n) + os * __expf(om - n); m2 = n; }
        om = __shfl_xor_sync(0xffffffffu, m3, o); os = __shfl_xor_sync(0xffffffffu, s3, o);
        { float n = fmaxf(m3, om); s3 = s3 * __expf(m3 - n) + os * __expf(om - n); m3 = n; }
    }
    const float i0 = 1.f / (s0 + 1e-16f);
    const float i1 = 1.f / (s1 + 1e-16f);
    const float i2 = 1.f / (s2 + 1e-16f);
    const float i3 = 1.f / (s3 + 1e-16f);

    const int hsel = lane >> 4;
    const float mh0 = hsel ? m1 : m0;
    const float mh1 = hsel ? m3 : m2;
    const float ih0 = hsel ? i1 : i0;
    const float ih1 = hsel ? i3 : i2;

    float4 acc0 = make_float4(0.f, 0.f, 0.f, 0.f);
    float4 acc1 = make_float4(0.f, 0.f, 0.f, 0.f);
    const float* xh0 = g_xh + (size_t)lane * 4;
    const float* xh1 = g_xh + 128 + (size_t)lane * 4;

    for (int p = beg; p < end; p++) {
        int s = g_csrc[p];
        float4 as = *(const float4*)(g_asrc + (size_t)s * 4);
        float e0 = lrelu(as.x + ad.x);
        float e1 = lrelu(as.y + ad.y);
        float e2 = lrelu(as.z + ad.z);
        float e3 = lrelu(as.w + ad.w);
        float eh0 = hsel ? e1 : e0;
        float eh1 = hsel ? e3 : e2;
        float a0 = __expf(eh0 - mh0) * ih0;
        float a1 = __expf(eh1 - mh1) * ih1;
        float4 x0 = *(const float4*)(xh0 + (size_t)s * HC);
        float4 x1 = *(const float4*)(xh1 + (size_t)s * HC);
        acc0.x = fmaf(a0, x0.x, acc0.x);
        acc0.y = fmaf(a0, x0.y, acc0.y);
        acc0.z = fmaf(a0, x0.z, acc0.z);
        acc0.w = fmaf(a0, x0.w, acc0.w);
        acc1.x = fmaf(a1, x1.x, acc1.x);
        acc1.y = fmaf(a1, x1.y, acc1.y);
        acc1.z = fmaf(a1, x1.z, acc1.z);
        acc1.w = fmaf(a1, x1.w, acc1.w);
    }

    float4 b0 = *(const float4*)(bias + lane * 4);
    float4 b1 = *(const float4*)(bias + 128 + lane * 4);
    float v[8];
    v[0] = fmaxf(acc0.x + b0.x, 0.f);
    v[1] = fmaxf(acc0.y + b0.y, 0.f);
    v[2] = fmaxf(acc0.z + b0.z, 0.f);
    v[3] = fmaxf(acc0.w + b0.w, 0.f);
    v[4] = fmaxf(acc1.x + b1.x, 0.f);
    v[5] = fmaxf(acc1.y + b1.y, 0.f);
    v[6] = fmaxf(acc1.z + b1.z, 0.f);
    v[7] = fmaxf(acc1.w + b1.w, 0.f);
    size_t base0 = (size_t)d * HC + lane * 4;
    size_t base1 = (size_t)d * HC + 128 + lane * 4;
    #pragma unroll
    for (int j = 0; j < 4; j++) {
        split_bf16(v[j],     &g_ahi[base0 + j], &g_alo[base0 + j]);
        split_bf16(v[4 + j], &g_ahi[base1 + j], &g_alo[base1 + j]);
    }
    (void)xh_out;
}

// ---------------- host ----------------
extern "C" void kernel_launch(void* const* d_in, const int* in_sizes, int n_in,
                              void* d_out, int out_size) {
    const float*     x   = (const float*)d_in[0];
    const long long* ei  = (const long long*)d_in[1];
    const float* W1  = (const float*)d_in[3];
    const float* as1 = (const float*)d_in[4];
    const float* ad1 = (const float*)d_in[5];
    const float* b1  = (const float*)d_in[6];
    const float* W2  = (const float*)d_in[7];
    const float* as2 = (const float*)d_in[8];
    const float* ad2 = (const float*)d_in[9];
    const float* b2  = (const float*)d_in[10];
    const float* Wfc = (const float*)d_in[11];
    const float* bfc = (const float*)d_in[12];
    float* out = (float*)d_out;

    float *p_xh = nullptr;
    __nv_bfloat16 *p_ahi = nullptr, *p_alo = nullptr;
    __nv_bfloat16 *p_b1hi = nullptr, *p_b1lo = nullptr;
    __nv_bfloat16 *p_b2hi = nullptr, *p_b2lo = nullptr;
    __nv_bfloat16 *p_bfhi = nullptr, *p_bflo = nullptr;
    cudaGetSymbolAddress((void**)&p_xh,  g_xh);
    cudaGetSymbolAddress((void**)&p_ahi, g_ahi);
    cudaGetSymbolAddress((void**)&p_alo, g_alo);
    cudaGetSymbolAddress((void**)&p_b1hi, g_b1hi);
    cudaGetSymbolAddress((void**)&p_b1lo, g_b1lo);
    cudaGetSymbolAddress((void**)&p_b2hi, g_b2hi);
    cudaGetSymbolAddress((void**)&p_b2lo, g_b2lo);
    cudaGetSymbolAddress((void**)&p_bfhi, g_bfhi);
    cudaGetSymbolAddress((void**)&p_bflo, g_bflo);

    const int TPB = 256;
    const int eblk = (ET + TPB - 1) / TPB;
    const int zblk = (NN * HEADS + TPB - 1) / TPB;
    const int gblk = (NN * 32 + TPB - 1) / TPB;
    const int mtiles = (NN + 127) / 128;   // 391

    detect_kernel<<<1, 32>>>(ei);                                   // 0
    zero_all_kernel<<<zblk, TPB>>>();                               // 1
    convert_hist_kernel<<<eblk, TPB>>>((const void*)ei);            // 2
    conv_w_kernel<<<(128*256 + 256*256 + 256*64 + TPB - 1) / TPB, TPB>>>(W1, W2, Wfc); // 3
    scan_partial_kernel<<<NBLK, SCAN_B>>>();                        // 4
    {
        dim3 grid(2, mtiles);
        gemm_mma_kernel<128, 128, 256, false, true, true><<<grid, 256>>>( // 5 (profiled)
            x, nullptr, p_b1hi, p_b1lo, p_xh, nullptr, as1, ad1);
    }
    scan_part2_kernel<<<1, SCAN_B>>>();                             // 6
    scan_final_kernel<<<NBLK, SCAN_B>>>();                          // 7
    scatter_kernel<<<eblk, TPB>>>();                                // 8
    agg_kernel<<<gblk, TPB>>>(b1, p_xh);                            // 9
    zero_alpha_kernel<<<zblk, TPB>>>();                             // 10
    {
        dim3 grid(2, mtiles);
        gemm_mma_kernel<128, 256, 256, false, false, true><<<grid, 256>>>( // 11
            p_ahi, p_alo, p_b2hi, p_b2lo, p_xh, nullptr, as2, ad2);
    }
    agg_kernel<<<gblk, TPB>>>(b2, p_xh);                            // 12
    {
        dim3 grid(1, mtiles);
        gemm_mma_kernel<64, 256, 64, true, false, false><<<grid, 256>>>(   // 13
            p_ahi, p_alo, p_bfhi, p_bflo, out, bfc, nullptr, nullptr);
    }
}

// round 7
// speedup vs baseline: 7.1879x; 1.1102x over previous
#include <cuda_runtime.h>
#include <cuda_bf16.h>
#include <cuda_fp16.h>
#include <cstdint>
#include <cfloat>

// Problem constants
#define NN     50000
#define EIN    800000
#define ET     (EIN + NN)
#define IND    128
#define HEADS  4
#define HID    64
#define HC     256
#define OUTD   64
#define NEG_SLOPE 0.2f

#define SCAN_B 256
#define NBLK   ((NN + SCAN_B - 1) / SCAN_B)

// ---------------- device scratch ----------------
__device__ __align__(16) __half g_xh16[(size_t)NN * HC];   // fp16 message table
__device__ float g_asrc[(size_t)NN * HEADS];
__device__ float g_adst[(size_t)NN * HEADS];
__device__ __align__(16) __nv_bfloat16 g_ahi[(size_t)NN * HC];
__device__ __align__(16) __nv_bfloat16 g_alo[(size_t)NN * HC];
__device__ __align__(16) __nv_bfloat16 g_b1hi[256 * 128];
__device__ __align__(16) __nv_bfloat16 g_b1lo[256 * 128];
__device__ __align__(16) __nv_bfloat16 g_b2hi[256 * 256];
__device__ __align__(16) __nv_bfloat16 g_b2lo[256 * 256];
__device__ __align__(16) __nv_bfloat16 g_bfhi[64 * 256];
__device__ __align__(16) __nv_bfloat16 g_bflo[64 * 256];
__device__ int   g_deg [NN];
__device__ int   g_off [NN + 1];
__device__ int   g_cur [NN];
__device__ int   g_part[NBLK];
__device__ int   g_csrc[ET];
__device__ int   g_src [ET];
__device__ int   g_dst [ET];
__device__ int   g_is64;

__device__ __forceinline__ float lrelu(float v) {
    return v >= 0.f ? v : NEG_SLOPE * v;
}
__device__ __forceinline__ void split_bf16(float v, __nv_bfloat16* hi, __nv_bfloat16* lo) {
    __nv_bfloat16 h = __float2bfloat16(v);
    *hi = h;
    *lo = __float2bfloat16(v - __bfloat162float(h));
}

// ---------------- edge index prep ----------------
__global__ void detect_kernel(const long long* __restrict__ ei) {
    if (threadIdx.x == 0 && blockIdx.x == 0) {
        int is64 = 1;
        for (int k = 0; k < 16; k++) {
            long long v = ei[k];
            if (v < 0 || v >= (long long)NN) { is64 = 0; break; }
        }
        g_is64 = is64;
    }
}

__global__ void zero_all_kernel() {
    int i = blockIdx.x * blockDim.x + threadIdx.x;
    if (i < NN) g_deg[i] = 0;
    if (i < NN * HEADS) { g_asrc[i] = 0.f; g_adst[i] = 0.f; }
}

__global__ void zero_alpha_kernel() {
    int i = blockIdx.x * blockDim.x + threadIdx.x;
    if (i < NN * HEADS) { g_asrc[i] = 0.f; g_adst[i] = 0.f; }
}

__global__ void convert_hist_kernel(const void* __restrict__ ei) {
    int i = blockIdx.x * blockDim.x + threadIdx.x;
    if (i >= ET) return;
    int s, d;
    if (i < EIN) {
        if (g_is64) {
            const long long* p = (const long long*)ei;
            s = (int)p[i];
            d = (int)p[EIN + i];
        } else {
            const int* p = (const int*)ei;
            s = p[i];
            d = p[EIN + i];
        }
    } else {
        s = d = i - EIN;
    }
    g_src[i] = s;
    g_dst[i] = d;
    atomicAdd(&g_deg[d], 1);
}

// W1 [128,256] -> B1 [256,128]; W2 [256,256] -> B2 [256,256]; Wfc [256,64] -> Bf [64,256]
__global__ void conv_w_kernel(const float* __restrict__ W1,
                              const float* __restrict__ W2,
                              const float* __restrict__ Wfc) {
    int i = blockIdx.x * blockDim.x + threadIdx.x;
    const int s1 = 128 * 256, s2 = s1 + 256 * 256, s3 = s2 + 256 * 64;
    if (i < s1) {
        int k = i / 256, n = i % 256;
        split_bf16(W1[i], &g_b1hi[n * 128 + k], &g_b1lo[n * 128 + k]);
    } else if (i < s2) {
        int j = i - s1;
        int k = j / 256, n = j % 256;
        split_bf16(W2[j], &g_b2hi[n * 256 + k], &g_b2lo[n * 256 + k]);
    } else if (i < s3) {
        int j = i - s2;
        int k = j / 64, n = j % 64;
        split_bf16(Wfc[j], &g_bfhi[n * 256 + k], &g_bflo[n * 256 + k]);
    }
}

// ---------------- mma.sync bf16 helper ----------------
__device__ __forceinline__ void mma16816(float* c, const uint32_t* a, const uint32_t* b) {
    asm volatile(
        "mma.sync.aligned.m16n8k16.row.col.f32.bf16.bf16.f32 "
        "{%0,%1,%2,%3}, {%4,%5,%6,%7}, {%8,%9}, {%0,%1,%2,%3};"
        : "+f"(c[0]), "+f"(c[1]), "+f"(c[2]), "+f"(c[3])
        : "r"(a[0]), "r"(a[1]), "r"(a[2]), "r"(a[3]), "r"(b[0]), "r"(b[1]));
}

__device__ __forceinline__ uint32_t pack_bf16x2(float a, float b) {
    __nv_bfloat162 h = __floats2bfloat162_rn(a, b);
    return *(uint32_t*)&h;
}

// ---------------- tensor-core GEMM via mma.sync ----------------
// C[M, NTOT] = A[M, KTOT] @ B[NTOT, KTOT]^T, two-term bf16 split (3 MMA terms).
// AF32: A given fp32, split during staging. ALPHA: fused asrc/adst accumulation.
// OUTF16: write fp16 (message table); else fp32 (+bias).
template<int BN, int KTOT, int NTOT, bool BIAS, bool AF32, bool ALPHA, bool OUTF16>
__global__ void __launch_bounds__(256, 1)
gemm_mma_kernel(const void* __restrict__ Aptr,
                const __nv_bfloat16* __restrict__ Alo,
                const __nv_bfloat16* __restrict__ Bhi,
                const __nv_bfloat16* __restrict__ Blo,
                void* __restrict__ Cptr,
                const float* __restrict__ bias,
                const float* __restrict__ aw_src,
                const float* __restrict__ aw_dst) {
    constexpr int RS  = 40;
    constexpr int NF  = BN / 32;
    constexpr int NB4 = BN / 64;

    __shared__ __nv_bfloat16 sm[(2 * 128 + 2 * BN) * RS];
    __nv_bfloat16* smAh = sm;
    __nv_bfloat16* smAl = sm + 128 * RS;
    __nv_bfloat16* smBh = sm + 2 * 128 * RS;
    __nv_bfloat16* smBl = smBh + BN * RS;

    const int tid  = threadIdx.x;
    const int wid  = tid >> 5, lane = tid & 31;
    const int wm   = wid & 1, wn = wid >> 1;
    const int row0 = blockIdx.y * 128;
    const int col0 = blockIdx.x * BN;

    const __nv_bfloat16* Ahi = (const __nv_bfloat16*)Aptr;
    const float* Af = (const float*)Aptr;

    float acc[4][NF][4];
    #pragma unroll
    for (int i = 0; i < 4; i++)
        #pragma unroll
        for (int j = 0; j < NF; j++)
            #pragma unroll
            for (int q = 0; q < 4; q++) acc[i][j][q] = 0.f;

    uint4 pah[2], pal[2], pbh[2], pbl[2];
    float4 pf[4];
    const uint4 Z = make_uint4(0u, 0u, 0u, 0u);
    const float4 ZF = make_float4(0.f, 0.f, 0.f, 0.f);

    auto loadA = [&](int k0) {
        if (AF32) {
            #pragma unroll
            for (int q = 0; q < 4; q++) {
                int idx = tid + q * 256;
                int row = idx >> 3, c4 = (idx & 7) * 4;
                int gr = row0 + row;
                pf[q] = (gr < NN) ? *(const float4*)(Af + (size_t)gr * KTOT + k0 + c4) : ZF;
            }
        } else {
            #pragma unroll
            for (int q = 0; q < 2; q++) {
                int idx = tid + q * 256;
                int row = idx >> 2, c8 = (idx & 3) * 8;
                int gr = row0 + row;
                pah[q] = (gr < NN) ? *(const uint4*)(Ahi + (size_t)gr * KTOT + k0 + c8) : Z;
                pal[q] = (gr < NN) ? *(const uint4*)(Alo + (size_t)gr * KTOT + k0 + c8) : Z;
            }
        }
    };
    auto storeA = [&]() {
        if (AF32) {
            #pragma unroll
            for (int q = 0; q < 4; q++) {
                int idx = tid + q * 256;
                int row = idx >> 3, c4 = (idx & 7) * 4;
                float4 v = pf[q];
                __nv_bfloat16 h0, h1, h2, h3, l0, l1, l2, l3;
                split_bf16(v.x, &h0, &l0);
                split_bf16(v.y, &h1, &l1);
                split_bf16(v.z, &h2, &l2);
                split_bf16(v.w, &h3, &l3);
                uint2 hh, ll;
                hh.x = pack_bf16x2(__bfloat162float(h0), __bfloat162float(h1));
                hh.y = pack_bf16x2(__bfloat162float(h2), __bfloat162float(h3));
                ll.x = pack_bf16x2(__bfloat162float(l0), __bfloat162float(l1));
                ll.y = pack_bf16x2(__bfloat162float(l2), __bfloat162float(l3));
                *(uint2*)(smAh + row * RS + c4) = hh;
                *(uint2*)(smAl + row * RS + c4) = ll;
            }
        } else {
            #pragma unroll
            for (int q = 0; q < 2; q++) {
                int idx = tid + q * 256;
                int row = idx >> 2, c8 = (idx & 3) * 8;
                *(uint4*)(smAh + row * RS + c8) = pah[q];
                *(uint4*)(smAl + row * RS + c8) = pal[q];
            }
        }
    };
    auto loadB = [&](int k0) {
        #pragma unroll
        for (int q = 0; q < NB4; q++) {
            int idx = tid + q * 256;
            int row = idx >> 2, c8 = (idx & 3) * 8;
            pbh[q] = *(const uint4*)(Bhi + (size_t)(col0 + row) * KTOT + k0 + c8);
            pbl[q] = *(const uint4*)(Blo + (size_t)(col0 + row) * KTOT + k0 + c8);
        }
    };
    auto storeB = [&]() {
        #pragma unroll
        for (int q = 0; q < NB4; q++) {
            int idx = tid + q * 256;
            int row = idx >> 2, c8 = (idx & 3) * 8;
            *(uint4*)(smBh + row * RS + c8) = pbh[q];
            *(uint4*)(smBl + row * RS + c8) = pbl[q];
        }
    };

    loadA(0); loadB(0);
    storeA(); storeB();
    __syncthreads();

    const int arow = (lane >> 2);
    const int acol = (lane & 3) * 2;

    for (int k0 = 32; k0 <= KTOT; k0 += 32) {
        if (k0 < KTOT) { loadA(k0); loadB(k0); }

        #pragma unroll
        for (int ks = 0; ks < 2; ks++) {
            const int kc = ks * 16 + acol;
            uint32_t bh[NF][2], bl[NF][2];
            #pragma unroll
            for (int j = 0; j < NF; j++) {
                int nrow = wn * (BN / 4) + j * 8 + arow;
                bh[j][0] = *(const uint32_t*)(smBh + nrow * RS + kc);
                bh[j][1] = *(const uint32_t*)(smBh + nrow * RS + kc + 8);
                bl[j][0] = *(const uint32_t*)(smBl + nrow * RS + kc);
                bl[j][1] = *(const uint32_t*)(smBl + nrow * RS + kc + 8);
            }
            #pragma unroll
            for (int i = 0; i < 4; i++) {
                int r0 = wm * 64 + i * 16 + arow;
                uint32_t ah[4], al[4];
                ah[0] = *(const uint32_t*)(smAh + r0 * RS + kc);
                ah[1] = *(const uint32_t*)(smAh + (r0 + 8) * RS + kc);
                ah[2] = *(const uint32_t*)(smAh + r0 * RS + kc + 8);
                ah[3] = *(const uint32_t*)(smAh + (r0 + 8) * RS + kc + 8);
                al[0] = *(const uint32_t*)(smAl + r0 * RS + kc);
                al[1] = *(const uint32_t*)(smAl + (r0 + 8) * RS + kc);
                al[2] = *(const uint32_t*)(smAl + r0 * RS + kc + 8);
                al[3] = *(const uint32_t*)(smAl + (r0 + 8) * RS + kc + 8);
                #pragma unroll
                for (int j = 0; j < NF; j++) {
                    mma16816(acc[i][j], ah, bh[j]);
                    mma16816(acc[i][j], ah, bl[j]);
                    mma16816(acc[i][j], al, bh[j]);
                }
            }
        }
        __syncthreads();
        if (k0 < KTOT) {
            storeA(); storeB();
            __syncthreads();
        }
    }

    // ---- epilogue: write C ----
    #pragma unroll
    for (int i = 0; i < 4; i++) {
        int r = row0 + wm * 64 + i * 16 + arow;
        #pragma unroll
        for (int j = 0; j < NF; j++) {
            int c = col0 + wn * (BN / 4) + j * 8 + acol;
            if (OUTF16) {
                __half* C16 = (__half*)Cptr;
                if (r < NN) {
                    __half2 v = __floats2half2_rn(acc[i][j][0], acc[i][j][1]);
                    *(__half2*)(C16 + (size_t)r * NTOT + c) = v;
                }
                if (r + 8 < NN) {
                    __half2 v = __floats2half2_rn(acc[i][j][2], acc[i][j][3]);
                    *(__half2*)(C16 + (size_t)(r + 8) * NTOT + c) = v;
                }
            } else {
                float* C = (float*)Cptr;
                float bx = 0.f, by = 0.f;
                if (BIAS) { bx = bias[c]; by = bias[c + 1]; }
                if (r < NN) {
                    float2 v = make_float2(acc[i][j][0] + bx, acc[i][j][1] + by);
                    *(float2*)(C + (size_t)r * NTOT + c) = v;
                }
                if (r + 8 < NN) {
                    float2 v = make_float2(acc[i][j][2] + bx, acc[i][j][3] + by);
                    *(float2*)(C + (size_t)(r + 8) * NTOT + c) = v;
                }
            }
        }
    }

    // ---- epilogue: fused alpha accumulation ----
    if (ALPHA) {
        const int hw = (col0 + wn * 32) >> 6;
        #pragma unroll
        for (int i = 0; i < 4; i++) {
            float ss0 = 0.f, sd0 = 0.f, ss1 = 0.f, sd1 = 0.f;
            #pragma unroll
            for (int j = 0; j < NF; j++) {
                #pragma unroll
                for (int qq = 0; qq < 2; qq++) {
                    int cw = hw * HID + ((wn & 1) * 32 + j * 8 + acol + qq);
                    float ws = aw_src[cw], wd = aw_dst[cw];
                    ss0 += acc[i][j][qq]     * ws;
                    sd0 += acc[i][j][qq]     * wd;
                    ss1 += acc[i][j][2 + qq] * ws;
                    sd1 += acc[i][j][2 + qq] * wd;
                }
            }
            #pragma unroll
            for (int o = 1; o < 4; o <<= 1) {
                ss0 += __shfl_xor_sync(0xffffffffu, ss0, o);
                sd0 += __shfl_xor_sync(0xffffffffu, sd0, o);
                ss1 += __shfl_xor_sync(0xffffffffu, ss1, o);
                sd1 += __shfl_xor_sync(0xffffffffu, sd1, o);
            }
            if ((lane & 3) == 0) {
                int r = row0 + wm * 64 + i * 16 + arow;
                if (r < NN) {
                    atomicAdd(&g_asrc[r * 4 + hw], ss0);
                    atomicAdd(&g_adst[r * 4 + hw], sd0);
                }
                if (r + 8 < NN) {
                    atomicAdd(&g_asrc[(r + 8) * 4 + hw], ss1);
                    atomicAdd(&g_adst[(r + 8) * 4 + hw], sd1);
                }
            }
        }
    }
}

// ---------------- scan (3-phase, device-wide) ----------------
__device__ __forceinline__ int block_excl_scan(int v, int t, int* tot) {
    __shared__ int ws[8];
    int lane = t & 31, w = t >> 5;
    int x = v;
    #pragma unroll
    for (int o = 1; o < 32; o <<= 1) {
        int y = __shfl_up_sync(0xffffffffu, x, o);
        if (lane >= o) x += y;
    }
    if (lane == 31) ws[w] = x;
    __syncthreads();
    if (w == 0) {
        int z = (lane < 8) ? ws[lane] : 0;
        #pragma unroll
        for (int o = 1; o < 8; o <<= 1) {
            int y = __shfl_up_sync(0xffffffffu, z, o);
            if (lane >= o) z += y;
        }
        if (lane < 8) ws[lane] = z;
    }
    __syncthreads();
    int base = (w > 0) ? ws[w - 1] : 0;
    int total = ws[7];
    __syncthreads();
    *tot = total;
    return base + x - v;
}

__global__ void scan_partial_kernel() {
    int i = blockIdx.x * SCAN_B + threadIdx.x;
    int v = (i < NN) ? g_deg[i] : 0;
    int tot;
    block_excl_scan(v, threadIdx.x, &tot);
    if (threadIdx.x == 0) g_part[blockIdx.x] = tot;
}

__global__ void scan_part2_kernel() {
    int t = threadIdx.x;
    int v = (t < NBLK) ? g_part[t] : 0;
    int tot;
    int excl = block_excl_scan(v, t, &tot);
    if (t < NBLK) g_part[t] = excl;
    if (t == 0) g_off[NN] = tot;
}

__global__ void scan_final_kernel() {
    int i = blockIdx.x * SCAN_B + threadIdx.x;
    int v = (i < NN) ? g_deg[i] : 0;
    int tot;
    int excl = block_excl_scan(v, threadIdx.x, &tot) + g_part[blockIdx.x];
    if (i < NN) {
        g_off[i] = excl;
        g_cur[i] = excl;
    }
}

__global__ void scatter_kernel() {
    int i = blockIdx.x * blockDim.x + threadIdx.x;
    if (i >= ET) return;
    int d = g_dst[i];
    int pos = atomicAdd(&g_cur[d], 1);
    g_csrc[pos] = g_src[i];
}

// ---------------- fused softmax + aggregation: one warp per dst node ----------------
// pass 1: online (max,expsum) per head; pass 2: fp16 gather-weighted accumulation.
// lane owns channels [lane*8, lane*8+8)  (head = lane>>3)
__global__ void agg_kernel(const float* __restrict__ bias) {
    int warp = (blockIdx.x * blockDim.x + threadIdx.x) >> 5;
    int lane = threadIdx.x & 31;
    if (warp >= NN) return;
    const int d = warp;
    const int beg = g_off[d], end = g_off[d + 1];
    const float4 ad = *(const float4*)(g_adst + (size_t)d * 4);

    float m0 = -FLT_MAX, m1 = -FLT_MAX, m2 = -FLT_MAX, m3 = -FLT_MAX;
    float s0 = 0.f, s1 = 0.f, s2 = 0.f, s3 = 0.f;
    for (int p = beg + lane; p < end; p += 32) {
        int s = g_csrc[p];
        float4 as = *(const float4*)(g_asrc + (size_t)s * 4);
        float e0 = lrelu(as.x + ad.x);
        float e1 = lrelu(as.y + ad.y);
        float e2 = lrelu(as.z + ad.z);
        float e3 = lrelu(as.w + ad.w);
        float n0 = fmaxf(m0, e0), n1 = fmaxf(m1, e1);
        float n2 = fmaxf(m2, e2), n3 = fmaxf(m3, e3);
        s0 = s0 * __expf(m0 - n0) + __expf(e0 - n0);
        s1 = s1 * __expf(m1 - n1) + __expf(e1 - n1);
        s2 = s2 * __expf(m2 - n2) + __expf(e2 - n2);
        s3 = s3 * __expf(m3 - n3) + __expf(e3 - n3);
        m0 = n0; m1 = n1; m2 = n2; m3 = n3;
    }
    #pragma unroll
    for (int o = 16; o > 0; o >>= 1) {
        float om, os;
        om = __shfl_xor_sync(0xffffffffu, m0, o); os = __shfl_xor_sync(0xffffffffu, s0, o);
        { float n = fmaxf(m0, om); s0 = s0 * __expf(m0 - n) + os * __expf(om - n); m0 = n; }
        om = __shfl_xor_sync(0xffffffffu, m1, o); os = __shfl_xor_sync(0xffffffffu, s1, o);
        { float n = fmaxf(m1, om); s1 = s1 * __expf(m1 - n) + os * __expf(om - n); m1 = n; }
        om = __shfl_xor_sync(0xffffffffu, m2, o); os = __shfl_xor_sync(0xffffffffu, s2, o);
        { float n = fmaxf(m2, om); s2 = s2 * __expf(m2 - n) + os * __expf(om - n); m2 = n; }
        om = __shfl_xor_sync(0xffffffffu, m3, o); os = __shfl_xor_sync(0xffffffffu, s3, o);
        { float n = fmaxf(m3, om); s3 = s3 * __expf(m3 - n) + os * __expf(om - n); m3 = n; }
    }

    const int h = lane >> 3;
    const float adh = (h == 0) ? ad.x : (h == 1) ? ad.y : (h == 2) ? ad.z : ad.w;
    const float mh  = (h == 0) ? m0 : (h == 1) ? m1 : (h == 2) ? m2 : m3;
    const float sh  = (h == 0) ? s0 : (h == 1) ? s1 : (h == 2) ? s2 : s3;
    const float ih  = 1.f / (sh + 1e-16f);

    float acc[8] = {};
    const __half* xrow = g_xh16 + (size_t)lane * 8;

    for (int p = beg; p < end; p++) {
        int s = g_csrc[p];
        float e = lrelu(g_asrc[s * 4 + h] + adh);
        float a = __expf(e - mh) * ih;
        uint4 v = *(const uint4*)(xrow + (size_t)s * HC);
        __half2 h01 = *(__half2*)&v.x;
        __half2 h23 = *(__half2*)&v.y;
        __half2 h45 = *(__half2*)&v.z;
        __half2 h67 = *(__half2*)&v.w;
        float2 f01 = __half22float2(h01);
        float2 f23 = __half22float2(h23);
        float2 f45 = __half22float2(h45);
        float2 f67 = __half22float2(h67);
        acc[0] = fmaf(a, f01.x, acc[0]);
        acc[1] = fmaf(a, f01.y, acc[1]);
        acc[2] = fmaf(a, f23.x, acc[2]);
        acc[3] = fmaf(a, f23.y, acc[3]);
        acc[4] = fmaf(a, f45.x, acc[4]);
        acc[5] = fmaf(a, f45.y, acc[5]);
        acc[6] = fmaf(a, f67.x, acc[6]);
        acc[7] = fmaf(a, f67.y, acc[7]);
    }

    size_t base = (size_t)d * HC + lane * 8;
    #pragma unroll
    for (int j = 0; j < 8; j++) {
        float v = fmaxf(acc[j] + bias[lane * 8 + j], 0.f);
        split_bf16(v, &g_ahi[base + j], &g_alo[base + j]);
    }
}

// ---------------- host ----------------
extern "C" void kernel_launch(void* const* d_in, const int* in_sizes, int n_in,
                              void* d_out, int out_size) {
    const float*     x   = (const float*)d_in[0];
    const long long* ei  = (const long long*)d_in[1];
    const float* W1  = (const float*)d_in[3];
    const float* as1 = (const float*)d_in[4];
    const float* ad1 = (const float*)d_in[5];
    const float* b1  = (const float*)d_in[6];
    const float* W2  = (const float*)d_in[7];
    const float* as2 = (const float*)d_in[8];
    const float* ad2 = (const float*)d_in[9];
    const float* b2  = (const float*)d_in[10];
    const float* Wfc = (const float*)d_in[11];
    const float* bfc = (const float*)d_in[12];
    float* out = (float*)d_out;

    __half *p_xh16 = nullptr;
    __nv_bfloat16 *p_ahi = nullptr, *p_alo = nullptr;
    __nv_bfloat16 *p_b1hi = nullptr, *p_b1lo = nullptr;
    __nv_bfloat16 *p_b2hi = nullptr, *p_b2lo = nullptr;
    __nv_bfloat16 *p_bfhi = nullptr, *p_bflo = nullptr;
    cudaGetSymbolAddress((void**)&p_xh16, g_xh16);
    cudaGetSymbolAddress((void**)&p_ahi, g_ahi);
    cudaGetSymbolAddress((void**)&p_alo, g_alo);
    cudaGetSymbolAddress((void**)&p_b1hi, g_b1hi);
    cudaGetSymbolAddress((void**)&p_b1lo, g_b1lo);
    cudaGetSymbolAddress((void**)&p_b2hi, g_b2hi);
    cudaGetSymbolAddress((void**)&p_b2lo, g_b2lo);
    cudaGetSymbolAddress((void**)&p_bfhi, g_bfhi);
    cudaGetSymbolAddress((void**)&p_bflo, g_bflo);

    const int TPB = 256;
    const int eblk = (ET + TPB - 1) / TPB;
    const int zblk = (NN * HEADS + TPB - 1) / TPB;
    const int gblk = (NN * 32 + TPB - 1) / TPB;
    const int mtiles = (NN + 127) / 128;   // 391

    detect_kernel<<<1, 32>>>(ei);                                   // 0
    zero_all_kernel<<<zblk, TPB>>>();                               // 1
    convert_hist_kernel<<<eblk, TPB>>>((const void*)ei);            // 2
    conv_w_kernel<<<(128*256 + 256*256 + 256*64 + TPB - 1) / TPB, TPB>>>(W1, W2, Wfc); // 3
    scan_partial_kernel<<<NBLK, SCAN_B>>>();                        // 4
    {
        dim3 grid(2, mtiles);
        gemm_mma_kernel<128, 128, 256, false, true, true, true><<<grid, 256>>>( // 5
            x, nullptr, p_b1hi, p_b1lo, p_xh16, nullptr, as1, ad1);
    }
    scan_part2_kernel<<<1, SCAN_B>>>();                             // 6
    scan_final_kernel<<<NBLK, SCAN_B>>>();                          // 7
    scatter_kernel<<<eblk, TPB>>>();                                // 8
    agg_kernel<<<gblk, TPB>>>(b1);                                  // 9
    zero_alpha_kernel<<<zblk, TPB>>>();                             // 10
    {
        dim3 grid(2, mtiles);
        gemm_mma_kernel<128, 256, 256, false, false, true, true><<<grid, 256>>>( // 11
            p_ahi, p_alo, p_b2hi, p_b2lo, p_xh16, nullptr, as2, ad2);
    }
    agg_kernel<<<gblk, TPB>>>(b2);                                  // 12
    {
        dim3 grid(1, mtiles);
        gemm_mma_kernel<64, 256, 64, true, false, false, false><<<grid, 256>>>(  // 13
            p_ahi, p_alo, p_bfhi, p_bflo, out, bfc, nullptr, nullptr);
    }
}

// round 8
// speedup vs baseline: 9.6581x; 1.3437x over previous
#include <cuda_runtime.h>
#include <cuda_fp16.h>
#include <cstdint>
#include <cfloat>

// Problem constants
#define NN     50000
#define EIN    800000
#define ET     (EIN + NN)
#define IND    128
#define HEADS  4
#define HID    64
#define HC     256
#define OUTD   64
#define NEG_SLOPE 0.2f

#define SCAN_B 256
#define NBLK   ((NN + SCAN_B - 1) / SCAN_B)

// ---------------- device scratch ----------------
__device__ __align__(16) __half g_xh16[(size_t)NN * HC];   // messages (GEMM out)
__device__ __align__(16) __half g_h16 [(size_t)NN * HC];   // layer activations
__device__ float g_asrc[(size_t)NN * HEADS];
__device__ float g_adst[(size_t)NN * HEADS];
__device__ __align__(16) __half g_w1[256 * 128];           // transposed fp16 weights
__device__ __align__(16) __half g_w2[256 * 256];
__device__ __align__(16) __half g_wf[64 * 256];
__device__ int   g_deg [NN];
__device__ int   g_off [NN + 1];
__device__ int   g_cur [NN];
__device__ int   g_part[NBLK];
__device__ int   g_csrc[ET];
__device__ int   g_src [ET];
__device__ int   g_dst [ET];
__device__ int   g_is64;

__device__ __forceinline__ float lrelu(float v) {
    return v >= 0.f ? v : NEG_SLOPE * v;
}

// ---------------- edge index prep ----------------
__global__ void detect_kernel(const long long* __restrict__ ei) {
    if (threadIdx.x == 0 && blockIdx.x == 0) {
        int is64 = 1;
        for (int k = 0; k < 16; k++) {
            long long v = ei[k];
            if (v < 0 || v >= (long long)NN) { is64 = 0; break; }
        }
        g_is64 = is64;
    }
}

__global__ void zero_all_kernel() {
    int i = blockIdx.x * blockDim.x + threadIdx.x;
    if (i < NN) g_deg[i] = 0;
    if (i < NN * HEADS) { g_asrc[i] = 0.f; g_adst[i] = 0.f; }
}

__global__ void zero_alpha_kernel() {
    int i = blockIdx.x * blockDim.x + threadIdx.x;
    if (i < NN * HEADS) { g_asrc[i] = 0.f; g_adst[i] = 0.f; }
}

__global__ void convert_hist_kernel(const void* __restrict__ ei) {
    int i = blockIdx.x * blockDim.x + threadIdx.x;
    if (i >= ET) return;
    int s, d;
    if (i < EIN) {
        if (g_is64) {
            const long long* p = (const long long*)ei;
            s = (int)p[i];
            d = (int)p[EIN + i];
        } else {
            const int* p = (const int*)ei;
            s = p[i];
            d = p[EIN + i];
        }
    } else {
        s = d = i - EIN;
    }
    g_src[i] = s;
    g_dst[i] = d;
    atomicAdd(&g_deg[d], 1);
}

// W1 [128,256] -> w1 [256,128]; W2 [256,256] -> w2 [256,256]; Wfc [256,64] -> wf [64,256]
__global__ void conv_w_kernel(const float* __restrict__ W1,
                              const float* __restrict__ W2,
                              const float* __restrict__ Wfc) {
    int i = blockIdx.x * blockDim.x + threadIdx.x;
    const int s1 = 128 * 256, s2 = s1 + 256 * 256, s3 = s2 + 256 * 64;
    if (i < s1) {
        int k = i / 256, n = i % 256;
        g_w1[n * 128 + k] = __float2half(W1[i]);
    } else if (i < s2) {
        int j = i - s1;
        int k = j / 256, n = j % 256;
        g_w2[n * 256 + k] = __float2half(W2[j]);
    } else if (i < s3) {
        int j = i - s2;
        int k = j / 64, n = j % 64;
        g_wf[n * 256 + k] = __float2half(Wfc[j]);
    }
}

// ---------------- mma.sync fp16 helper ----------------
__device__ __forceinline__ void mma16816(float* c, const uint32_t* a, const uint32_t* b) {
    asm volatile(
        "mma.sync.aligned.m16n8k16.row.col.f32.f16.f16.f32 "
        "{%0,%1,%2,%3}, {%4,%5,%6,%7}, {%8,%9}, {%0,%1,%2,%3};"
        : "+f"(c[0]), "+f"(c[1]), "+f"(c[2]), "+f"(c[3])
        : "r"(a[0]), "r"(a[1]), "r"(a[2]), "r"(a[3]), "r"(b[0]), "r"(b[1]));
}

// ---------------- tensor-core GEMM (single fp16 term) ----------------
// C[M, NTOT] = A[M, KTOT] @ B[NTOT, KTOT]^T
// AF32: A fp32, cast during staging. ALPHA: fused asrc/adst. OUTF16 vs fp32(+bias).
template<int BN, int KTOT, int NTOT, bool BIAS, bool AF32, bool ALPHA, bool OUTF16>
__global__ void __launch_bounds__(256, 2)
gemm_mma_kernel(const void* __restrict__ Aptr,
                const __half* __restrict__ B,
                void* __restrict__ Cptr,
                const float* __restrict__ bias,
                const float* __restrict__ aw_src,
                const float* __restrict__ aw_dst) {
    constexpr int RS  = 40;          // smem row stride (80B, conflict-free)
    constexpr int NF  = BN / 32;
    constexpr int NB4 = BN / 64;

    __shared__ __half sm[(128 + BN) * RS];
    __half* smA = sm;
    __half* smB = sm + 128 * RS;

    const int tid  = threadIdx.x;
    const int wid  = tid >> 5, lane = tid & 31;
    const int wm   = wid & 1, wn = wid >> 1;
    const int row0 = blockIdx.y * 128;
    const int col0 = blockIdx.x * BN;

    const __half* A16 = (const __half*)Aptr;
    const float*  Af  = (const float*)Aptr;

    float acc[4][NF][4];
    #pragma unroll
    for (int i = 0; i < 4; i++)
        #pragma unroll
        for (int j = 0; j < NF; j++)
            #pragma unroll
            for (int q = 0; q < 4; q++) acc[i][j][q] = 0.f;

    uint4 pa[2], pb[2];
    float4 pf[4];
    const uint4 Z = make_uint4(0u, 0u, 0u, 0u);
    const float4 ZF = make_float4(0.f, 0.f, 0.f, 0.f);

    auto loadA = [&](int k0) {
        if (AF32) {
            #pragma unroll
            for (int q = 0; q < 4; q++) {
                int idx = tid + q * 256;
                int row = idx >> 3, c4 = (idx & 7) * 4;
                int gr = row0 + row;
                pf[q] = (gr < NN) ? *(const float4*)(Af + (size_t)gr * KTOT + k0 + c4) : ZF;
            }
        } else {
            #pragma unroll
            for (int q = 0; q < 2; q++) {
                int idx = tid + q * 256;
                int row = idx >> 2, c8 = (idx & 3) * 8;
                int gr = row0 + row;
                pa[q] = (gr < NN) ? *(const uint4*)(A16 + (size_t)gr * KTOT + k0 + c8) : Z;
            }
        }
    };
    auto storeA = [&]() {
        if (AF32) {
            #pragma unroll
            for (int q = 0; q < 4; q++) {
                int idx = tid + q * 256;
                int row = idx >> 3, c4 = (idx & 7) * 4;
                float4 v = pf[q];
                __half2 h01 = __floats2half2_rn(v.x, v.y);
                __half2 h23 = __floats2half2_rn(v.z, v.w);
                uint2 u;
                u.x = *(uint32_t*)&h01;
                u.y = *(uint32_t*)&h23;
                *(uint2*)(smA + row * RS + c4) = u;
            }
        } else {
            #pragma unroll
            for (int q = 0; q < 2; q++) {
                int idx = tid + q * 256;
                int row = idx >> 2, c8 = (idx & 3) * 8;
                *(uint4*)(smA + row * RS + c8) = pa[q];
            }
        }
    };
    auto loadB = [&](int k0) {
        #pragma unroll
        for (int q = 0; q < NB4; q++) {
            int idx = tid + q * 256;
            int row = idx >> 2, c8 = (idx & 3) * 8;
            pb[q] = *(const uint4*)(B + (size_t)(col0 + row) * KTOT + k0 + c8);
        }
    };
    auto storeB = [&]() {
        #pragma unroll
        for (int q = 0; q < NB4; q++) {
            int idx = tid + q * 256;
            int row = idx >> 2, c8 = (idx & 3) * 8;
            *(uint4*)(smB + row * RS + c8) = pb[q];
        }
    };

    loadA(0); loadB(0);
    storeA(); storeB();
    __syncthreads();

    const int arow = (lane >> 2);
    const int acol = (lane & 3) * 2;

    for (int k0 = 32; k0 <= KTOT; k0 += 32) {
        if (k0 < KTOT) { loadA(k0); loadB(k0); }

        #pragma unroll
        for (int ks = 0; ks < 2; ks++) {
            const int kc = ks * 16 + acol;
            uint32_t b[NF][2];
            #pragma unroll
            for (int j = 0; j < NF; j++) {
                int nrow = wn * (BN / 4) + j * 8 + arow;
                b[j][0] = *(const uint32_t*)(smB + nrow * RS + kc);
                b[j][1] = *(const uint32_t*)(smB + nrow * RS + kc + 8);
            }
            #pragma unroll
            for (int i = 0; i < 4; i++) {
                int r0 = wm * 64 + i * 16 + arow;
                uint32_t a[4];
                a[0] = *(const uint32_t*)(smA + r0 * RS + kc);
                a[1] = *(const uint32_t*)(smA + (r0 + 8) * RS + kc);
                a[2] = *(const uint32_t*)(smA + r0 * RS + kc + 8);
                a[3] = *(const uint32_t*)(smA + (r0 + 8) * RS + kc + 8);
                #pragma unroll
                for (int j = 0; j < NF; j++)
                    mma16816(acc[i][j], a, b[j]);
            }
        }
        __syncthreads();
        if (k0 < KTOT) {
            storeA(); storeB();
            __syncthreads();
        }
    }

    // ---- epilogue: write C ----
    #pragma unroll
    for (int i = 0; i < 4; i++) {
        int r = row0 + wm * 64 + i * 16 + arow;
        #pragma unroll
        for (int j = 0; j < NF; j++) {
            int c = col0 + wn * (BN / 4) + j * 8 + acol;
            if (OUTF16) {
                __half* C16 = (__half*)Cptr;
                if (r < NN) {
                    __half2 v = __floats2half2_rn(acc[i][j][0], acc[i][j][1]);
                    *(__half2*)(C16 + (size_t)r * NTOT + c) = v;
                }
                if (r + 8 < NN) {
                    __half2 v = __floats2half2_rn(acc[i][j][2], acc[i][j][3]);
                    *(__half2*)(C16 + (size_t)(r + 8) * NTOT + c) = v;
                }
            } else {
                float* C = (float*)Cptr;
                float bx = 0.f, by = 0.f;
                if (BIAS) { bx = bias[c]; by = bias[c + 1]; }
                if (r < NN) {
                    float2 v = make_float2(acc[i][j][0] + bx, acc[i][j][1] + by);
                    *(float2*)(C + (size_t)r * NTOT + c) = v;
                }
                if (r + 8 < NN) {
                    float2 v = make_float2(acc[i][j][2] + bx, acc[i][j][3] + by);
                    *(float2*)(C + (size_t)(r + 8) * NTOT + c) = v;
                }
            }
        }
    }

    // ---- epilogue: fused alpha accumulation ----
    if (ALPHA) {
        const int hw = (col0 + wn * 32) >> 6;
        #pragma unroll
        for (int i = 0; i < 4; i++) {
            float ss0 = 0.f, sd0 = 0.f, ss1 = 0.f, sd1 = 0.f;
            #pragma unroll
            for (int j = 0; j < NF; j++) {
                #pragma unroll
                for (int qq = 0; qq < 2; qq++) {
                    int cw = hw * HID + ((wn & 1) * 32 + j * 8 + acol + qq);
                    float ws = aw_src[cw], wd = aw_dst[cw];
                    ss0 += acc[i][j][qq]     * ws;
                    sd0 += acc[i][j][qq]     * wd;
                    ss1 += acc[i][j][2 + qq] * ws;
                    sd1 += acc[i][j][2 + qq] * wd;
                }
            }
            #pragma unroll
            for (int o = 1; o < 4; o <<= 1) {
                ss0 += __shfl_xor_sync(0xffffffffu, ss0, o);
                sd0 += __shfl_xor_sync(0xffffffffu, sd0, o);
                ss1 += __shfl_xor_sync(0xffffffffu, ss1, o);
                sd1 += __shfl_xor_sync(0xffffffffu, sd1, o);
            }
            if ((lane & 3) == 0) {
                int r = row0 + wm * 64 + i * 16 + arow;
                if (r < NN) {
                    atomicAdd(&g_asrc[r * 4 + hw], ss0);
                    atomicAdd(&g_adst[r * 4 + hw], sd0);
                }
                if (r + 8 < NN) {
                    atomicAdd(&g_asrc[(r + 8) * 4 + hw], ss1);
                    atomicAdd(&g_adst[(r + 8) * 4 + hw], sd1);
                }
            }
        }
    }
}

// ---------------- scan (3-phase, device-wide) ----------------
__device__ __forceinline__ int block_excl_scan(int v, int t, int* tot) {
    __shared__ int ws[8];
    int lane = t & 31, w = t >> 5;
    int x = v;
    #pragma unroll
    for (int o = 1; o < 32; o <<= 1) {
        int y = __shfl_up_sync(0xffffffffu, x, o);
        if (lane >= o) x += y;
    }
    if (lane == 31) ws[w] = x;
    __syncthreads();
    if (w == 0) {
        int z = (lane < 8) ? ws[lane] : 0;
        #pragma unroll
        for (int o = 1; o < 8; o <<= 1) {
            int y = __shfl_up_sync(0xffffffffu, z, o);
            if (lane >= o) z += y;
        }
        if (lane < 8) ws[lane] = z;
    }
    __syncthreads();
    int base = (w > 0) ? ws[w - 1] : 0;
    int total = ws[7];
    __syncthreads();
    *tot = total;
    return base + x - v;
}

__global__ void scan_partial_kernel() {
    int i = blockIdx.x * SCAN_B + threadIdx.x;
    int v = (i < NN) ? g_deg[i] : 0;
    int tot;
    block_excl_scan(v, threadIdx.x, &tot);
    if (threadIdx.x == 0) g_part[blockIdx.x] = tot;
}

__global__ void scan_part2_kernel() {
    int t = threadIdx.x;
    int v = (t < NBLK) ? g_part[t] : 0;
    int tot;
    int excl = block_excl_scan(v, t, &tot);
    if (t < NBLK) g_part[t] = excl;
    if (t == 0) g_off[NN] = tot;
}

__global__ void scan_final_kernel() {
    int i = blockIdx.x * SCAN_B + threadIdx.x;
    int v = (i < NN) ? g_deg[i] : 0;
    int tot;
    int excl = block_excl_scan(v, threadIdx.x, &tot) + g_part[blockIdx.x];
    if (i < NN) {
        g_off[i] = excl;
        g_cur[i] = excl;
    }
}

__global__ void scatter_kernel() {
    int i = blockIdx.x * blockDim.x + threadIdx.x;
    if (i >= ET) return;
    int d = g_dst[i];
    int pos = atomicAdd(&g_cur[d], 1);
    g_csrc[pos] = g_src[i];
}

// ---------------- fused softmax + aggregation: one warp per dst node ----------------
// pass 1: online (max,expsum) per head; pass 2: fp16 gather-weighted accumulation.
// lane owns channels [lane*8, lane*8+8)  (head = lane>>3). writes fp16 h.
__global__ void agg_kernel(const float* __restrict__ bias, __half* __restrict__ hout) {
    int warp = (blockIdx.x * blockDim.x + threadIdx.x) >> 5;
    int lane = threadIdx.x & 31;
    if (warp >= NN) return;
    const int d = warp;
    const int beg = g_off[d], end = g_off[d + 1];
    const float4 ad = *(const float4*)(g_adst + (size_t)d * 4);

    float m0 = -FLT_MAX, m1 = -FLT_MAX, m2 = -FLT_MAX, m3 = -FLT_MAX;
    float s0 = 0.f, s1 = 0.f, s2 = 0.f, s3 = 0.f;
    for (int p = beg + lane; p < end; p += 32) {
        int s = g_csrc[p];
        float4 as = *(const float4*)(g_asrc + (size_t)s * 4);
        float e0 = lrelu(as.x + ad.x);
        float e1 = lrelu(as.y + ad.y);
        float e2 = lrelu(as.z + ad.z);
        float e3 = lrelu(as.w + ad.w);
        float n0 = fmaxf(m0, e0), n1 = fmaxf(m1, e1);
        float n2 = fmaxf(m2, e2), n3 = fmaxf(m3, e3);
        s0 = s0 * __expf(m0 - n0) + __expf(e0 - n0);
        s1 = s1 * __expf(m1 - n1) + __expf(e1 - n1);
        s2 = s2 * __expf(m2 - n2) + __expf(e2 - n2);
        s3 = s3 * __expf(m3 - n3) + __expf(e3 - n3);
        m0 = n0; m1 = n1; m2 = n2; m3 = n3;
    }
    #pragma unroll
    for (int o = 16; o > 0; o >>= 1) {
        float om, os;
        om = __shfl_xor_sync(0xffffffffu, m0, o); os = __shfl_xor_sync(0xffffffffu, s0, o);
        { float n = fmaxf(m0, om); s0 = s0 * __expf(m0 - n) + os * __expf(om - n); m0 = n; }
        om = __shfl_xor_sync(0xffffffffu, m1, o); os = __shfl_xor_sync(0xffffffffu, s1, o);
        { float n = fmaxf(m1, om); s1 = s1 * __expf(m1 - n) + os * __expf(om - n); m1 = n; }
        om = __shfl_xor_sync(0xffffffffu, m2, o); os = __shfl_xor_sync(0xffffffffu, s2, o);
        { float n = fmaxf(m2, om); s2 = s2 * __expf(m2 - n) + os * __expf(om - n); m2 = n; }
        om = __shfl_xor_sync(0xffffffffu, m3, o); os = __shfl_xor_sync(0xffffffffu, s3, o);
        { float n = fmaxf(m3, om); s3 = s3 * __expf(m3 - n) + os * __expf(om - n); m3 = n; }
    }

    const int h = lane >> 3;
    const float adh = (h == 0) ? ad.x : (h == 1) ? ad.y : (h == 2) ? ad.z : ad.w;
    const float mh  = (h == 0) ? m0 : (h == 1) ? m1 : (h == 2) ? m2 : m3;
    const float sh  = (h == 0) ? s0 : (h == 1) ? s1 : (h == 2) ? s2 : s3;
    const float ih  = 1.f / (sh + 1e-16f);

    float acc[8] = {};
    const __half* xrow = g_xh16 + (size_t)lane * 8;

    for (int p = beg; p < end; p++) {
        int s = g_csrc[p];
        float e = lrelu(g_asrc[s * 4 + h] + adh);
        float a = __expf(e - mh) * ih;
        uint4 v = *(const uint4*)(xrow + (size_t)s * HC);
        __half2 h01 = *(__half2*)&v.x;
        __half2 h23 = *(__half2*)&v.y;
        __half2 h45 = *(__half2*)&v.z;
        __half2 h67 = *(__half2*)&v.w;
        float2 f01 = __half22float2(h01);
        float2 f23 = __half22float2(h23);
        float2 f45 = __half22float2(h45);
        float2 f67 = __half22float2(h67);
        acc[0] = fmaf(a, f01.x, acc[0]);
        acc[1] = fmaf(a, f01.y, acc[1]);
        acc[2] = fmaf(a, f23.x, acc[2]);
        acc[3] = fmaf(a, f23.y, acc[3]);
        acc[4] = fmaf(a, f45.x, acc[4]);
        acc[5] = fmaf(a, f45.y, acc[5]);
        acc[6] = fmaf(a, f67.x, acc[6]);
        acc[7] = fmaf(a, f67.y, acc[7]);
    }

    size_t base = (size_t)d * HC + lane * 8;
    #pragma unroll
    for (int j = 0; j < 4; j++) {
        float va = fmaxf(acc[2*j]   + bias[lane * 8 + 2*j],   0.f);
        float vb = fmaxf(acc[2*j+1] + bias[lane * 8 + 2*j+1], 0.f);
        __half2 hv = __floats2half2_rn(va, vb);
        *(__half2*)(hout + base + 2*j) = hv;
    }
}

// ---------------- host ----------------
extern "C" void kernel_launch(void* const* d_in, const int* in_sizes, int n_in,
                              void* d_out, int out_size) {
    const float*     x   = (const float*)d_in[0];
    const long long* ei  = (const long long*)d_in[1];
    const float* W1  = (const float*)d_in[3];
    const float* as1 = (const float*)d_in[4];
    const float* ad1 = (const float*)d_in[5];
    const float* b1  = (const float*)d_in[6];
    const float* W2  = (const float*)d_in[7];
    const float* as2 = (const float*)d_in[8];
    const float* ad2 = (const float*)d_in[9];
    const float* b2  = (const float*)d_in[10];
    const float* Wfc = (const float*)d_in[11];
    const float* bfc = (const float*)d_in[12];
    float* out = (float*)d_out;

    __half *p_xh16 = nullptr, *p_h16 = nullptr;
    __half *p_w1 = nullptr, *p_w2 = nullptr, *p_wf = nullptr;
    cudaGetSymbolAddress((void**)&p_xh16, g_xh16);
    cudaGetSymbolAddress((void**)&p_h16,  g_h16);
    cudaGetSymbolAddress((void**)&p_w1, g_w1);
    cudaGetSymbolAddress((void**)&p_w2, g_w2);
    cudaGetSymbolAddress((void**)&p_wf, g_wf);

    const int TPB = 256;
    const int eblk = (ET + TPB - 1) / TPB;
    const int zblk = (NN * HEADS + TPB - 1) / TPB;
    const int gblk = (NN * 32 + TPB - 1) / TPB;
    const int mtiles = (NN + 127) / 128;   // 391

    detect_kernel<<<1, 32>>>(ei);                                   // 0
    zero_all_kernel<<<zblk, TPB>>>();                               // 1
    convert_hist_kernel<<<eblk, TPB>>>((const void*)ei);            // 2
    conv_w_kernel<<<(128*256 + 256*256 + 256*64 + TPB - 1) / TPB, TPB>>>(W1, W2, Wfc); // 3
    scan_partial_kernel<<<NBLK, SCAN_B>>>();                        // 4
    {
        dim3 grid(2, mtiles);
        gemm_mma_kernel<128, 128, 256, false, true, true, true><<<grid, 256>>>( // 5 (profiled)
            x, p_w1, p_xh16, nullptr, as1, ad1);
    }
    scan_part2_kernel<<<1, SCAN_B>>>();                             // 6
    scan_final_kernel<<<NBLK, SCAN_B>>>();                          // 7
    scatter_kernel<<<eblk, TPB>>>();                                // 8
    agg_kernel<<<gblk, TPB>>>(b1, p_h16);                           // 9
    zero_alpha_kernel<<<zblk, TPB>>>();                             // 10
    {
        dim3 grid(2, mtiles);
        gemm_mma_kernel<128, 256, 256, false, false, true, true><<<grid, 256>>>( // 11
            p_h16, p_w2, p_xh16, nullptr, as2, ad2);
    }
    agg_kernel<<<gblk, TPB>>>(b2, p_h16);                           // 12
    {
        dim3 grid(1, mtiles);
        gemm_mma_kernel<64, 256, 64, true, false, false, false><<<grid, 256>>>(  // 13
            p_h16, p_wf, out, bfc, nullptr, nullptr);
    }
}

// round 9
// speedup vs baseline: 10.2165x; 1.0578x over previous
#include <cuda_runtime.h>
#include <cuda_fp16.h>
#include <cstdint>
#include <cfloat>

// Problem constants
#define NN     50000
#define EIN    800000
#define ET     (EIN + NN)
#define IND    128
#define HEADS  4
#define HID    64
#define HC     256
#define OUTD   64
#define NEG_SLOPE 0.2f

#define SCAN_B 256
#define NBLK   ((NN + SCAN_B - 1) / SCAN_B)

// ---------------- device scratch ----------------
__device__ __align__(16) __half g_xh16[(size_t)NN * HC];   // messages (GEMM out)
__device__ __align__(16) __half g_h16 [(size_t)NN * HC];   // layer activations
__device__ float g_asrcA[(size_t)NN * HEADS];
__device__ float g_adstA[(size_t)NN * HEADS];
__device__ float g_asrcB[(size_t)NN * HEADS];
__device__ float g_adstB[(size_t)NN * HEADS];
__device__ __align__(16) __half g_w1[256 * 128];
__device__ __align__(16) __half g_w2[256 * 256];
__device__ __align__(16) __half g_wf[64 * 256];
__device__ int   g_deg [NN];
__device__ int   g_off [NN + 1];
__device__ int   g_cur [NN];
__device__ int   g_part[NBLK];
__device__ int   g_csrc[ET];
__device__ int   g_src [ET];
__device__ int   g_dst [ET];
__device__ int   g_is64;

__device__ __forceinline__ float lrelu(float v) {
    return v >= 0.f ? v : NEG_SLOPE * v;
}
__device__ __forceinline__ uint32_t smem_u32(const void* p) {
    uint32_t a;
    asm("{ .reg .u64 t; cvta.to.shared.u64 t, %1; cvt.u32.u64 %0, t; }" : "=r"(a) : "l"(p));
    return a;
}

// ---------------- fused prep: detect + zero + weight convert ----------------
__global__ void prep_kernel(const long long* __restrict__ ei,
                            const float* __restrict__ W1,
                            const float* __restrict__ W2,
                            const float* __restrict__ Wfc) {
    int i = blockIdx.x * blockDim.x + threadIdx.x;
    if (i == 0) {
        int is64 = 1;
        for (int k = 0; k < 16; k++) {
            long long v = ei[k];
            if (v < 0 || v >= (long long)NN) { is64 = 0; break; }
        }
        g_is64 = is64;
    }
    if (i < NN) g_deg[i] = 0;
    if (i < NN * HEADS) {
        g_asrcA[i] = 0.f; g_adstA[i] = 0.f;
        g_asrcB[i] = 0.f; g_adstB[i] = 0.f;
    }
    const int s1 = 128 * 256, s2 = s1 + 256 * 256, s3 = s2 + 256 * 64;
    if (i < s1) {
        int k = i / 256, n = i % 256;
        g_w1[n * 128 + k] = __float2half(W1[i]);
    } else if (i < s2) {
        int j = i - s1;
        int k = j / 256, n = j % 256;
        g_w2[n * 256 + k] = __float2half(W2[j]);
    } else if (i < s3) {
        int j = i - s2;
        int k = j / 64, n = j % 64;
        g_wf[n * 256 + k] = __float2half(Wfc[j]);
    }
}

__global__ void convert_hist_kernel(const void* __restrict__ ei) {
    int i = blockIdx.x * blockDim.x + threadIdx.x;
    if (i >= ET) return;
    int s, d;
    if (i < EIN) {
        if (g_is64) {
            const long long* p = (const long long*)ei;
            s = (int)p[i];
            d = (int)p[EIN + i];
        } else {
            const int* p = (const int*)ei;
            s = p[i];
            d = p[EIN + i];
        }
    } else {
        s = d = i - EIN;
    }
    g_src[i] = s;
    g_dst[i] = d;
    atomicAdd(&g_deg[d], 1);
}

// ---------------- mma.sync fp16 + ldmatrix helpers ----------------
__device__ __forceinline__ void mma16816(float* c, const uint32_t* a, const uint32_t* b) {
    asm volatile(
        "mma.sync.aligned.m16n8k16.row.col.f32.f16.f16.f32 "
        "{%0,%1,%2,%3}, {%4,%5,%6,%7}, {%8,%9}, {%0,%1,%2,%3};"
        : "+f"(c[0]), "+f"(c[1]), "+f"(c[2]), "+f"(c[3])
        : "r"(a[0]), "r"(a[1]), "r"(a[2]), "r"(a[3]), "r"(b[0]), "r"(b[1]));
}
__device__ __forceinline__ void ldsm_x4(uint32_t* r, uint32_t addr) {
    asm volatile("ldmatrix.sync.aligned.m8n8.x4.shared.b16 {%0,%1,%2,%3}, [%4];"
                 : "=r"(r[0]), "=r"(r[1]), "=r"(r[2]), "=r"(r[3]) : "r"(addr));
}
__device__ __forceinline__ void ldsm_x2(uint32_t* r, uint32_t addr) {
    asm volatile("ldmatrix.sync.aligned.m8n8.x2.shared.b16 {%0,%1}, [%2];"
                 : "=r"(r[0]), "=r"(r[1]) : "r"(addr));
}

// ---------------- tensor-core GEMM (single fp16 term, ldmatrix) ----------------
// C[M, NTOT] = A[M, KTOT] @ B[NTOT, KTOT]^T
template<int BN, int KTOT, int NTOT, bool BIAS, bool AF32, bool ALPHA, bool OUTF16>
__global__ void __launch_bounds__(256, 2)
gemm_mma_kernel(const void* __restrict__ Aptr,
                const __half* __restrict__ B,
                void* __restrict__ Cptr,
                const float* __restrict__ bias,
                const float* __restrict__ aw_src,
                const float* __restrict__ aw_dst,
                float* __restrict__ asrc_out,
                float* __restrict__ adst_out) {
    constexpr int RS  = 40;          // smem row stride in halves (80B)
    constexpr int NF  = BN / 32;
    constexpr int NB4 = BN / 64;

    __shared__ __half sm[(128 + BN) * RS];
    __half* smA = sm;
    __half* smB = sm + 128 * RS;

    const int tid  = threadIdx.x;
    const int wid  = tid >> 5, lane = tid & 31;
    const int wm   = wid & 1, wn = wid >> 1;
    const int row0 = blockIdx.y * 128;
    const int col0 = blockIdx.x * BN;

    const __half* A16 = (const __half*)Aptr;
    const float*  Af  = (const float*)Aptr;

    float acc[4][NF][4];
    #pragma unroll
    for (int i = 0; i < 4; i++)
        #pragma unroll
        for (int j = 0; j < NF; j++)
            #pragma unroll
            for (int q = 0; q < 4; q++) acc[i][j][q] = 0.f;

    uint4 pa[2], pb[2];
    float4 pf[4];
    const uint4 Z = make_uint4(0u, 0u, 0u, 0u);
    const float4 ZF = make_float4(0.f, 0.f, 0.f, 0.f);

    auto loadA = [&](int k0) {
        if (AF32) {
            #pragma unroll
            for (int q = 0; q < 4; q++) {
                int idx = tid + q * 256;
                int row = idx >> 3, c4 = (idx & 7) * 4;
                int gr = row0 + row;
                pf[q] = (gr < NN) ? *(const float4*)(Af + (size_t)gr * KTOT + k0 + c4) : ZF;
            }
        } else {
            #pragma unroll
            for (int q = 0; q < 2; q++) {
                int idx = tid + q * 256;
                int row = idx >> 2, c8 = (idx & 3) * 8;
                int gr = row0 + row;
                pa[q] = (gr < NN) ? *(const uint4*)(A16 + (size_t)gr * KTOT + k0 + c8) : Z;
            }
        }
    };
    auto storeA = [&]() {
        if (AF32) {
            #pragma unroll
            for (int q = 0; q < 4; q++) {
                int idx = tid + q * 256;
                int row = idx >> 3, c4 = (idx & 7) * 4;
                float4 v = pf[q];
                __half2 h01 = __floats2half2_rn(v.x, v.y);
                __half2 h23 = __floats2half2_rn(v.z, v.w);
                uint2 u;
                u.x = *(uint32_t*)&h01;
                u.y = *(uint32_t*)&h23;
                *(uint2*)(smA + row * RS + c4) = u;
            }
        } else {
            #pragma unroll
            for (int q = 0; q < 2; q++) {
                int idx = tid + q * 256;
                int row = idx >> 2, c8 = (idx & 3) * 8;
                *(uint4*)(smA + row * RS + c8) = pa[q];
            }
        }
    };
    auto loadB = [&](int k0) {
        #pragma unroll
        for (int q = 0; q < NB4; q++) {
            int idx = tid + q * 256;
            int row = idx >> 2, c8 = (idx & 3) * 8;
            pb[q] = *(const uint4*)(B + (size_t)(col0 + row) * KTOT + k0 + c8);
        }
    };
    auto storeB = [&]() {
        #pragma unroll
        for (int q = 0; q < NB4; q++) {
            int idx = tid + q * 256;
            int row = idx >> 2, c8 = (idx & 3) * 8;
            *(uint4*)(smB + row * RS + c8) = pb[q];
        }
    };

    loadA(0); loadB(0);
    storeA(); storeB();
    __syncthreads();

    const int arow = (lane >> 2);
    const int acol = (lane & 3) * 2;

    // ldmatrix per-lane base addresses (bytes)
    const uint32_t smA_u = smem_u32(smA);
    const uint32_t smB_u = smem_u32(smB);
    // A x4: lanes 0-7: rows lo/k lo; 8-15: rows hi/k lo; 16-23: rows lo/k hi; 24-31: rows hi/k hi
    const int aLaneRow = wm * 64 + (lane & 7) + ((lane >> 3) & 1) * 8;
    const uint32_t aLaneK = (lane >> 4) * 16;            // bytes
    // B x2: lanes 0-7: k lo; 8-15: k hi (lanes 16-31 unused; keep in range)
    const int bLaneRow = wn * (BN / 4) + (lane & 7);
    const uint32_t bLaneK = ((lane >> 3) & 1) * 16;      // bytes

    for (int k0 = 32; k0 <= KTOT; k0 += 32) {
        if (k0 < KTOT) { loadA(k0); loadB(k0); }

        #pragma unroll
        for (int ks = 0; ks < 2; ks++) {
            uint32_t b[NF][2];
            #pragma unroll
            for (int j = 0; j < NF; j++)
                ldsm_x2(b[j], smB_u + (uint32_t)(bLaneRow + j * 8) * 80u + (uint32_t)ks * 32u + bLaneK);
            #pragma unroll
            for (int i = 0; i < 4; i++) {
                uint32_t a[4];
                ldsm_x4(a, smA_u + (uint32_t)(aLaneRow + i * 16) * 80u + (uint32_t)ks * 32u + aLaneK);
                #pragma unroll
                for (int j = 0; j < NF; j++)
                    mma16816(acc[i][j], a, b[j]);
            }
        }
        __syncthreads();
        if (k0 < KTOT) {
            storeA(); storeB();
            __syncthreads();
        }
    }

    // ---- epilogue: write C ----
    #pragma unroll
    for (int i = 0; i < 4; i++) {
        int r = row0 + wm * 64 + i * 16 + arow;
        #pragma unroll
        for (int j = 0; j < NF; j++) {
            int c = col0 + wn * (BN / 4) + j * 8 + acol;
            if (OUTF16) {
                __half* C16 = (__half*)Cptr;
                if (r < NN) {
                    __half2 v = __floats2half2_rn(acc[i][j][0], acc[i][j][1]);
                    *(__half2*)(C16 + (size_t)r * NTOT + c) = v;
                }
                if (r + 8 < NN) {
                    __half2 v = __floats2half2_rn(acc[i][j][2], acc[i][j][3]);
                    *(__half2*)(C16 + (size_t)(r + 8) * NTOT + c) = v;
                }
            } else {
                float* C = (float*)Cptr;
                float bx = 0.f, by = 0.f;
                if (BIAS) { bx = bias[c]; by = bias[c + 1]; }
                if (r < NN) {
                    float2 v = make_float2(acc[i][j][0] + bx, acc[i][j][1] + by);
                    *(float2*)(C + (size_t)r * NTOT + c) = v;
                }
                if (r + 8 < NN) {
                    float2 v = make_float2(acc[i][j][2] + bx, acc[i][j][3] + by);
                    *(float2*)(C + (size_t)(r + 8) * NTOT + c) = v;
                }
            }
        }
    }

    // ---- epilogue: fused alpha accumulation ----
    if (ALPHA) {
        const int hw = (col0 + wn * 32) >> 6;
        #pragma unroll
        for (int i = 0; i < 4; i++) {
            float ss0 = 0.f, sd0 = 0.f, ss1 = 0.f, sd1 = 0.f;
            #pragma unroll
            for (int j = 0; j < NF; j++) {
                #pragma unroll
                for (int qq = 0; qq < 2; qq++) {
                    int cw = hw * HID + ((wn & 1) * 32 + j * 8 + acol + qq);
                    float ws = aw_src[cw], wd = aw_dst[cw];
                    ss0 += acc[i][j][qq]     * ws;
                    sd0 += acc[i][j][qq]     * wd;
                    ss1 += acc[i][j][2 + qq] * ws;
                    sd1 += acc[i][j][2 + qq] * wd;
                }
            }
            #pragma unroll
            for (int o = 1; o < 4; o <<= 1) {
                ss0 += __shfl_xor_sync(0xffffffffu, ss0, o);
                sd0 += __shfl_xor_sync(0xffffffffu, sd0, o);
                ss1 += __shfl_xor_sync(0xffffffffu, ss1, o);
                sd1 += __shfl_xor_sync(0xffffffffu, sd1, o);
            }
            if ((lane & 3) == 0) {
                int r = row0 + wm * 64 + i * 16 + arow;
                if (r < NN) {
                    atomicAdd(&asrc_out[r * 4 + hw], ss0);
                    atomicAdd(&adst_out[r * 4 + hw], sd0);
                }
                if (r + 8 < NN) {
                    atomicAdd(&asrc_out[(r + 8) * 4 + hw], ss1);
                    atomicAdd(&adst_out[(r + 8) * 4 + hw], sd1);
                }
            }
        }
    }
}

// ---------------- scan (3-phase, device-wide) ----------------
__device__ __forceinline__ int block_excl_scan(int v, int t, int* tot) {
    __shared__ int ws[8];
    int lane = t & 31, w = t >> 5;
    int x = v;
    #pragma unroll
    for (int o = 1; o < 32; o <<= 1) {
        int y = __shfl_up_sync(0xffffffffu, x, o);
        if (lane >= o) x += y;
    }
    if (lane == 31) ws[w] = x;
    __syncthreads();
    if (w == 0) {
        int z = (lane < 8) ? ws[lane] : 0;
        #pragma unroll
        for (int o = 1; o < 8; o <<= 1) {
            int y = __shfl_up_sync(0xffffffffu, z, o);
            if (lane >= o) z += y;
        }
        if (lane < 8) ws[lane] = z;
    }
    __syncthreads();
    int base = (w > 0) ? ws[w - 1] : 0;
    int total = ws[7];
    __syncthreads();
    *tot = total;
    return base + x - v;
}

__global__ void scan_partial_kernel() {
    int i = blockIdx.x * SCAN_B + threadIdx.x;
    int v = (i < NN) ? g_deg[i] : 0;
    int tot;
    block_excl_scan(v, threadIdx.x, &tot);
    if (threadIdx.x == 0) g_part[blockIdx.x] = tot;
}

__global__ void scan_part2_kernel() {
    int t = threadIdx.x;
    int v = (t < NBLK) ? g_part[t] : 0;
    int tot;
    int excl = block_excl_scan(v, t, &tot);
    if (t < NBLK) g_part[t] = excl;
    if (t == 0) g_off[NN] = tot;
}

__global__ void scan_final_kernel() {
    int i = blockIdx.x * SCAN_B + threadIdx.x;
    int v = (i < NN) ? g_deg[i] : 0;
    int tot;
    int excl = block_excl_scan(v, threadIdx.x, &tot) + g_part[blockIdx.x];
    if (i < NN) {
        g_off[i] = excl;
        g_cur[i] = excl;
    }
}

__global__ void scatter_kernel() {
    int i = blockIdx.x * blockDim.x + threadIdx.x;
    if (i >= ET) return;
    int d = g_dst[i];
    int pos = atomicAdd(&g_cur[d], 1);
    g_csrc[pos] = g_src[i];
}

// ---------------- fused softmax + aggregation: one warp per dst node ----------------
__global__ void agg_kernel(const float* __restrict__ asrc,
                           const float* __restrict__ adstv,
                           const float* __restrict__ bias,
                           __half* __restrict__ hout) {
    int warp = (blockIdx.x * blockDim.x + threadIdx.x) >> 5;
    int lane = threadIdx.x & 31;
    if (warp >= NN) return;
    const int d = warp;
    const int beg = g_off[d], end = g_off[d + 1];
    const float4 ad = *(const float4*)(adstv + (size_t)d * 4);

    float m0 = -FLT_MAX, m1 = -FLT_MAX, m2 = -FLT_MAX, m3 = -FLT_MAX;
    float s0 = 0.f, s1 = 0.f, s2 = 0.f, s3 = 0.f;
    for (int p = beg + lane; p < end; p += 32) {
        int s = g_csrc[p];
        float4 as = *(const float4*)(asrc + (size_t)s * 4);
        float e0 = lrelu(as.x + ad.x);
        float e1 = lrelu(as.y + ad.y);
        float e2 = lrelu(as.z + ad.z);
        float e3 = lrelu(as.w + ad.w);
        float n0 = fmaxf(m0, e0), n1 = fmaxf(m1, e1);
        float n2 = fmaxf(m2, e2), n3 = fmaxf(m3, e3);
        s0 = s0 * __expf(m0 - n0) + __expf(e0 - n0);
        s1 = s1 * __expf(m1 - n1) + __expf(e1 - n1);
        s2 = s2 * __expf(m2 - n2) + __expf(e2 - n2);
        s3 = s3 * __expf(m3 - n3) + __expf(e3 - n3);
        m0 = n0; m1 = n1; m2 = n2; m3 = n3;
    }
    #pragma unroll
    for (int o = 16; o > 0; o >>= 1) {
        float om, os;
        om = __shfl_xor_sync(0xffffffffu, m0, o); os = __shfl_xor_sync(0xffffffffu, s0, o);
        { float n = fmaxf(m0, om); s0 = s0 * __expf(m0 - n) + os * __expf(om - n); m0 = n; }
        om = __shfl_xor_sync(0xffffffffu, m1, o); os = __shfl_xor_sync(0xffffffffu, s1, o);
        { float n = fmaxf(m1, om); s1 = s1 * __expf(m1 - n) + os * __expf(om - n); m1 = n; }
        om = __shfl_xor_sync(0xffffffffu, m2, o); os = __shfl_xor_sync(0xffffffffu, s2, o);
        { float n = fmaxf(m2, om); s2 = s2 * __expf(m2 - n) + os * __expf(om - n); m2 = n; }
        om = __shfl_xor_sync(0xffffffffu, m3, o); os = __shfl_xor_sync(0xffffffffu, s3, o);
        { float n = fmaxf(m3, om); s3 = s3 * __expf(m3 - n) + os * __expf(om - n); m3 = n; }
    }

    const int h = lane >> 3;
    const float adh = (h == 0) ? ad.x : (h == 1) ? ad.y : (h == 2) ? ad.z : ad.w;
    const float mh  = (h == 0) ? m0 : (h == 1) ? m1 : (h == 2) ? m2 : m3;
    const float sh  = (h == 0) ? s0 : (h == 1) ? s1 : (h == 2) ? s2 : s3;
    const float ih  = 1.f / (sh + 1e-16f);

    float acc[8] = {};
    const __half* xrow = g_xh16 + (size_t)lane * 8;

    for (int p = beg; p < end; p++) {
        int s = g_csrc[p];
        float e = lrelu(asrc[s * 4 + h] + adh);
        float a = __expf(e - mh) * ih;
        uint4 v = *(const uint4*)(xrow + (size_t)s * HC);
        __half2 h01 = *(__half2*)&v.x;
        __half2 h23 = *(__half2*)&v.y;
        __half2 h45 = *(__half2*)&v.z;
        __half2 h67 = *(__half2*)&v.w;
        float2 f01 = __half22float2(h01);
        float2 f23 = __half22float2(h23);
        float2 f45 = __half22float2(h45);
        float2 f67 = __half22float2(h67);
        acc[0] = fmaf(a, f01.x, acc[0]);
        acc[1] = fmaf(a, f01.y, acc[1]);
        acc[2] = fmaf(a, f23.x, acc[2]);
        acc[3] = fmaf(a, f23.y, acc[3]);
        acc[4] = fmaf(a, f45.x, acc[4]);
        acc[5] = fmaf(a, f45.y, acc[5]);
        acc[6] = fmaf(a, f67.x, acc[6]);
        acc[7] = fmaf(a, f67.y, acc[7]);
    }

    size_t base = (size_t)d * HC + lane * 8;
    #pragma unroll
    for (int j = 0; j < 4; j++) {
        float va = fmaxf(acc[2*j]   + bias[lane * 8 + 2*j],   0.f);
        float vb = fmaxf(acc[2*j+1] + bias[lane * 8 + 2*j+1], 0.f);
        __half2 hv = __floats2half2_rn(va, vb);
        *(__half2*)(hout + base + 2*j) = hv;
    }
}

// ---------------- host ----------------
extern "C" void kernel_launch(void* const* d_in, const int* in_sizes, int n_in,
                              void* d_out, int out_size) {
    const float*     x   = (const float*)d_in[0];
    const long long* ei  = (const long long*)d_in[1];
    const float* W1  = (const float*)d_in[3];
    const float* as1 = (const float*)d_in[4];
    const float* ad1 = (const float*)d_in[5];
    const float* b1  = (const float*)d_in[6];
    const float* W2  = (const float*)d_in[7];
    const float* as2 = (const float*)d_in[8];
    const float* ad2 = (const float*)d_in[9];
    const float* b2  = (const float*)d_in[10];
    const float* Wfc = (const float*)d_in[11];
    const float* bfc = (const float*)d_in[12];
    float* out = (float*)d_out;

    __half *p_xh16 = nullptr, *p_h16 = nullptr;
    __half *p_w1 = nullptr, *p_w2 = nullptr, *p_wf = nullptr;
    float *p_asA = nullptr, *p_adA = nullptr, *p_asB = nullptr, *p_adB = nullptr;
    cudaGetSymbolAddress((void**)&p_xh16, g_xh16);
    cudaGetSymbolAddress((void**)&p_h16,  g_h16);
    cudaGetSymbolAddress((void**)&p_w1, g_w1);
    cudaGetSymbolAddress((void**)&p_w2, g_w2);
    cudaGetSymbolAddress((void**)&p_wf, g_wf);
    cudaGetSymbolAddress((void**)&p_asA, g_asrcA);
    cudaGetSymbolAddress((void**)&p_adA, g_adstA);
    cudaGetSymbolAddress((void**)&p_asB, g_asrcB);
    cudaGetSymbolAddress((void**)&p_adB, g_adstB);

    const int TPB = 256;
    const int eblk = (ET + TPB - 1) / TPB;
    const int pblk = (NN * HEADS + TPB - 1) / TPB;   // covers all prep jobs
    const int gblk = (NN * 32 + TPB - 1) / TPB;
    const int mtiles = (NN + 127) / 128;   // 391

    prep_kernel<<<pblk, TPB>>>(ei, W1, W2, Wfc);                    // 0
    convert_hist_kernel<<<eblk, TPB>>>((const void*)ei);            // 1
    scan_partial_kernel<<<NBLK, SCAN_B>>>();                        // 2
    {
        dim3 grid(2, mtiles);
        gemm_mma_kernel<128, 128, 256, false, true, true, true><<<grid, 256>>>( // 3 (profiled)
            x, p_w1, p_xh16, nullptr, as1, ad1, p_asA, p_adA);
    }
    scan_part2_kernel<<<1, SCAN_B>>>();                             // 4
    scan_final_kernel<<<NBLK, SCAN_B>>>();                          // 5
    scatter_kernel<<<eblk, TPB>>>();                                // 6
    agg_kernel<<<gblk, TPB>>>(p_asA, p_adA, b1, p_h16);             // 7
    {
        dim3 grid(2, mtiles);
        gemm_mma_kernel<128, 256, 256, false, false, true, true><<<grid, 256>>>( // 8
            p_h16, p_w2, p_xh16, nullptr, as2, ad2, p_asB, p_adB);
    }
    agg_kernel<<<gblk, TPB>>>(p_asB, p_adB, b2, p_h16);             // 9
    {
        dim3 grid(1, mtiles);
        gemm_mma_kernel<64, 256, 64, true, false, false, false><<<grid, 256>>>(  // 10
            p_h16, p_wf, out, bfc, nullptr, nullptr, nullptr, nullptr);
    }
}

// round 10
// speedup vs baseline: 10.2193x; 1.0003x over previous
#include <cuda_runtime.h>
#include <cuda_fp16.h>
#include <cstdint>
#include <cfloat>

// Problem constants
#define NN     50000
#define EIN    800000
#define ET     (EIN + NN)
#define IND    128
#define HEADS  4
#define HID    64
#define HC     256
#define OUTD   64
#define NEG_SLOPE 0.2f

#define SCAN_B 256
#define NBLK   ((NN + SCAN_B - 1) / SCAN_B)

// ---------------- device scratch ----------------
__device__ __align__(16) __half g_x16 [(size_t)NN * IND];  // fp16 input features
__device__ __align__(16) __half g_xh16[(size_t)NN * HC];   // messages (GEMM out)
__device__ __align__(16) __half g_h16 [(size_t)NN * HC];   // layer activations
__device__ float g_asrcA[(size_t)NN * HEADS];
__device__ float g_adstA[(size_t)NN * HEADS];
__device__ float g_asrcB[(size_t)NN * HEADS];
__device__ float g_adstB[(size_t)NN * HEADS];
__device__ __align__(16) __half g_w1[256 * 128];
__device__ __align__(16) __half g_w2[256 * 256];
__device__ __align__(16) __half g_wf[64 * 256];
__device__ int   g_deg [NN];
__device__ int   g_off [NN + 1];
__device__ int   g_cur [NN];
__device__ int   g_part[NBLK];
__device__ int   g_csrc[ET];
__device__ int   g_src [ET];
__device__ int   g_dst [ET];
__device__ int   g_is64;

__device__ __forceinline__ float lrelu(float v) {
    return v >= 0.f ? v : NEG_SLOPE * v;
}
__device__ __forceinline__ uint32_t smem_u32(const void* p) {
    uint32_t a;
    asm("{ .reg .u64 t; cvta.to.shared.u64 t, %1; cvt.u32.u64 %0, t; }" : "=r"(a) : "l"(p));
    return a;
}
__device__ __forceinline__ void cp_async16(uint32_t dst, const void* src, bool pred) {
    int sz = pred ? 16 : 0;
    asm volatile("cp.async.cg.shared.global [%0], [%1], 16, %2;"
                 :: "r"(dst), "l"(src), "r"(sz) : "memory");
}
#define CP_COMMIT() asm volatile("cp.async.commit_group;" ::: "memory")
#define CP_WAIT0()  asm volatile("cp.async.wait_group 0;" ::: "memory")

// ---------------- fused prep: detect + zero + weight/x convert ----------------
__global__ void prep_kernel(const long long* __restrict__ ei,
                            const float* __restrict__ x,
                            const float* __restrict__ W1,
                            const float* __restrict__ W2,
                            const float* __restrict__ Wfc) {
    int i = blockIdx.x * blockDim.x + threadIdx.x;
    if (i == 0) {
        int is64 = 1;
        for (int k = 0; k < 16; k++) {
            long long v = ei[k];
            if (v < 0 || v >= (long long)NN) { is64 = 0; break; }
        }
        g_is64 = is64;
        g_off[NN] = ET;
    }
    if (i < NN) g_deg[i] = 0;
    if (i < NN * HEADS) {
        g_asrcA[i] = 0.f; g_adstA[i] = 0.f;
        g_asrcB[i] = 0.f; g_adstB[i] = 0.f;
    }
    const int s1 = 128 * 256, s2 = s1 + 256 * 256, s3 = s2 + 256 * 64;
    if (i < s1) {
        int k = i / 256, n = i % 256;
        g_w1[n * 128 + k] = __float2half(W1[i]);
    } else if (i < s2) {
        int j = i - s1;
        int k = j / 256, n = j % 256;
        g_w2[n * 256 + k] = __float2half(W2[j]);
    } else if (i < s3) {
        int j = i - s2;
        int k = j / 64, n = j % 64;
        g_wf[n * 256 + k] = __float2half(Wfc[j]);
    }
    // x -> fp16 (float4 granularity)
    if (i < NN * IND / 4) {
        float4 v = *(const float4*)(x + (size_t)i * 4);
        __half2 h01 = __floats2half2_rn(v.x, v.y);
        __half2 h23 = __floats2half2_rn(v.z, v.w);
        uint2 u;
        u.x = *(uint32_t*)&h01;
        u.y = *(uint32_t*)&h23;
        *(uint2*)(g_x16 + (size_t)i * 4) = u;
    }
}

__global__ void convert_hist_kernel(const void* __restrict__ ei) {
    int i = blockIdx.x * blockDim.x + threadIdx.x;
    if (i >= ET) return;
    int s, d;
    if (i < EIN) {
        if (g_is64) {
            const long long* p = (const long long*)ei;
            s = (int)p[i];
            d = (int)p[EIN + i];
        } else {
            const int* p = (const int*)ei;
            s = p[i];
            d = p[EIN + i];
        }
    } else {
        s = d = i - EIN;
    }
    g_src[i] = s;
    g_dst[i] = d;
    atomicAdd(&g_deg[d], 1);
}

// ---------------- mma.sync fp16 + ldmatrix helpers ----------------
__device__ __forceinline__ void mma16816(float* c, const uint32_t* a, const uint32_t* b) {
    asm volatile(
        "mma.sync.aligned.m16n8k16.row.col.f32.f16.f16.f32 "
        "{%0,%1,%2,%3}, {%4,%5,%6,%7}, {%8,%9}, {%0,%1,%2,%3};"
        : "+f"(c[0]), "+f"(c[1]), "+f"(c[2]), "+f"(c[3])
        : "r"(a[0]), "r"(a[1]), "r"(a[2]), "r"(a[3]), "r"(b[0]), "r"(b[1]));
}
__device__ __forceinline__ void ldsm_x4(uint32_t* r, uint32_t addr) {
    asm volatile("ldmatrix.sync.aligned.m8n8.x4.shared.b16 {%0,%1,%2,%3}, [%4];"
                 : "=r"(r[0]), "=r"(r[1]), "=r"(r[2]), "=r"(r[3]) : "r"(addr));
}
__device__ __forceinline__ void ldsm_x2(uint32_t* r, uint32_t addr) {
    asm volatile("ldmatrix.sync.aligned.m8n8.x2.shared.b16 {%0,%1}, [%2];"
                 : "=r"(r[0]), "=r"(r[1]) : "r"(addr));
}

// ---------------- tensor-core GEMM (fp16, cp.async double buffer) ----------------
// C[M, NTOT] = A[M, KTOT] @ B[NTOT, KTOT]^T.  A, B fp16.
template<int BN, int KTOT, int NTOT, bool BIAS, bool ALPHA, bool OUTF16>
__global__ void __launch_bounds__(256, 2)
gemm_mma_kernel(const __half* __restrict__ A16,
                const __half* __restrict__ B,
                void* __restrict__ Cptr,
                const float* __restrict__ bias,
                const float* __restrict__ aw_src,
                const float* __restrict__ aw_dst,
                float* __restrict__ asrc_out,
                float* __restrict__ adst_out) {
    constexpr int RS  = 40;                 // smem row stride in halves (80B)
    constexpr int NF  = BN / 32;
    constexpr int NB4 = BN / 64;
    constexpr int NC  = KTOT / 32;
    constexpr uint32_t BUF_HALVES = (uint32_t)(128 + BN) * RS;

    __shared__ __half sm[2 * (128 + BN) * RS];

    const int tid  = threadIdx.x;
    const int wid  = tid >> 5, lane = tid & 31;
    const int wm   = wid & 1, wn = wid >> 1;
    const int row0 = blockIdx.y * 128;
    const int col0 = blockIdx.x * BN;

    float acc[4][NF][4];
    #pragma unroll
    for (int i = 0; i < 4; i++)
        #pragma unroll
        for (int j = 0; j < NF; j++)
            #pragma unroll
            for (int q = 0; q < 4; q++) acc[i][j][q] = 0.f;

    const uint32_t smA_u = smem_u32(sm);
    const uint32_t smB_u = smA_u + 128u * RS * 2u;
    const uint32_t bufBytes = BUF_HALVES * 2u;

    auto stage = [&](int c, int buf) {
        uint32_t dstA = smA_u + (uint32_t)buf * bufBytes;
        #pragma unroll
        for (int q = 0; q < 2; q++) {
            int idx = tid + q * 256;
            int row = idx >> 2, c8 = (idx & 3) * 8;
            int gr = row0 + row;
            bool ok = (gr < NN);
            const __half* src = A16 + (size_t)(ok ? gr : 0) * KTOT + c * 32 + c8;
            cp_async16(dstA + (uint32_t)(row * RS + c8) * 2u, src, ok);
        }
        uint32_t dstB = smB_u + (uint32_t)buf * bufBytes;
        #pragma unroll
        for (int q = 0; q < NB4; q++) {
            int idx = tid + q * 256;
            int row = idx >> 2, c8 = (idx & 3) * 8;
            cp_async16(dstB + (uint32_t)(row * RS + c8) * 2u,
                       B + (size_t)(col0 + row) * KTOT + c * 32 + c8, true);
        }
        CP_COMMIT();
    };

    stage(0, 0);
    CP_WAIT0();
    __syncthreads();

    const int arow = (lane >> 2);
    const int acol = (lane & 3) * 2;
    // ldmatrix per-lane addresses
    const int aLaneRow = wm * 64 + (lane & 7) + ((lane >> 3) & 1) * 8;
    const uint32_t aLaneK = (lane >> 4) * 16;            // bytes
    const int bLaneRow = wn * (BN / 4) + (lane & 7);
    const uint32_t bLaneK = ((lane >> 3) & 1) * 16;      // bytes

    for (int c = 0; c < NC; c++) {
        if (c + 1 < NC) stage(c + 1, (c + 1) & 1);

        const uint32_t aBase = smA_u + (uint32_t)(c & 1) * bufBytes;
        const uint32_t bBase = smB_u + (uint32_t)(c & 1) * bufBytes;
        #pragma unroll
        for (int ks = 0; ks < 2; ks++) {
            uint32_t b[NF][2];
            #pragma unroll
            for (int j = 0; j < NF; j++)
                ldsm_x2(b[j], bBase + (uint32_t)(bLaneRow + j * 8) * 80u + (uint32_t)ks * 32u + bLaneK);
            #pragma unroll
            for (int i = 0; i < 4; i++) {
                uint32_t a[4];
                ldsm_x4(a, aBase + (uint32_t)(aLaneRow + i * 16) * 80u + (uint32_t)ks * 32u + aLaneK);
                #pragma unroll
                for (int j = 0; j < NF; j++)
                    mma16816(acc[i][j], a, b[j]);
            }
        }
        if (c + 1 < NC) {
            CP_WAIT0();
            __syncthreads();
        }
    }

    // ---- epilogue: write C ----
    #pragma unroll
    for (int i = 0; i < 4; i++) {
        int r = row0 + wm * 64 + i * 16 + arow;
        #pragma unroll
        for (int j = 0; j < NF; j++) {
            int c = col0 + wn * (BN / 4) + j * 8 + acol;
            if (OUTF16) {
                __half* C16 = (__half*)Cptr;
                if (r < NN) {
                    __half2 v = __floats2half2_rn(acc[i][j][0], acc[i][j][1]);
                    *(__half2*)(C16 + (size_t)r * NTOT + c) = v;
                }
                if (r + 8 < NN) {
                    __half2 v = __floats2half2_rn(acc[i][j][2], acc[i][j][3]);
                    *(__half2*)(C16 + (size_t)(r + 8) * NTOT + c) = v;
                }
            } else {
                float* C = (float*)Cptr;
                float bx = 0.f, by = 0.f;
                if (BIAS) { bx = bias[c]; by = bias[c + 1]; }
                if (r < NN) {
                    float2 v = make_float2(acc[i][j][0] + bx, acc[i][j][1] + by);
                    *(float2*)(C + (size_t)r * NTOT + c) = v;
                }
                if (r + 8 < NN) {
                    float2 v = make_float2(acc[i][j][2] + bx, acc[i][j][3] + by);
                    *(float2*)(C + (size_t)(r + 8) * NTOT + c) = v;
                }
            }
        }
    }

    // ---- epilogue: fused alpha accumulation ----
    if (ALPHA) {
        const int hw = (col0 + wn * 32) >> 6;
        #pragma unroll
        for (int i = 0; i < 4; i++) {
            float ss0 = 0.f, sd0 = 0.f, ss1 = 0.f, sd1 = 0.f;
            #pragma unroll
            for (int j = 0; j < NF; j++) {
                #pragma unroll
                for (int qq = 0; qq < 2; qq++) {
                    int cw = hw * HID + ((wn & 1) * 32 + j * 8 + acol + qq);
                    float ws = aw_src[cw], wd = aw_dst[cw];
                    ss0 += acc[i][j][qq]     * ws;
                    sd0 += acc[i][j][qq]     * wd;
                    ss1 += acc[i][j][2 + qq] * ws;
                    sd1 += acc[i][j][2 + qq] * wd;
                }
            }
            #pragma unroll
            for (int o = 1; o < 4; o <<= 1) {
                ss0 += __shfl_xor_sync(0xffffffffu, ss0, o);
                sd0 += __shfl_xor_sync(0xffffffffu, sd0, o);
                ss1 += __shfl_xor_sync(0xffffffffu, ss1, o);
                sd1 += __shfl_xor_sync(0xffffffffu, sd1, o);
            }
            if ((lane & 3) == 0) {
                int r = row0 + wm * 64 + i * 16 + arow;
                if (r < NN) {
                    atomicAdd(&asrc_out[r * 4 + hw], ss0);
                    atomicAdd(&adst_out[r * 4 + hw], sd0);
                }
                if (r + 8 < NN) {
                    atomicAdd(&asrc_out[(r + 8) * 4 + hw], ss1);
                    atomicAdd(&adst_out[(r + 8) * 4 + hw], sd1);
                }
            }
        }
    }
}

// ---------------- scan (2-phase, device-wide) ----------------
__device__ __forceinline__ int block_excl_scan(int v, int t, int* tot) {
    __shared__ int ws[8];
    int lane = t & 31, w = t >> 5;
    int x = v;
    #pragma unroll
    for (int o = 1; o < 32; o <<= 1) {
        int y = __shfl_up_sync(0xffffffffu, x, o);
        if (lane >= o) x += y;
    }
    if (lane == 31) ws[w] = x;
    __syncthreads();
    if (w == 0) {
        int z = (lane < 8) ? ws[lane] : 0;
        #pragma unroll
        for (int o = 1; o < 8; o <<= 1) {
            int y = __shfl_up_sync(0xffffffffu, z, o);
            if (lane >= o) z += y;
        }
        if (lane < 8) ws[lane] = z;
    }
    __syncthreads();
    int base = (w > 0) ? ws[w - 1] : 0;
    int total = ws[7];
    __syncthreads();
    *tot = total;
    return base + x - v;
}

__global__ void scan_partial_kernel() {
    int i = blockIdx.x * SCAN_B + threadIdx.x;
    int v = (i < NN) ? g_deg[i] : 0;
    int tot;
    block_excl_scan(v, threadIdx.x, &tot);
    if (threadIdx.x == 0) g_part[blockIdx.x] = tot;
}

// final scan: each block reduces the partials preceding it, then local scan
__global__ void scan_final_kernel() {
    __shared__ int sred[8];
    __shared__ int sbase;
    int t = threadIdx.x;
    int lane = t & 31, w = t >> 5;

    int pv = (t < blockIdx.x && t < NBLK) ? g_part[t] : 0;
    #pragma unroll
    for (int o = 16; o > 0; o >>= 1) pv += __shfl_xor_sync(0xffffffffu, pv, o);
    if (lane == 0) sred[w] = pv;
    __syncthreads();
    if (t == 0) {
        int s = 0;
        #pragma unroll
        for (int q = 0; q < 8; q++) s += sred[q];
        sbase = s;
    }
    __syncthreads();

    int i = blockIdx.x * SCAN_B + t;
    int v = (i < NN) ? g_deg[i] : 0;
    int tot;
    int excl = block_excl_scan(v, t, &tot) + sbase;
    if (i < NN) {
        g_off[i] = excl;
        g_cur[i] = excl;
    }
}

__global__ void scatter_kernel() {
    int i = blockIdx.x * blockDim.x + threadIdx.x;
    if (i >= ET) return;
    int d = g_dst[i];
    int pos = atomicAdd(&g_cur[d], 1);
    g_csrc[pos] = g_src[i];
}

// ---------------- fused softmax + aggregation: one warp per dst node ----------------
__global__ void agg_kernel(const float* __restrict__ asrc,
                           const float* __restrict__ adstv,
                           const float* __restrict__ bias,
                           __half* __restrict__ hout) {
    int warp = (blockIdx.x * blockDim.x + threadIdx.x) >> 5;
    int lane = threadIdx.x & 31;
    if (warp >= NN) return;
    const int d = warp;
    const int beg = g_off[d], end = g_off[d + 1];
    const float4 ad = *(const float4*)(adstv + (size_t)d * 4);

    float m0 = -FLT_MAX, m1 = -FLT_MAX, m2 = -FLT_MAX, m3 = -FLT_MAX;
    float s0 = 0.f, s1 = 0.f, s2 = 0.f, s3 = 0.f;
    for (int p = beg + lane; p < end; p += 32) {
        int s = g_csrc[p];
        float4 as = *(const float4*)(asrc + (size_t)s * 4);
        float e0 = lrelu(as.x + ad.x);
        float e1 = lrelu(as.y + ad.y);
        float e2 = lrelu(as.z + ad.z);
        float e3 = lrelu(as.w + ad.w);
        float n0 = fmaxf(m0, e0), n1 = fmaxf(m1, e1);
        float n2 = fmaxf(m2, e2), n3 = fmaxf(m3, e3);
        s0 = s0 * __expf(m0 - n0) + __expf(e0 - n0);
        s1 = s1 * __expf(m1 - n1) + __expf(e1 - n1);
        s2 = s2 * __expf(m2 - n2) + __expf(e2 - n2);
        s3 = s3 * __expf(m3 - n3) + __expf(e3 - n3);
        m0 = n0; m1 = n1; m2 = n2; m3 = n3;
    }
    #pragma unroll
    for (int o = 16; o > 0; o >>= 1) {
        float om, os;
        om = __shfl_xor_sync(0xffffffffu, m0, o); os = __shfl_xor_sync(0xffffffffu, s0, o);
        { float n = fmaxf(m0, om); s0 = s0 * __expf(m0 - n) + os * __expf(om - n); m0 = n; }
        om = __shfl_xor_sync(0xffffffffu, m1, o); os = __shfl_xor_sync(0xffffffffu, s1, o);
        { float n = fmaxf(m1, om); s1 = s1 * __expf(m1 - n) + os * __expf(om - n); m1 = n; }
        om = __shfl_xor_sync(0xffffffffu, m2, o); os = __shfl_xor_sync(0xffffffffu, s2, o);
        { float n = fmaxf(m2, om); s2 = s2 * __expf(m2 - n) + os * __expf(om - n); m2 = n; }
        om = __shfl_xor_sync(0xffffffffu, m3, o); os = __shfl_xor_sync(0xffffffffu, s3, o);
        { float n = fmaxf(m3, om); s3 = s3 * __expf(m3 - n) + os * __expf(om - n); m3 = n; }
    }

    const int h = lane >> 3;
    const float adh = (h == 0) ? ad.x : (h == 1) ? ad.y : (h == 2) ? ad.z : ad.w;
    const float mh  = (h == 0) ? m0 : (h == 1) ? m1 : (h == 2) ? m2 : m3;
    const float sh  = (h == 0) ? s0 : (h == 1) ? s1 : (h == 2) ? s2 : s3;
    const float ih  = 1.f / (sh + 1e-16f);

    float acc[8] = {};
    const __half* xrow = g_xh16 + (size_t)lane * 8;

    for (int p = beg; p < end; p++) {
        int s = g_csrc[p];
        float e = lrelu(asrc[s * 4 + h] + adh);
        float a = __expf(e - mh) * ih;
        uint4 v = *(const uint4*)(xrow + (size_t)s * HC);
        __half2 h01 = *(__half2*)&v.x;
        __half2 h23 = *(__half2*)&v.y;
        __half2 h45 = *(__half2*)&v.z;
        __half2 h67 = *(__half2*)&v.w;
        float2 f01 = __half22float2(h01);
        float2 f23 = __half22float2(h23);
        float2 f45 = __half22float2(h45);
        float2 f67 = __half22float2(h67);
        acc[0] = fmaf(a, f01.x, acc[0]);
        acc[1] = fmaf(a, f01.y, acc[1]);
        acc[2] = fmaf(a, f23.x, acc[2]);
        acc[3] = fmaf(a, f23.y, acc[3]);
        acc[4] = fmaf(a, f45.x, acc[4]);
        acc[5] = fmaf(a, f45.y, acc[5]);
        acc[6] = fmaf(a, f67.x, acc[6]);
        acc[7] = fmaf(a, f67.y, acc[7]);
    }

    size_t base = (size_t)d * HC + lane * 8;
    #pragma unroll
    for (int j = 0; j < 4; j++) {
        float va = fmaxf(acc[2*j]   + bias[lane * 8 + 2*j],   0.f);
        float vb = fmaxf(acc[2*j+1] + bias[lane * 8 + 2*j+1], 0.f);
        __half2 hv = __floats2half2_rn(va, vb);
        *(__half2*)(hout + base + 2*j) = hv;
    }
}

// ---------------- host ----------------
extern "C" void kernel_launch(void* const* d_in, const int* in_sizes, int n_in,
                              void* d_out, int out_size) {
    const float*     x   = (const float*)d_in[0];
    const long long* ei  = (const long long*)d_in[1];
    const float* W1  = (const float*)d_in[3];
    const float* as1 = (const float*)d_in[4];
    const float* ad1 = (const float*)d_in[5];
    const float* b1  = (const float*)d_in[6];
    const float* W2  = (const float*)d_in[7];
    const float* as2 = (const float*)d_in[8];
    const float* ad2 = (const float*)d_in[9];
    const float* b2  = (const float*)d_in[10];
    const float* Wfc = (const float*)d_in[11];
    const float* bfc = (const float*)d_in[12];
    float* out = (float*)d_out;

    __half *p_x16 = nullptr, *p_xh16 = nullptr, *p_h16 = nullptr;
    __half *p_w1 = nullptr, *p_w2 = nullptr, *p_wf = nullptr;
    float *p_asA = nullptr, *p_adA = nullptr, *p_asB = nullptr, *p_adB = nullptr;
    cudaGetSymbolAddress((void**)&p_x16,  g_x16);
    cudaGetSymbolAddress((void**)&p_xh16, g_xh16);
    cudaGetSymbolAddress((void**)&p_h16,  g_h16);
    cudaGetSymbolAddress((void**)&p_w1, g_w1);
    cudaGetSymbolAddress((void**)&p_w2, g_w2);
    cudaGetSymbolAddress((void**)&p_wf, g_wf);
    cudaGetSymbolAddress((void**)&p_asA, g_asrcA);
    cudaGetSymbolAddress((void**)&p_adA, g_adstA);
    cudaGetSymbolAddress((void**)&p_asB, g_asrcB);
    cudaGetSymbolAddress((void**)&p_adB, g_adstB);

    const int TPB = 256;
    const int eblk = (ET + TPB - 1) / TPB;
    const int pblk = (NN * IND / 4 + TPB - 1) / TPB;   // 6250: covers all prep jobs
    const int gblk = (NN * 32 + TPB - 1) / TPB;
    const int mtiles = (NN + 127) / 128;   // 391

    prep_kernel<<<pblk, TPB>>>(ei, x, W1, W2, Wfc);                 // 0
    convert_hist_kernel<<<eblk, TPB>>>((const void*)ei);            // 1
    scan_partial_kernel<<<NBLK, SCAN_B>>>();                        // 2
    {
        dim3 grid(2, mtiles);
        gemm_mma_kernel<128, 128, 256, false, true, true><<<grid, 256>>>( // 3 (profiled)
            p_x16, p_w1, p_xh16, nullptr, as1, ad1, p_asA, p_adA);
    }
    scan_final_kernel<<<NBLK, SCAN_B>>>();                          // 4
    scatter_kernel<<<eblk, TPB>>>();                                // 5
    agg_kernel<<<gblk, TPB>>>(p_asA, p_adA, b1, p_h16);             // 6
    {
        dim3 grid(2, mtiles);
        gemm_mma_kernel<128, 256, 256, false, true, true><<<grid, 256>>>( // 7
            p_h16, p_w2, p_xh16, nullptr, as2, ad2, p_asB, p_adB);
    }
    agg_kernel<<<gblk, TPB>>>(p_asB, p_adB, b2, p_h16);             // 8
    {
        dim3 grid(1, mtiles);
        gemm_mma_kernel<64, 256, 64, true, false, false><<<grid, 256>>>(  // 9
            p_h16, p_wf, out, bfc, nullptr, nullptr, nullptr, nullptr);
    }
}